// round 8
// baseline (speedup 1.0000x reference)
#include <cuda_runtime.h>
#include <math.h>

#define N0 100000
#define N1 50000
#define N2 25000
#define N3 12500
#define D  128
#define EPAIR 10000
#define NTOT 87500
#define ETOT 1125000
#define BN_EPS 1e-5f

// ---------------- scratch ----------------
__device__ float g_bufA[2][N1 * D];
__device__ float g_bufB[2][N2 * D];
__device__ float g_agg [2][N1 * D];
__device__ int   g_cnt [NTOT];
__device__ int   g_off [NTOT + 1];
__device__ int   g_cur [NTOT];
__device__ int   g_csr [ETOT];
__device__ int   g_csr2[ETOT];
__device__ float g_stats[2][2][D];     // [stream][sum|sq][col]
__device__ float g_bnA[2][D];          // per-stream BN scale
__device__ float g_bnB[2][D];          // per-stream BN shift
__device__ float g_ws[D];
__device__ float g_loss[2];
__device__ float g_z [2 * EPAIR * D];
__device__ float g_z2[2 * EPAIR * D];

// ---------------- f32x2 helpers ----------------
__device__ __forceinline__ unsigned long long pk2(float x, float y) {
    unsigned long long r;
    asm("mov.b64 %0, {%1, %2};" : "=l"(r) : "f"(x), "f"(y));
    return r;
}
__device__ __forceinline__ void upk2(unsigned long long v, float& x, float& y) {
    asm("mov.b64 {%0, %1}, %2;" : "=f"(x), "=f"(y) : "l"(v));
}
__device__ __forceinline__ unsigned long long fma2(unsigned long long a,
                                                   unsigned long long b,
                                                   unsigned long long c) {
    unsigned long long d;
    asm("fma.rn.f32x2 %0, %1, %2, %3;" : "=l"(d) : "l"(a), "l"(b), "l"(c));
    return d;
}

__device__ __forceinline__ float4 bn_relu4(float4 v, float4 a, float4 b) {
    v.x = fmaxf(fmaf(v.x, a.x, b.x), 0.f);
    v.y = fmaxf(fmaf(v.y, a.y, b.y), 0.f);
    v.z = fmaxf(fmaf(v.z, a.z, b.z), 0.f);
    v.w = fmaxf(fmaf(v.w, a.w, b.w), 0.f);
    return v;
}

// ---------------- CSR build ----------------
__global__ void k_count_all(const int* __restrict__ d0, int E0,
                            const int* __restrict__ d1, int E1,
                            const int* __restrict__ d2, int E2,
                            int* __restrict__ cnt) {
    int e = blockIdx.x * blockDim.x + threadIdx.x;
    if (e < E0) atomicAdd(&cnt[d0[e]], 1);
    else if (e < E0 + E1) atomicAdd(&cnt[N1 + d1[e - E0]], 1);
    else if (e < E0 + E1 + E2) atomicAdd(&cnt[N1 + N2 + d2[e - E0 - E1]], 1);
}

__global__ void k_scan(const int* __restrict__ cnt, int n, int* __restrict__ off) {
    __shared__ int wsum[32];
    int t = threadIdx.x, lane = t & 31, wid = t >> 5;
    int carry = 0;
    for (int base = 0; base < n; base += 8192) {
        int v[8]; int s = 0;
#pragma unroll
        for (int u = 0; u < 8; u++) {
            int i = base + t * 8 + u;
            v[u] = (i < n) ? cnt[i] : 0;
            s += v[u];
        }
        int ps = s;
#pragma unroll
        for (int o = 1; o < 32; o <<= 1) {
            int x = __shfl_up_sync(0xffffffffu, ps, o);
            if (lane >= o) ps += x;
        }
        if (lane == 31) wsum[wid] = ps;
        __syncthreads();
        if (t < 32) {
            int x = wsum[t];
#pragma unroll
            for (int o = 1; o < 32; o <<= 1) {
                int y = __shfl_up_sync(0xffffffffu, x, o);
                if (t >= o) x += y;
            }
            wsum[t] = x;
        }
        __syncthreads();
        int warpbase = wid ? wsum[wid - 1] : 0;
        int run = carry + warpbase + (ps - s);
#pragma unroll
        for (int u = 0; u < 8; u++) {
            int i = base + t * 8 + u;
            if (i < n) off[i] = run;
            run += v[u];
        }
        carry += wsum[31];
        __syncthreads();
    }
    if (t == 0) off[n] = carry;
}

// csr = src; csr2 = perm[src] for layer-0 segment, else src
__global__ void k_fill_all(const int* __restrict__ s0, const int* __restrict__ d0, int E0,
                           const int* __restrict__ s1, const int* __restrict__ d1, int E1,
                           const int* __restrict__ s2, const int* __restrict__ d2, int E2,
                           const int* __restrict__ perm,
                           const int* __restrict__ off, int* __restrict__ cur,
                           int* __restrict__ csr, int* __restrict__ csr2) {
    int e = blockIdx.x * blockDim.x + threadIdx.x;
    int src, node, alt;
    if (e < E0) { src = s0[e]; node = d0[e]; alt = __ldg(&perm[src]); }
    else if (e < E0 + E1) { int i = e - E0; src = s1[i]; node = N1 + d1[i]; alt = src; }
    else if (e < E0 + E1 + E2) { int i = e - E0 - E1; src = s2[i]; node = N1 + N2 + d2[i]; alt = src; }
    else return;
    int p = off[node] + atomicAdd(&cur[node], 1);
    csr[p] = src;
    csr2[p] = alt;
}

// ---------------- gather (neighbor mean, both streams, optional lazy BN+relu) ----------------
template <bool BN>
__global__ void k_gather2(const float4* __restrict__ hp, const float4* __restrict__ hn,
                          const int* __restrict__ csrP, const int* __restrict__ csrN,
                          const int* __restrict__ off,
                          const float4* __restrict__ bnAp, const float4* __restrict__ bnBp,
                          const float4* __restrict__ bnAn, const float4* __restrict__ bnBn,
                          float4* __restrict__ ap, float4* __restrict__ an, int M) {
    int warp = (blockIdx.x * blockDim.x + threadIdx.x) >> 5;
    if (warp >= M) return;
    int lane = threadIdx.x & 31;
    int s0 = off[warp], s1 = off[warp + 1];

    float4 cAp, cBp, cAn, cBn;
    if (BN) {
        cAp = __ldg(&bnAp[lane]); cBp = __ldg(&bnBp[lane]);
        cAn = __ldg(&bnAn[lane]); cBn = __ldg(&bnBn[lane]);
    }

    float4 accp = make_float4(0.f, 0.f, 0.f, 0.f);
    float4 accn = make_float4(0.f, 0.f, 0.f, 0.f);
    int j = s0;
    for (; j + 2 <= s1; j += 2) {
        int pa = __ldg(&csrP[j]), pb = __ldg(&csrP[j + 1]);
        int na = __ldg(&csrN[j]), nb = __ldg(&csrN[j + 1]);
        float4 v0 = hp[pa * 32 + lane];
        float4 v1 = hn[na * 32 + lane];
        float4 w0 = hp[pb * 32 + lane];
        float4 w1 = hn[nb * 32 + lane];
        if (BN) {
            v0 = bn_relu4(v0, cAp, cBp); w0 = bn_relu4(w0, cAp, cBp);
            v1 = bn_relu4(v1, cAn, cBn); w1 = bn_relu4(w1, cAn, cBn);
        }
        accp.x += v0.x + w0.x; accp.y += v0.y + w0.y;
        accp.z += v0.z + w0.z; accp.w += v0.w + w0.w;
        accn.x += v1.x + w1.x; accn.y += v1.y + w1.y;
        accn.z += v1.z + w1.z; accn.w += v1.w + w1.w;
    }
    if (j < s1) {
        int pa = __ldg(&csrP[j]);
        int na = __ldg(&csrN[j]);
        float4 v0 = hp[pa * 32 + lane];
        float4 v1 = hn[na * 32 + lane];
        if (BN) {
            v0 = bn_relu4(v0, cAp, cBp);
            v1 = bn_relu4(v1, cAn, cBn);
        }
        accp.x += v0.x; accp.y += v0.y; accp.z += v0.z; accp.w += v0.w;
        accn.x += v1.x; accn.y += v1.y; accn.z += v1.z; accn.w += v1.w;
    }
    int deg = s1 - s0;
    float inv = 1.0f / (float)(deg > 0 ? deg : 1);
    accp.x *= inv; accp.y *= inv; accp.z *= inv; accp.w *= inv;
    accn.x *= inv; accn.y *= inv; accn.z *= inv; accn.w *= inv;
    ap[warp * 32 + lane] = accp;
    an[warp * 32 + lane] = accn;
}

// ---------------- fused GEMM ----------------
// C = A1@W1 [+ A2@W2] + bias.  512 threads, 128-row tile, 4r x 8c per thread.
// Phase-0 A-load options (runtime, uniform): row indirection pidx[], lazy BN+relu (bnA/bnB).
// PAIRG: A row = h[ga[r]]*h[gb[r]] (predictor; rows>=EPAIR use ga2/gb2).
// STATS: per-column sum/sumsq of output (pre-relu path used by BN layers).
template <bool DUAL, bool PAIRG, bool STATS>
__global__ void __launch_bounds__(512, 1)
gemm_v3(const float4* __restrict__ A1p, const float4* __restrict__ A1n,
        const float4* __restrict__ A2p, const float4* __restrict__ A2n,
        const float4* __restrict__ W1, const float4* __restrict__ W2,
        const float* __restrict__ bias,
        float4* __restrict__ Cp, float4* __restrict__ Cn,
        float* __restrict__ statsP, float* __restrict__ statsN,
        const float4* __restrict__ bnAp, const float4* __restrict__ bnBp,
        const float4* __restrict__ bnAn, const float4* __restrict__ bnBn,
        const int* __restrict__ pidxP, const int* __restrict__ pidxN,
        const int* __restrict__ ga, const int* __restrict__ gb,
        const int* __restrict__ ga2, const int* __restrict__ gb2,
        int M, int relu) {
    extern __shared__ float4 smem[];
    float4* sA = smem;          // [128][32]
    float4* sB = smem + 4096;   // [128][32]

    int t = threadIdx.x;
    int rowBase = blockIdx.x * 128;
    int strm = blockIdx.y;

    const float4* A1 = strm ? A1n : A1p;
    const float4* A2 = strm ? A2n : A2p;
    float4* C = strm ? Cn : Cp;
    float* stats = strm ? statsN : statsP;
    const float4* bnA = strm ? bnAn : bnAp;
    const float4* bnB = strm ? bnBn : bnBp;
    const int* pidx = strm ? pidxN : pidxP;

    int c8 = t & 15;
    int r0 = (t >> 4) * 4;
    const ulonglong2* sB2 = (const ulonglong2*)sB;

    unsigned long long acc[4][4];
#pragma unroll
    for (int i = 0; i < 4; i++)
#pragma unroll
        for (int j = 0; j < 4; j++) acc[i][j] = 0ULL;

#pragma unroll
    for (int ph = 0; ph < (DUAL ? 2 : 1); ph++) {
        if (ph) __syncthreads();
        const float4* W = ph ? W2 : W1;
        const float4* A = ph ? A2 : A1;
#pragma unroll
        for (int i = 0; i < 8; i++) sB[t + i * 512] = W[t + i * 512];
#pragma unroll
        for (int i = 0; i < 8; i++) {
            int p = t + i * 512;
            int r = p >> 5, kq = p & 31;
            int row = rowBase + r;
            float4 v = make_float4(0.f, 0.f, 0.f, 0.f);
            if (row < M) {
                if (PAIRG) {
                    const int* A_ = (row < EPAIR) ? ga : ga2;
                    const int* B_ = (row < EPAIR) ? gb : gb2;
                    int rr = (row < EPAIR) ? row : row - EPAIR;
                    float4 u = A[A_[rr] * 32 + kq];
                    float4 w = A[B_[rr] * 32 + kq];
                    v = make_float4(u.x * w.x, u.y * w.y, u.z * w.z, u.w * w.w);
                } else {
                    int rr = row;
                    if (ph == 0 && pidx) rr = __ldg(&pidx[row]);
                    v = A[rr * 32 + kq];
                    if (ph == 0 && bnA)
                        v = bn_relu4(v, __ldg(&bnA[kq]), __ldg(&bnB[kq]));
                }
            }
            sA[r * 32 + kq] = v;
        }
        __syncthreads();

#pragma unroll 4
        for (int k4 = 0; k4 < 32; k4++) {
            float4 a0 = sA[(r0 + 0) * 32 + k4];
            float4 a1 = sA[(r0 + 1) * 32 + k4];
            float4 a2 = sA[(r0 + 2) * 32 + k4];
            float4 a3 = sA[(r0 + 3) * 32 + k4];
#pragma unroll
            for (int kk = 0; kk < 4; kk++) {
                int k = k4 * 4 + kk;
                ulonglong2 p0 = sB2[k * 32 + c8];
                ulonglong2 p1 = sB2[k * 32 + 16 + c8];
                float f0 = kk == 0 ? a0.x : kk == 1 ? a0.y : kk == 2 ? a0.z : a0.w;
                float f1 = kk == 0 ? a1.x : kk == 1 ? a1.y : kk == 2 ? a1.z : a1.w;
                float f2 = kk == 0 ? a2.x : kk == 1 ? a2.y : kk == 2 ? a2.z : a2.w;
                float f3 = kk == 0 ? a3.x : kk == 1 ? a3.y : kk == 2 ? a3.z : a3.w;
                unsigned long long aa0 = pk2(f0, f0);
                unsigned long long aa1 = pk2(f1, f1);
                unsigned long long aa2 = pk2(f2, f2);
                unsigned long long aa3 = pk2(f3, f3);
                acc[0][0] = fma2(aa0, p0.x, acc[0][0]);
                acc[0][1] = fma2(aa0, p0.y, acc[0][1]);
                acc[0][2] = fma2(aa0, p1.x, acc[0][2]);
                acc[0][3] = fma2(aa0, p1.y, acc[0][3]);
                acc[1][0] = fma2(aa1, p0.x, acc[1][0]);
                acc[1][1] = fma2(aa1, p0.y, acc[1][1]);
                acc[1][2] = fma2(aa1, p1.x, acc[1][2]);
                acc[1][3] = fma2(aa1, p1.y, acc[1][3]);
                acc[2][0] = fma2(aa2, p0.x, acc[2][0]);
                acc[2][1] = fma2(aa2, p0.y, acc[2][1]);
                acc[2][2] = fma2(aa2, p1.x, acc[2][2]);
                acc[2][3] = fma2(aa2, p1.y, acc[2][3]);
                acc[3][0] = fma2(aa3, p0.x, acc[3][0]);
                acc[3][1] = fma2(aa3, p0.y, acc[3][1]);
                acc[3][2] = fma2(aa3, p1.x, acc[3][2]);
                acc[3][3] = fma2(aa3, p1.y, acc[3][3]);
            }
        }
    }

    float4 bv0 = make_float4(0.f, 0.f, 0.f, 0.f);
    float4 bv1 = make_float4(0.f, 0.f, 0.f, 0.f);
    if (bias) {
        bv0 = ((const float4*)bias)[c8];
        bv1 = ((const float4*)bias)[16 + c8];
    }

    float csum[8] = {0,0,0,0,0,0,0,0};
    float csq [8] = {0,0,0,0,0,0,0,0};

#pragma unroll
    for (int i = 0; i < 4; i++) {
        int row = rowBase + r0 + i;
        if (row >= M) continue;
        float4 o0, o1;
        upk2(acc[i][0], o0.x, o0.y);
        upk2(acc[i][1], o0.z, o0.w);
        upk2(acc[i][2], o1.x, o1.y);
        upk2(acc[i][3], o1.z, o1.w);
        o0.x += bv0.x; o0.y += bv0.y; o0.z += bv0.z; o0.w += bv0.w;
        o1.x += bv1.x; o1.y += bv1.y; o1.z += bv1.z; o1.w += bv1.w;
        if (relu) {
            o0.x = fmaxf(o0.x, 0.f); o0.y = fmaxf(o0.y, 0.f);
            o0.z = fmaxf(o0.z, 0.f); o0.w = fmaxf(o0.w, 0.f);
            o1.x = fmaxf(o1.x, 0.f); o1.y = fmaxf(o1.y, 0.f);
            o1.z = fmaxf(o1.z, 0.f); o1.w = fmaxf(o1.w, 0.f);
        }
        if (STATS) {
            csum[0] += o0.x; csq[0] += o0.x * o0.x;
            csum[1] += o0.y; csq[1] += o0.y * o0.y;
            csum[2] += o0.z; csq[2] += o0.z * o0.z;
            csum[3] += o0.w; csq[3] += o0.w * o0.w;
            csum[4] += o1.x; csq[4] += o1.x * o1.x;
            csum[5] += o1.y; csq[5] += o1.y * o1.y;
            csum[6] += o1.z; csq[6] += o1.z * o1.z;
            csum[7] += o1.w; csq[7] += o1.w * o1.w;
        }
        C[row * 32 + c8]      = o0;
        C[row * 32 + 16 + c8] = o1;
    }

    if (STATS) {
        int lane = t & 31;
#pragma unroll
        for (int j = 0; j < 8; j++) {
            csum[j] += __shfl_xor_sync(0xffffffffu, csum[j], 16);
            csq [j] += __shfl_xor_sync(0xffffffffu, csq [j], 16);
        }
        if (lane < 16) {
#pragma unroll
            for (int j = 0; j < 4; j++) {
                atomicAdd(&stats[4 * c8 + j],          csum[j]);
                atomicAdd(&stats[D + 4 * c8 + j],      csq [j]);
                atomicAdd(&stats[64 + 4 * c8 + j],     csum[4 + j]);
                atomicAdd(&stats[D + 64 + 4 * c8 + j], csq [4 + j]);
            }
        }
    }
}

// fold per-stream BN stats into per-column scale/shift
__global__ void k_bncoef(const float* __restrict__ statsP, const float* __restrict__ statsN,
                         const float* __restrict__ gamma, const float* __restrict__ beta,
                         float* __restrict__ bnAp, float* __restrict__ bnBp,
                         float* __restrict__ bnAn, float* __restrict__ bnBn, int M) {
    int t = threadIdx.x;               // 256
    int strm = t >> 7, c = t & 127;
    const float* st = strm ? statsN : statsP;
    float* A = strm ? bnAn : bnAp;
    float* B = strm ? bnBn : bnBp;
    float invM = 1.0f / (float)M;
    float m = st[c] * invM;
    float v = st[D + c] * invM - m * m;
    float a = gamma[c] * rsqrtf(v + BN_EPS);
    A[c] = a;
    B[c] = beta[c] - m * a;
}

__global__ void k_summary_ws(const float* __restrict__ colsum,
                             const float* __restrict__ discW, float* __restrict__ ws) {
    __shared__ float sm[D];
    int t = threadIdx.x;
    float mn = colsum[t] / (float)N3;
    sm[t] = 1.0f / (1.0f + expf(-mn));
    __syncthreads();
    float a = 0.f;
#pragma unroll 8
    for (int j = 0; j < D; j++) a += discW[t * D + j] * sm[j];
    ws[t] = a;
}

__device__ __forceinline__ float warp_dot128(const float4* __restrict__ a,
                                             const float4* __restrict__ b, int lane) {
    float4 x = a[lane], y = b[lane];
    float s = x.x * y.x + x.y * y.y + x.z * y.z + x.w * y.w;
#pragma unroll
    for (int o = 16; o; o >>= 1) s += __shfl_down_sync(0xffffffffu, s, o);
    return s;
}

__global__ void k_loss(const float4* __restrict__ pos, const float4* __restrict__ neg,
                       const float4* __restrict__ ws, float* __restrict__ loss) {
    int tid = blockIdx.x * blockDim.x + threadIdx.x;
    int e = tid >> 5;
    if (e >= 2 * N3) return;
    int lane = tid & 31;
    int strm = (e >= N3);
    int r = e - strm * N3;
    const float4* row = (strm ? neg : pos) + r * 32;
    float s = warp_dot128(row, ws, lane);
    if (lane == 0) {
        float xx = strm ? s : -s;
        float sp = fmaxf(xx, 0.f) + log1pf(expf(-fabsf(xx)));
        atomicAdd(&loss[strm], sp);
    }
}

__global__ void k_pred_out(const float4* __restrict__ z, const float4* __restrict__ w3,
                           const float* __restrict__ b3, float* __restrict__ out) {
    int tid = blockIdx.x * blockDim.x + threadIdx.x;
    int e = tid >> 5;
    if (e >= 2 * EPAIR) return;
    int lane = tid & 31;
    float s = warp_dot128(z + e * 32, w3, lane);
    if (lane == 0) out[e] = s + b3[0];
}

__global__ void k_final_loss(const float* __restrict__ loss, float* __restrict__ out) {
    out[0] = (loss[0] + loss[1]) * (1.0f / (float)N3);
}

// ---------------- host orchestration ----------------
extern "C" void kernel_launch(void* const* d_in, const int* in_sizes, int n_in,
                              void* d_out, int out_size) {
    const float* x      = (const float*)d_in[0];
    const int* srcs[3]  = {(const int*)d_in[1], (const int*)d_in[3], (const int*)d_in[5]};
    const int* dsts[3]  = {(const int*)d_in[2], (const int*)d_in[4], (const int*)d_in[6]};
    const int* perm     = (const int*)d_in[7];
    const int* pos_src  = (const int*)d_in[8];
    const int* pos_dst  = (const int*)d_in[9];
    const int* neg_src  = (const int*)d_in[10];
    const int* neg_dst  = (const int*)d_in[11];
    const float* Ws[3]  = {(const float*)d_in[12], (const float*)d_in[15], (const float*)d_in[18]};
    const float* Wn[3]  = {(const float*)d_in[13], (const float*)d_in[16], (const float*)d_in[19]};
    const float* bb[3]  = {(const float*)d_in[14], (const float*)d_in[17], (const float*)d_in[20]};
    const float* gamma[2] = {(const float*)d_in[21], (const float*)d_in[23]};
    const float* beta [2] = {(const float*)d_in[22], (const float*)d_in[24]};
    const float* discW  = (const float*)d_in[25];
    const float* pW1 = (const float*)d_in[26]; const float* pb1 = (const float*)d_in[27];
    const float* pW2 = (const float*)d_in[28]; const float* pb2 = (const float*)d_in[29];
    const float* pW3 = (const float*)d_in[30]; const float* pb3 = (const float*)d_in[31];
    float* out = (float*)d_out;

    int E[3] = {in_sizes[1], in_sizes[3], in_sizes[5]};
    int ND[3] = {N1, N2, N3};
    int segbase[3] = {0, N1, N1 + N2};

    float *p_bufA, *p_bufB, *p_agg, *p_stats, *p_bnA, *p_bnB, *p_ws, *p_loss, *p_z, *p_z2;
    int *p_cnt, *p_off, *p_cur, *p_csr, *p_csr2;
    cudaGetSymbolAddress((void**)&p_bufA,  g_bufA);
    cudaGetSymbolAddress((void**)&p_bufB,  g_bufB);
    cudaGetSymbolAddress((void**)&p_agg,   g_agg);
    cudaGetSymbolAddress((void**)&p_cnt,   g_cnt);
    cudaGetSymbolAddress((void**)&p_off,   g_off);
    cudaGetSymbolAddress((void**)&p_cur,   g_cur);
    cudaGetSymbolAddress((void**)&p_csr,   g_csr);
    cudaGetSymbolAddress((void**)&p_csr2,  g_csr2);
    cudaGetSymbolAddress((void**)&p_stats, g_stats);
    cudaGetSymbolAddress((void**)&p_bnA,   g_bnA);
    cudaGetSymbolAddress((void**)&p_bnB,   g_bnB);
    cudaGetSymbolAddress((void**)&p_ws,    g_ws);
    cudaGetSymbolAddress((void**)&p_loss,  g_loss);
    cudaGetSymbolAddress((void**)&p_z,     g_z);
    cudaGetSymbolAddress((void**)&p_z2,    g_z2);

    const size_t GEMM_SMEM = 131072;
    cudaFuncSetAttribute(gemm_v3<true,  false, true >, cudaFuncAttributeMaxDynamicSharedMemorySize, GEMM_SMEM);
    cudaFuncSetAttribute(gemm_v3<false, true,  false>, cudaFuncAttributeMaxDynamicSharedMemorySize, GEMM_SMEM);
    cudaFuncSetAttribute(gemm_v3<false, false, false>, cudaFuncAttributeMaxDynamicSharedMemorySize, GEMM_SMEM);

    int Etot = E[0] + E[1] + E[2];

    // batched CSR build (csr2 carries perm[src] for layer-0 segment)
    cudaMemsetAsync(p_cnt, 0, NTOT * sizeof(int), 0);
    cudaMemsetAsync(p_cur, 0, NTOT * sizeof(int), 0);
    k_count_all<<<(Etot + 255) / 256, 256>>>(dsts[0], E[0], dsts[1], E[1], dsts[2], E[2], p_cnt);
    k_scan<<<1, 1024>>>(p_cnt, NTOT, p_off);
    k_fill_all<<<(Etot + 255) / 256, 256>>>(srcs[0], dsts[0], E[0],
                                            srcs[1], dsts[1], E[1],
                                            srcs[2], dsts[2], E[2],
                                            perm, p_off, p_cur, p_csr, p_csr2);

    float* bufA[2] = {p_bufA, p_bufA + (size_t)N1 * D};
    float* bufB[2] = {p_bufB, p_bufB + (size_t)N2 * D};
    float* agg [2] = {p_agg,  p_agg  + (size_t)N1 * D};
    float* stP = p_stats;
    float* stN = p_stats + 2 * D;
    float* bnAp = p_bnA;          float* bnAn = p_bnA + D;
    float* bnBp = p_bnB;          float* bnBn = p_bnB + D;

    const float* hinP = x;
    const float* hinN = x;   // layer 0 negative uses x with perm indirection

    for (int l = 0; l < 3; l++) {
        int nd = ND[l];
        float* outb[2];
        if (l == 1) { outb[0] = bufB[0]; outb[1] = bufB[1]; }
        else        { outb[0] = bufA[0]; outb[1] = bufA[1]; }

        const int* csrN = (l == 0) ? p_csr2 : p_csr;
        int gthreads = nd * 32;
        if (l == 0) {
            k_gather2<false><<<(gthreads + 255) / 256, 256>>>(
                (const float4*)hinP, (const float4*)hinN, p_csr + 0, csrN + 0,
                p_off + segbase[l], nullptr, nullptr, nullptr, nullptr,
                (float4*)agg[0], (float4*)agg[1], nd);
        } else {
            // NOTE: csr offsets are global; pass csr base (indices inside use off[])
            k_gather2<true><<<(gthreads + 255) / 256, 256>>>(
                (const float4*)hinP, (const float4*)hinN, p_csr, csrN,
                p_off + segbase[l],
                (const float4*)bnAp, (const float4*)bnBp,
                (const float4*)bnAn, (const float4*)bnBn,
                (float4*)agg[0], (float4*)agg[1], nd);
        }

        cudaMemsetAsync(p_stats, 0, 2 * 2 * D * sizeof(float), 0);

        dim3 grid((nd + 127) / 128, 2);
        gemm_v3<true, false, true><<<grid, 512, GEMM_SMEM>>>(
            (const float4*)hinP, (const float4*)hinN,
            (const float4*)agg[0], (const float4*)agg[1],
            (const float4*)Ws[l], (const float4*)Wn[l], bb[l],
            (float4*)outb[0], (float4*)outb[1],
            stP, stN,
            (l > 0) ? (const float4*)bnAp : nullptr, (l > 0) ? (const float4*)bnBp : nullptr,
            (l > 0) ? (const float4*)bnAn : nullptr, (l > 0) ? (const float4*)bnBn : nullptr,
            nullptr, (l == 0) ? perm : nullptr,
            nullptr, nullptr, nullptr, nullptr, nd, 0);

        if (l < 2)
            k_bncoef<<<1, 256>>>(stP, stN, gamma[l], beta[l],
                                 bnAp, bnBp, bnAn, bnBn, nd);

        hinP = outb[0];
        hinN = outb[1];
    }

    float* positive = bufA[0];
    float* negative = bufA[1];

    // summary from layer-2 positive column sums (already in stP)
    cudaMemsetAsync(p_loss, 0, 2 * sizeof(float), 0);
    k_summary_ws<<<1, 128>>>(stP, discW, p_ws);
    k_loss<<<(2 * N3 * 32 + 255) / 256, 256>>>((const float4*)positive,
                                               (const float4*)negative,
                                               (const float4*)p_ws, p_loss);

    // link predictor: 20000 rows, pair-product fused into GEMM1
    int Mp = 2 * EPAIR;
    dim3 pgrid((Mp + 127) / 128, 1);
    gemm_v3<false, true, false><<<pgrid, 512, GEMM_SMEM>>>(
        (const float4*)positive, (const float4*)positive, nullptr, nullptr,
        (const float4*)pW1, nullptr, pb1, (float4*)p_z2, (float4*)p_z2,
        nullptr, nullptr, nullptr, nullptr, nullptr, nullptr, nullptr, nullptr,
        pos_src, pos_dst, neg_src, neg_dst, Mp, 1);
    gemm_v3<false, false, false><<<pgrid, 512, GEMM_SMEM>>>(
        (const float4*)p_z2, (const float4*)p_z2, nullptr, nullptr,
        (const float4*)pW2, nullptr, pb2, (float4*)p_z, (float4*)p_z,
        nullptr, nullptr, nullptr, nullptr, nullptr, nullptr, nullptr, nullptr,
        nullptr, nullptr, nullptr, nullptr, Mp, 1);
    k_pred_out<<<(Mp * 32 + 255) / 256, 256>>>((const float4*)p_z,
                                               (const float4*)pW3, pb3, out);

    k_final_loss<<<1, 1>>>(p_loss, out + 2 * EPAIR);
}

// round 9
// speedup vs baseline: 1.7061x; 1.7061x over previous
#include <cuda_runtime.h>
#include <math.h>

#define N0 100000
#define N1 50000
#define N2 25000
#define N3 12500
#define D  128
#define EPAIR 10000
#define NTOT 87500
#define ETOT 1125000
#define BN_EPS 1e-5f

// ---------------- scratch ----------------
__device__ float g_bufA[2][N1 * D];
__device__ float g_bufB[2][N2 * D];
__device__ float g_agg [2][N1 * D];
__device__ int   g_cnt [NTOT];
__device__ int   g_off [NTOT + 1];
__device__ int   g_cur [NTOT];
__device__ int   g_csr [ETOT];
__device__ int   g_csr2[ETOT];
__device__ float g_stats[2][2][D];
__device__ float g_csum[D];
__device__ float g_csq_dummy[D];
__device__ float g_ws[D];
__device__ float g_loss[2];
__device__ float g_z [2 * EPAIR * D];
__device__ float g_z2[2 * EPAIR * D];

// ---------------- f32x2 helpers ----------------
__device__ __forceinline__ unsigned long long pk2(float x, float y) {
    unsigned long long r;
    asm("mov.b64 %0, {%1, %2};" : "=l"(r) : "f"(x), "f"(y));
    return r;
}
__device__ __forceinline__ void upk2(unsigned long long v, float& x, float& y) {
    asm("mov.b64 {%0, %1}, %2;" : "=f"(x), "=f"(y) : "l"(v));
}
__device__ __forceinline__ unsigned long long fma2(unsigned long long a,
                                                   unsigned long long b,
                                                   unsigned long long c) {
    unsigned long long d;
    asm("fma.rn.f32x2 %0, %1, %2, %3;" : "=l"(d) : "l"(a), "l"(b), "l"(c));
    return d;
}

// ---------------- CSR build ----------------
__global__ void k_count_all(const int* __restrict__ d0, int E0,
                            const int* __restrict__ d1, int E1,
                            const int* __restrict__ d2, int E2,
                            int* __restrict__ cnt) {
    int e = blockIdx.x * blockDim.x + threadIdx.x;
    if (e < E0) atomicAdd(&cnt[d0[e]], 1);
    else if (e < E0 + E1) atomicAdd(&cnt[N1 + d1[e - E0]], 1);
    else if (e < E0 + E1 + E2) atomicAdd(&cnt[N1 + N2 + d2[e - E0 - E1]], 1);
}

__global__ void k_scan(const int* __restrict__ cnt, int n, int* __restrict__ off) {
    __shared__ int wsum[32];
    int t = threadIdx.x, lane = t & 31, wid = t >> 5;
    int carry = 0;
    for (int base = 0; base < n; base += 8192) {
        int v[8]; int s = 0;
#pragma unroll
        for (int u = 0; u < 8; u++) {
            int i = base + t * 8 + u;
            v[u] = (i < n) ? cnt[i] : 0;
            s += v[u];
        }
        int ps = s;
#pragma unroll
        for (int o = 1; o < 32; o <<= 1) {
            int x = __shfl_up_sync(0xffffffffu, ps, o);
            if (lane >= o) ps += x;
        }
        if (lane == 31) wsum[wid] = ps;
        __syncthreads();
        if (t < 32) {
            int x = wsum[t];
#pragma unroll
            for (int o = 1; o < 32; o <<= 1) {
                int y = __shfl_up_sync(0xffffffffu, x, o);
                if (t >= o) x += y;
            }
            wsum[t] = x;
        }
        __syncthreads();
        int warpbase = wid ? wsum[wid - 1] : 0;
        int run = carry + warpbase + (ps - s);
#pragma unroll
        for (int u = 0; u < 8; u++) {
            int i = base + t * 8 + u;
            if (i < n) off[i] = run;
            run += v[u];
        }
        carry += wsum[31];
        __syncthreads();
    }
    if (t == 0) off[n] = carry;
}

// csr = src; csr2 = perm[src] for layer-0 segment, else src
__global__ void k_fill_all(const int* __restrict__ s0, const int* __restrict__ d0, int E0,
                           const int* __restrict__ s1, const int* __restrict__ d1, int E1,
                           const int* __restrict__ s2, const int* __restrict__ d2, int E2,
                           const int* __restrict__ perm,
                           const int* __restrict__ off, int* __restrict__ cur,
                           int* __restrict__ csr, int* __restrict__ csr2) {
    int e = blockIdx.x * blockDim.x + threadIdx.x;
    int src, node, alt;
    if (e < E0) { src = s0[e]; node = d0[e]; alt = __ldg(&perm[src]); }
    else if (e < E0 + E1) { int i = e - E0; src = s1[i]; node = N1 + d1[i]; alt = src; }
    else if (e < E0 + E1 + E2) { int i = e - E0 - E1; src = s2[i]; node = N1 + N2 + d2[i]; alt = src; }
    else return;
    int p = off[node] + atomicAdd(&cur[node], 1);
    csr[p] = src;
    csr2[p] = alt;
}

// ---------------- gather: neighbor mean for BOTH streams, 4-edge unroll ----------------
__global__ void k_gather3(const float4* __restrict__ hp, const float4* __restrict__ hn,
                          const int* __restrict__ csrP, const int* __restrict__ csrN,
                          const int* __restrict__ off,
                          float4* __restrict__ ap, float4* __restrict__ an, int M) {
    int warp = (blockIdx.x * blockDim.x + threadIdx.x) >> 5;
    if (warp >= M) return;
    int lane = threadIdx.x & 31;
    int s0 = off[warp], s1 = off[warp + 1];
    float4 accp = make_float4(0.f, 0.f, 0.f, 0.f);
    float4 accn = make_float4(0.f, 0.f, 0.f, 0.f);
    int j = s0;
    for (; j + 4 <= s1; j += 4) {
        int a0 = __ldg(&csrP[j]),     a1 = __ldg(&csrP[j + 1]);
        int a2 = __ldg(&csrP[j + 2]), a3 = __ldg(&csrP[j + 3]);
        int b0 = __ldg(&csrN[j]),     b1 = __ldg(&csrN[j + 1]);
        int b2 = __ldg(&csrN[j + 2]), b3 = __ldg(&csrN[j + 3]);
        float4 p0 = hp[a0 * 32 + lane], p1 = hp[a1 * 32 + lane];
        float4 p2 = hp[a2 * 32 + lane], p3 = hp[a3 * 32 + lane];
        float4 n0 = hn[b0 * 32 + lane], n1 = hn[b1 * 32 + lane];
        float4 n2 = hn[b2 * 32 + lane], n3 = hn[b3 * 32 + lane];
        accp.x += (p0.x + p1.x) + (p2.x + p3.x);
        accp.y += (p0.y + p1.y) + (p2.y + p3.y);
        accp.z += (p0.z + p1.z) + (p2.z + p3.z);
        accp.w += (p0.w + p1.w) + (p2.w + p3.w);
        accn.x += (n0.x + n1.x) + (n2.x + n3.x);
        accn.y += (n0.y + n1.y) + (n2.y + n3.y);
        accn.z += (n0.z + n1.z) + (n2.z + n3.z);
        accn.w += (n0.w + n1.w) + (n2.w + n3.w);
    }
    for (; j < s1; j++) {
        int a0 = __ldg(&csrP[j]);
        int b0 = __ldg(&csrN[j]);
        float4 p0 = hp[a0 * 32 + lane];
        float4 n0 = hn[b0 * 32 + lane];
        accp.x += p0.x; accp.y += p0.y; accp.z += p0.z; accp.w += p0.w;
        accn.x += n0.x; accn.y += n0.y; accn.z += n0.z; accn.w += n0.w;
    }
    int deg = s1 - s0;
    float inv = 1.0f / (float)(deg > 0 ? deg : 1);
    accp.x *= inv; accp.y *= inv; accp.z *= inv; accp.w *= inv;
    accn.x *= inv; accn.y *= inv; accn.z *= inv; accn.w *= inv;
    ap[warp * 32 + lane] = accp;
    an[warp * 32 + lane] = accn;
}

// ---------------- fused GEMM (R7-proven core) ----------------
// C = A1@W1 [+ A2@W2] + bias, optional relu. 512 thr, 128-row tile, 4r x 8c/thread.
// PIDX: phase-0 A row indirection via pidx[] (layer-0 negative stream = perm).
// PAIRG: A row = h[ga[r]]*h[gb[r]] (predictor; rows>=EPAIR use ga2/gb2).
template <bool DUAL, bool PAIRG, bool PIDX>
__global__ void __launch_bounds__(512, 1)
gemm_v4(const float4* __restrict__ A1p, const float4* __restrict__ A1n,
        const float4* __restrict__ A2p, const float4* __restrict__ A2n,
        const float4* __restrict__ W1, const float4* __restrict__ W2,
        const float* __restrict__ bias,
        float4* __restrict__ Cp, float4* __restrict__ Cn,
        const int* __restrict__ pidxP, const int* __restrict__ pidxN,
        const int* __restrict__ ga, const int* __restrict__ gb,
        const int* __restrict__ ga2, const int* __restrict__ gb2,
        int M, int relu) {
    extern __shared__ float4 smem[];
    float4* sA = smem;          // [128][32]
    float4* sB = smem + 4096;   // [128][32]

    int t = threadIdx.x;
    int rowBase = blockIdx.x * 128;
    int strm = blockIdx.y;

    const float4* A1 = strm ? A1n : A1p;
    const float4* A2 = strm ? A2n : A2p;
    float4* C = strm ? Cn : Cp;
    const int* pidx = strm ? pidxN : pidxP;

    int c8 = t & 15;
    int r0 = (t >> 4) * 4;
    const ulonglong2* sB2 = (const ulonglong2*)sB;

    unsigned long long acc[4][4];
#pragma unroll
    for (int i = 0; i < 4; i++)
#pragma unroll
        for (int j = 0; j < 4; j++) acc[i][j] = 0ULL;

#pragma unroll
    for (int ph = 0; ph < (DUAL ? 2 : 1); ph++) {
        if (ph) __syncthreads();
        const float4* W = ph ? W2 : W1;
        const float4* A = ph ? A2 : A1;
#pragma unroll
        for (int i = 0; i < 8; i++) sB[t + i * 512] = W[t + i * 512];
#pragma unroll
        for (int i = 0; i < 8; i++) {
            int p = t + i * 512;
            int r = p >> 5, kq = p & 31;
            int row = rowBase + r;
            float4 v = make_float4(0.f, 0.f, 0.f, 0.f);
            if (row < M) {
                if (PAIRG) {
                    const int* A_ = (row < EPAIR) ? ga : ga2;
                    const int* B_ = (row < EPAIR) ? gb : gb2;
                    int rr = (row < EPAIR) ? row : row - EPAIR;
                    float4 u = A[A_[rr] * 32 + kq];
                    float4 w = A[B_[rr] * 32 + kq];
                    v = make_float4(u.x * w.x, u.y * w.y, u.z * w.z, u.w * w.w);
                } else {
                    int rr = row;
                    if (PIDX && ph == 0 && pidx) rr = __ldg(&pidx[row]);
                    v = A[rr * 32 + kq];
                }
            }
            sA[r * 32 + kq] = v;
        }
        __syncthreads();

#pragma unroll 4
        for (int k4 = 0; k4 < 32; k4++) {
            float4 a0 = sA[(r0 + 0) * 32 + k4];
            float4 a1 = sA[(r0 + 1) * 32 + k4];
            float4 a2 = sA[(r0 + 2) * 32 + k4];
            float4 a3 = sA[(r0 + 3) * 32 + k4];
#pragma unroll
            for (int kk = 0; kk < 4; kk++) {
                int k = k4 * 4 + kk;
                ulonglong2 p0 = sB2[k * 32 + c8];
                ulonglong2 p1 = sB2[k * 32 + 16 + c8];
                float f0 = kk == 0 ? a0.x : kk == 1 ? a0.y : kk == 2 ? a0.z : a0.w;
                float f1 = kk == 0 ? a1.x : kk == 1 ? a1.y : kk == 2 ? a1.z : a1.w;
                float f2 = kk == 0 ? a2.x : kk == 1 ? a2.y : kk == 2 ? a2.z : a2.w;
                float f3 = kk == 0 ? a3.x : kk == 1 ? a3.y : kk == 2 ? a3.z : a3.w;
                unsigned long long aa0 = pk2(f0, f0);
                unsigned long long aa1 = pk2(f1, f1);
                unsigned long long aa2 = pk2(f2, f2);
                unsigned long long aa3 = pk2(f3, f3);
                acc[0][0] = fma2(aa0, p0.x, acc[0][0]);
                acc[0][1] = fma2(aa0, p0.y, acc[0][1]);
                acc[0][2] = fma2(aa0, p1.x, acc[0][2]);
                acc[0][3] = fma2(aa0, p1.y, acc[0][3]);
                acc[1][0] = fma2(aa1, p0.x, acc[1][0]);
                acc[1][1] = fma2(aa1, p0.y, acc[1][1]);
                acc[1][2] = fma2(aa1, p1.x, acc[1][2]);
                acc[1][3] = fma2(aa1, p1.y, acc[1][3]);
                acc[2][0] = fma2(aa2, p0.x, acc[2][0]);
                acc[2][1] = fma2(aa2, p0.y, acc[2][1]);
                acc[2][2] = fma2(aa2, p1.x, acc[2][2]);
                acc[2][3] = fma2(aa2, p1.y, acc[2][3]);
                acc[3][0] = fma2(aa3, p0.x, acc[3][0]);
                acc[3][1] = fma2(aa3, p0.y, acc[3][1]);
                acc[3][2] = fma2(aa3, p1.x, acc[3][2]);
                acc[3][3] = fma2(aa3, p1.y, acc[3][3]);
            }
        }
    }

    float4 bv0 = make_float4(0.f, 0.f, 0.f, 0.f);
    float4 bv1 = make_float4(0.f, 0.f, 0.f, 0.f);
    if (bias) {
        bv0 = ((const float4*)bias)[c8];
        bv1 = ((const float4*)bias)[16 + c8];
    }

#pragma unroll
    for (int i = 0; i < 4; i++) {
        int row = rowBase + r0 + i;
        if (row >= M) continue;
        float4 o0, o1;
        upk2(acc[i][0], o0.x, o0.y);
        upk2(acc[i][1], o0.z, o0.w);
        upk2(acc[i][2], o1.x, o1.y);
        upk2(acc[i][3], o1.z, o1.w);
        o0.x += bv0.x; o0.y += bv0.y; o0.z += bv0.z; o0.w += bv0.w;
        o1.x += bv1.x; o1.y += bv1.y; o1.z += bv1.z; o1.w += bv1.w;
        if (relu) {
            o0.x = fmaxf(o0.x, 0.f); o0.y = fmaxf(o0.y, 0.f);
            o0.z = fmaxf(o0.z, 0.f); o0.w = fmaxf(o0.w, 0.f);
            o1.x = fmaxf(o1.x, 0.f); o1.y = fmaxf(o1.y, 0.f);
            o1.z = fmaxf(o1.z, 0.f); o1.w = fmaxf(o1.w, 0.f);
        }
        C[row * 32 + c8]      = o0;
        C[row * 32 + 16 + c8] = o1;
    }
}

// per-column stats, both streams via grid.y
__global__ void k_colstats2(const float* __restrict__ Hp, const float* __restrict__ Hn,
                            int M, float* __restrict__ stats) {
    const float* H = blockIdx.y ? Hn : Hp;
    float* sum = stats + blockIdx.y * 2 * D;
    float* sq  = sum + D;
    int c = threadIdx.x;
    int r0 = blockIdx.x * 256;
    int rend = r0 + 256; if (rend > M) rend = M;
    float s = 0.f, s2 = 0.f;
    for (int r = r0; r < rend; r++) {
        float v = H[r * D + c];
        s += v; s2 += v * v;
    }
    atomicAdd(&sum[c], s);
    atomicAdd(&sq[c], s2);
}

__global__ void k_bnrelu2(float* __restrict__ Hp, float* __restrict__ Hn,
                          const float* __restrict__ stats,
                          const float* __restrict__ gamma, const float* __restrict__ beta,
                          int M) {
    int idx = blockIdx.x * blockDim.x + threadIdx.x;
    int tot = M * D;
    if (idx >= 2 * tot) return;
    int strm = idx >= tot;
    int i = idx - strm * tot;
    float* H = strm ? Hn : Hp;
    const float* st = stats + strm * 2 * D;
    int c = i & 127;
    float invM = 1.0f / (float)M;
    float m = st[c] * invM;
    float v = st[D + c] * invM - m * m;
    float y = gamma[c] * (H[i] - m) * rsqrtf(v + BN_EPS) + beta[c];
    H[i] = fmaxf(y, 0.f);
}

__global__ void k_colstats(const float* __restrict__ H, int M,
                           float* __restrict__ sum, float* __restrict__ sq) {
    int c = threadIdx.x;
    int r0 = blockIdx.x * 256;
    int rend = r0 + 256; if (rend > M) rend = M;
    float s = 0.f, s2 = 0.f;
    for (int r = r0; r < rend; r++) {
        float v = H[r * D + c];
        s += v; s2 += v * v;
    }
    atomicAdd(&sum[c], s);
    atomicAdd(&sq[c], s2);
}

__global__ void k_summary_ws(const float* __restrict__ colsum,
                             const float* __restrict__ discW, float* __restrict__ ws) {
    __shared__ float sm[D];
    int t = threadIdx.x;
    float mn = colsum[t] / (float)N3;
    sm[t] = 1.0f / (1.0f + expf(-mn));
    __syncthreads();
    float a = 0.f;
#pragma unroll 8
    for (int j = 0; j < D; j++) a += discW[t * D + j] * sm[j];
    ws[t] = a;
}

__device__ __forceinline__ float warp_dot128(const float4* __restrict__ a,
                                             const float4* __restrict__ b, int lane) {
    float4 x = a[lane], y = b[lane];
    float s = x.x * y.x + x.y * y.y + x.z * y.z + x.w * y.w;
#pragma unroll
    for (int o = 16; o; o >>= 1) s += __shfl_down_sync(0xffffffffu, s, o);
    return s;
}

__global__ void k_loss(const float4* __restrict__ pos, const float4* __restrict__ neg,
                       const float4* __restrict__ ws, float* __restrict__ loss) {
    int tid = blockIdx.x * blockDim.x + threadIdx.x;
    int e = tid >> 5;
    if (e >= 2 * N3) return;
    int lane = tid & 31;
    int strm = (e >= N3);
    int r = e - strm * N3;
    const float4* row = (strm ? neg : pos) + r * 32;
    float s = warp_dot128(row, ws, lane);
    if (lane == 0) {
        float xx = strm ? s : -s;
        float sp = fmaxf(xx, 0.f) + log1pf(expf(-fabsf(xx)));
        atomicAdd(&loss[strm], sp);
    }
}

__global__ void k_pred_out(const float4* __restrict__ z, const float4* __restrict__ w3,
                           const float* __restrict__ b3, float* __restrict__ out) {
    int tid = blockIdx.x * blockDim.x + threadIdx.x;
    int e = tid >> 5;
    if (e >= 2 * EPAIR) return;
    int lane = tid & 31;
    float s = warp_dot128(z + e * 32, w3, lane);
    if (lane == 0) out[e] = s + b3[0];
}

__global__ void k_final_loss(const float* __restrict__ loss, float* __restrict__ out) {
    out[0] = (loss[0] + loss[1]) * (1.0f / (float)N3);
}

// ---------------- host orchestration ----------------
extern "C" void kernel_launch(void* const* d_in, const int* in_sizes, int n_in,
                              void* d_out, int out_size) {
    const float* x      = (const float*)d_in[0];
    const int* srcs[3]  = {(const int*)d_in[1], (const int*)d_in[3], (const int*)d_in[5]};
    const int* dsts[3]  = {(const int*)d_in[2], (const int*)d_in[4], (const int*)d_in[6]};
    const int* perm     = (const int*)d_in[7];
    const int* pos_src  = (const int*)d_in[8];
    const int* pos_dst  = (const int*)d_in[9];
    const int* neg_src  = (const int*)d_in[10];
    const int* neg_dst  = (const int*)d_in[11];
    const float* Ws[3]  = {(const float*)d_in[12], (const float*)d_in[15], (const float*)d_in[18]};
    const float* Wn[3]  = {(const float*)d_in[13], (const float*)d_in[16], (const float*)d_in[19]};
    const float* bb[3]  = {(const float*)d_in[14], (const float*)d_in[17], (const float*)d_in[20]};
    const float* gamma[2] = {(const float*)d_in[21], (const float*)d_in[23]};
    const float* beta [2] = {(const float*)d_in[22], (const float*)d_in[24]};
    const float* discW  = (const float*)d_in[25];
    const float* pW1 = (const float*)d_in[26]; const float* pb1 = (const float*)d_in[27];
    const float* pW2 = (const float*)d_in[28]; const float* pb2 = (const float*)d_in[29];
    const float* pW3 = (const float*)d_in[30]; const float* pb3 = (const float*)d_in[31];
    float* out = (float*)d_out;

    int E[3] = {in_sizes[1], in_sizes[3], in_sizes[5]};
    int ND[3] = {N1, N2, N3};
    int segbase[3] = {0, N1, N1 + N2};

    float *p_bufA, *p_bufB, *p_agg, *p_stats, *p_csum, *p_csq, *p_ws, *p_loss, *p_z, *p_z2;
    int *p_cnt, *p_off, *p_cur, *p_csr, *p_csr2;
    cudaGetSymbolAddress((void**)&p_bufA,  g_bufA);
    cudaGetSymbolAddress((void**)&p_bufB,  g_bufB);
    cudaGetSymbolAddress((void**)&p_agg,   g_agg);
    cudaGetSymbolAddress((void**)&p_cnt,   g_cnt);
    cudaGetSymbolAddress((void**)&p_off,   g_off);
    cudaGetSymbolAddress((void**)&p_cur,   g_cur);
    cudaGetSymbolAddress((void**)&p_csr,   g_csr);
    cudaGetSymbolAddress((void**)&p_csr2,  g_csr2);
    cudaGetSymbolAddress((void**)&p_stats, g_stats);
    cudaGetSymbolAddress((void**)&p_csum,  g_csum);
    cudaGetSymbolAddress((void**)&p_csq,   g_csq_dummy);
    cudaGetSymbolAddress((void**)&p_ws,    g_ws);
    cudaGetSymbolAddress((void**)&p_loss,  g_loss);
    cudaGetSymbolAddress((void**)&p_z,     g_z);
    cudaGetSymbolAddress((void**)&p_z2,    g_z2);

    const size_t GEMM_SMEM = 131072;
    cudaFuncSetAttribute(gemm_v4<true,  false, true >, cudaFuncAttributeMaxDynamicSharedMemorySize, GEMM_SMEM);
    cudaFuncSetAttribute(gemm_v4<true,  false, false>, cudaFuncAttributeMaxDynamicSharedMemorySize, GEMM_SMEM);
    cudaFuncSetAttribute(gemm_v4<false, true,  false>, cudaFuncAttributeMaxDynamicSharedMemorySize, GEMM_SMEM);
    cudaFuncSetAttribute(gemm_v4<false, false, false>, cudaFuncAttributeMaxDynamicSharedMemorySize, GEMM_SMEM);

    int Etot = E[0] + E[1] + E[2];

    // batched CSR build (csr2 = perm[src] for layer-0 segment)
    cudaMemsetAsync(p_cnt, 0, NTOT * sizeof(int), 0);
    cudaMemsetAsync(p_cur, 0, NTOT * sizeof(int), 0);
    k_count_all<<<(Etot + 255) / 256, 256>>>(dsts[0], E[0], dsts[1], E[1], dsts[2], E[2], p_cnt);
    k_scan<<<1, 1024>>>(p_cnt, NTOT, p_off);
    k_fill_all<<<(Etot + 255) / 256, 256>>>(srcs[0], dsts[0], E[0],
                                            srcs[1], dsts[1], E[1],
                                            srcs[2], dsts[2], E[2],
                                            perm, p_off, p_cur, p_csr, p_csr2);

    float* bufA[2] = {p_bufA, p_bufA + (size_t)N1 * D};
    float* bufB[2] = {p_bufB, p_bufB + (size_t)N2 * D};
    float* agg [2] = {p_agg,  p_agg  + (size_t)N1 * D};

    const float* hinP = x;
    const float* hinN = x;   // layer-0 negative: x with perm indirection

    for (int l = 0; l < 3; l++) {
        int nd = ND[l];
        float* outb[2];
        if (l == 1) { outb[0] = bufB[0]; outb[1] = bufB[1]; }
        else        { outb[0] = bufA[0]; outb[1] = bufA[1]; }

        const int* csrN = (l == 0) ? p_csr2 : p_csr;
        k_gather3<<<(nd * 32 + 255) / 256, 256>>>(
            (const float4*)hinP, (const float4*)hinN, p_csr, csrN,
            p_off + segbase[l], (float4*)agg[0], (float4*)agg[1], nd);

        dim3 grid((nd + 127) / 128, 2);
        if (l == 0) {
            gemm_v4<true, false, true><<<grid, 512, GEMM_SMEM>>>(
                (const float4*)hinP, (const float4*)hinN,
                (const float4*)agg[0], (const float4*)agg[1],
                (const float4*)Ws[l], (const float4*)Wn[l], bb[l],
                (float4*)outb[0], (float4*)outb[1],
                nullptr, perm, nullptr, nullptr, nullptr, nullptr, nd, 0);
        } else {
            gemm_v4<true, false, false><<<grid, 512, GEMM_SMEM>>>(
                (const float4*)hinP, (const float4*)hinN,
                (const float4*)agg[0], (const float4*)agg[1],
                (const float4*)Ws[l], (const float4*)Wn[l], bb[l],
                (float4*)outb[0], (float4*)outb[1],
                nullptr, nullptr, nullptr, nullptr, nullptr, nullptr, nd, 0);
        }

        if (l < 2) {
            cudaMemsetAsync(p_stats, 0, 2 * 2 * D * sizeof(float), 0);
            dim3 sgrid((nd + 255) / 256, 2);
            k_colstats2<<<sgrid, 128>>>(outb[0], outb[1], nd, p_stats);
            k_bnrelu2<<<(2 * nd * D + 255) / 256, 256>>>(outb[0], outb[1], p_stats,
                                                         gamma[l], beta[l], nd);
        }
        hinP = outb[0];
        hinN = outb[1];
    }

    float* positive = bufA[0];
    float* negative = bufA[1];

    cudaMemsetAsync(p_csum, 0, D * sizeof(float), 0);
    cudaMemsetAsync(p_loss, 0, 2 * sizeof(float), 0);
    k_colstats<<<(N3 + 255) / 256, 128>>>(positive, N3, p_csum, p_csq);
    k_summary_ws<<<1, 128>>>(p_csum, discW, p_ws);
    k_loss<<<(2 * N3 * 32 + 255) / 256, 256>>>((const float4*)positive,
                                               (const float4*)negative,
                                               (const float4*)p_ws, p_loss);

    // link predictor: 20000 rows, pair-product fused into GEMM1
    int Mp = 2 * EPAIR;
    dim3 pgrid((Mp + 127) / 128, 1);
    gemm_v4<false, true, false><<<pgrid, 512, GEMM_SMEM>>>(
        (const float4*)positive, (const float4*)positive, nullptr, nullptr,
        (const float4*)pW1, nullptr, pb1, (float4*)p_z2, (float4*)p_z2,
        nullptr, nullptr, pos_src, pos_dst, neg_src, neg_dst, Mp, 1);
    gemm_v4<false, false, false><<<pgrid, 512, GEMM_SMEM>>>(
        (const float4*)p_z2, (const float4*)p_z2, nullptr, nullptr,
        (const float4*)pW2, nullptr, pb2, (float4*)p_z, (float4*)p_z,
        nullptr, nullptr, nullptr, nullptr, nullptr, nullptr, Mp, 1);
    k_pred_out<<<(Mp * 32 + 255) / 256, 256>>>((const float4*)p_z,
                                               (const float4*)pW3, pb3, out);

    k_final_loss<<<1, 1>>>(p_loss, out + 2 * EPAIR);
}

// round 11
// speedup vs baseline: 1.9088x; 1.1188x over previous
#include <cuda_runtime.h>
#include <cuda_bf16.h>
#include <math.h>

#define N0 100000
#define N1 50000
#define N2 25000
#define N3 12500
#define D  128
#define EPAIR 10000
#define NTOT 87500
#define ETOT 1125000
#define BN_EPS 1e-5f

typedef unsigned int u32;
typedef unsigned short u16;
typedef unsigned long long u64;

// ---------------- scratch ----------------
__device__ float g_bufA[2][N1 * D];
__device__ float g_bufB[2][N2 * D];
__device__ float g_agg [2][N1 * D];
__device__ int   g_cnt [NTOT];
__device__ int   g_off [NTOT + 1];
__device__ int   g_cur [NTOT];
__device__ int   g_csr [ETOT];
__device__ int   g_csr2[ETOT];
__device__ float g_stats[2][2][D];
__device__ float g_csum[D];
__device__ float g_csq_dummy[D];
__device__ float g_ws[D];
__device__ float g_loss[2];
__device__ float g_z [2 * EPAIR * D];
__device__ float g_z2[2 * EPAIR * D];
// pre-split/transposed weights: [matrix][n*128+k], hi and lo bf16 planes
__device__ __nv_bfloat16 g_wth[6][D * D];
__device__ __nv_bfloat16 g_wtl[6][D * D];

// ---------------- f32x2 helpers (predictor GEMM) ----------------
__device__ __forceinline__ u64 pk2(float x, float y) {
    u64 r; asm("mov.b64 %0, {%1, %2};" : "=l"(r) : "f"(x), "f"(y)); return r;
}
__device__ __forceinline__ void upk2(u64 v, float& x, float& y) {
    asm("mov.b64 {%0, %1}, %2;" : "=f"(x), "=f"(y) : "l"(v));
}
__device__ __forceinline__ u64 fma2(u64 a, u64 b, u64 c) {
    u64 d; asm("fma.rn.f32x2 %0, %1, %2, %3;" : "=l"(d) : "l"(a), "l"(b), "l"(c)); return d;
}

// ---------------- bf16 split helpers ----------------
__device__ __forceinline__ void split_bf16(float x, u16& hi, u16& lo) {
    __nv_bfloat16 h = __float2bfloat16(x);
    float hf = __bfloat162float(h);
    __nv_bfloat16 l = __float2bfloat16(x - hf);
    hi = __bfloat16_as_ushort(h);
    lo = __bfloat16_as_ushort(l);
}
__device__ __forceinline__ void mma_bf16(float* d, const u32* a, const u32* b) {
    asm volatile(
        "mma.sync.aligned.m16n8k16.row.col.f32.bf16.bf16.f32 "
        "{%0,%1,%2,%3}, {%4,%5,%6,%7}, {%8,%9}, {%0,%1,%2,%3};"
        : "+f"(d[0]), "+f"(d[1]), "+f"(d[2]), "+f"(d[3])
        : "r"(a[0]), "r"(a[1]), "r"(a[2]), "r"(a[3]), "r"(b[0]), "r"(b[1]));
}

// ---------------- CSR build ----------------
__global__ void k_count_all(const int* __restrict__ d0, int E0,
                            const int* __restrict__ d1, int E1,
                            const int* __restrict__ d2, int E2,
                            int* __restrict__ cnt) {
    int e = blockIdx.x * blockDim.x + threadIdx.x;
    if (e < E0) atomicAdd(&cnt[d0[e]], 1);
    else if (e < E0 + E1) atomicAdd(&cnt[N1 + d1[e - E0]], 1);
    else if (e < E0 + E1 + E2) atomicAdd(&cnt[N1 + N2 + d2[e - E0 - E1]], 1);
}

__global__ void k_scan(const int* __restrict__ cnt, int n, int* __restrict__ off) {
    __shared__ int wsum[32];
    int t = threadIdx.x, lane = t & 31, wid = t >> 5;
    int carry = 0;
    for (int base = 0; base < n; base += 8192) {
        int v[8]; int s = 0;
#pragma unroll
        for (int u = 0; u < 8; u++) {
            int i = base + t * 8 + u;
            v[u] = (i < n) ? cnt[i] : 0;
            s += v[u];
        }
        int ps = s;
#pragma unroll
        for (int o = 1; o < 32; o <<= 1) {
            int x = __shfl_up_sync(0xffffffffu, ps, o);
            if (lane >= o) ps += x;
        }
        if (lane == 31) wsum[wid] = ps;
        __syncthreads();
        if (t < 32) {
            int x = wsum[t];
#pragma unroll
            for (int o = 1; o < 32; o <<= 1) {
                int y = __shfl_up_sync(0xffffffffu, x, o);
                if (t >= o) x += y;
            }
            wsum[t] = x;
        }
        __syncthreads();
        int warpbase = wid ? wsum[wid - 1] : 0;
        int run = carry + warpbase + (ps - s);
#pragma unroll
        for (int u = 0; u < 8; u++) {
            int i = base + t * 8 + u;
            if (i < n) off[i] = run;
            run += v[u];
        }
        carry += wsum[31];
        __syncthreads();
    }
    if (t == 0) off[n] = carry;
}

__global__ void k_fill_all(const int* __restrict__ s0, const int* __restrict__ d0, int E0,
                           const int* __restrict__ s1, const int* __restrict__ d1, int E1,
                           const int* __restrict__ s2, const int* __restrict__ d2, int E2,
                           const int* __restrict__ perm,
                           const int* __restrict__ off, int* __restrict__ cur,
                           int* __restrict__ csr, int* __restrict__ csr2) {
    int e = blockIdx.x * blockDim.x + threadIdx.x;
    int src, node, alt;
    if (e < E0) { src = s0[e]; node = d0[e]; alt = __ldg(&perm[src]); }
    else if (e < E0 + E1) { int i = e - E0; src = s1[i]; node = N1 + d1[i]; alt = src; }
    else if (e < E0 + E1 + E2) { int i = e - E0 - E1; src = s2[i]; node = N1 + N2 + d2[i]; alt = src; }
    else return;
    int p = off[node] + atomicAdd(&cur[node], 1);
    csr[p] = src;
    csr2[p] = alt;
}

// ---------------- weight prep: split fp32 W[k][n] into bf16 Wt[n][k] hi/lo ----------------
__global__ void k_prep_w(const float4* __restrict__ W0, const float4* __restrict__ W1,
                         const float4* __restrict__ W2, const float4* __restrict__ W3,
                         const float4* __restrict__ W4, const float4* __restrict__ W5) {
    int m = blockIdx.y;
    const float4* W = m == 0 ? W0 : m == 1 ? W1 : m == 2 ? W2 : m == 3 ? W3 : m == 4 ? W4 : W5;
    __nv_bfloat16* Th = g_wth[m];
    __nv_bfloat16* Tl = g_wtl[m];
    int t = threadIdx.x;
#pragma unroll
    for (int i = 0; i < 16; i++) {
        int idx = t + i * 256;          // float4 index over [128][32]
        int k = idx >> 5, nq = idx & 31;
        float4 v = W[idx];
        float xs[4] = {v.x, v.y, v.z, v.w};
#pragma unroll
        for (int j = 0; j < 4; j++) {
            int n = nq * 4 + j;
            u16 hi, lo;
            split_bf16(xs[j], hi, lo);
            Th[n * D + k] = __ushort_as_bfloat16(hi);
            Tl[n * D + k] = __ushort_as_bfloat16(lo);
        }
    }
}

// ---------------- gather: neighbor mean for BOTH streams, 4-edge unroll ----------------
__global__ void k_gather3(const float4* __restrict__ hp, const float4* __restrict__ hn,
                          const int* __restrict__ csrP, const int* __restrict__ csrN,
                          const int* __restrict__ off,
                          float4* __restrict__ ap, float4* __restrict__ an, int M) {
    int warp = (blockIdx.x * blockDim.x + threadIdx.x) >> 5;
    if (warp >= M) return;
    int lane = threadIdx.x & 31;
    int s0 = off[warp], s1 = off[warp + 1];
    float4 accp = make_float4(0.f, 0.f, 0.f, 0.f);
    float4 accn = make_float4(0.f, 0.f, 0.f, 0.f);
    int j = s0;
    for (; j + 4 <= s1; j += 4) {
        int a0 = __ldg(&csrP[j]),     a1 = __ldg(&csrP[j + 1]);
        int a2 = __ldg(&csrP[j + 2]), a3 = __ldg(&csrP[j + 3]);
        int b0 = __ldg(&csrN[j]),     b1 = __ldg(&csrN[j + 1]);
        int b2 = __ldg(&csrN[j + 2]), b3 = __ldg(&csrN[j + 3]);
        float4 p0 = hp[a0 * 32 + lane], p1 = hp[a1 * 32 + lane];
        float4 p2 = hp[a2 * 32 + lane], p3 = hp[a3 * 32 + lane];
        float4 n0 = hn[b0 * 32 + lane], n1 = hn[b1 * 32 + lane];
        float4 n2 = hn[b2 * 32 + lane], n3 = hn[b3 * 32 + lane];
        accp.x += (p0.x + p1.x) + (p2.x + p3.x);
        accp.y += (p0.y + p1.y) + (p2.y + p3.y);
        accp.z += (p0.z + p1.z) + (p2.z + p3.z);
        accp.w += (p0.w + p1.w) + (p2.w + p3.w);
        accn.x += (n0.x + n1.x) + (n2.x + n3.x);
        accn.y += (n0.y + n1.y) + (n2.y + n3.y);
        accn.z += (n0.z + n1.z) + (n2.z + n3.z);
        accn.w += (n0.w + n1.w) + (n2.w + n3.w);
    }
    for (; j < s1; j++) {
        int a0 = __ldg(&csrP[j]);
        int b0 = __ldg(&csrN[j]);
        float4 p0 = hp[a0 * 32 + lane];
        float4 n0 = hn[b0 * 32 + lane];
        accp.x += p0.x; accp.y += p0.y; accp.z += p0.z; accp.w += p0.w;
        accn.x += n0.x; accn.y += n0.y; accn.z += n0.z; accn.w += n0.w;
    }
    int deg = s1 - s0;
    float inv = 1.0f / (float)(deg > 0 ? deg : 1);
    accp.x *= inv; accp.y *= inv; accp.z *= inv; accp.w *= inv;
    accn.x *= inv; accn.y *= inv; accn.z *= inv; accn.w *= inv;
    ap[warp * 32 + lane] = accp;
    an[warp * 32 + lane] = accn;
}

// ---------------- mma.sync bf16-split layer GEMM ----------------
// C = A1@W1 + A2@W2 + bias, K=128 per phase, fp32 accum in registers.
// 256 threads, 128x128 tile. Warp grid 2(m) x 4(n); warp tile 64x32.
// Smem planes padded to 272B pitch (conflict-free fragment loads).
#define GP_BYTES 272
#define PLANE (128 * GP_BYTES)
#define MMA_SMEM (4 * PLANE)

template <bool PIDX>
__global__ void __launch_bounds__(256, 1)
gemm_mma(const float4* __restrict__ A1p, const float4* __restrict__ A1n,
         const float4* __restrict__ A2p, const float4* __restrict__ A2n,
         const __nv_bfloat16* __restrict__ W1h, const __nv_bfloat16* __restrict__ W1l,
         const __nv_bfloat16* __restrict__ W2h, const __nv_bfloat16* __restrict__ W2l,
         const float* __restrict__ bias,
         float4* __restrict__ Cp, float4* __restrict__ Cn,
         const int* __restrict__ pidxN, int M) {
    extern __shared__ char smem[];
    char* sAh = smem;
    char* sAl = smem + PLANE;
    char* sBh = smem + 2 * PLANE;
    char* sBl = smem + 3 * PLANE;

    int t = threadIdx.x, lane = t & 31, wid = t >> 5;
    int strm = blockIdx.y;
    int rowBase = blockIdx.x * 128;

    const float4* A1 = strm ? A1n : A1p;
    const float4* A2 = strm ? A2n : A2p;
    float4* C = strm ? Cn : Cp;

    float acc[4][4][4];
#pragma unroll
    for (int i = 0; i < 4; i++)
#pragma unroll
        for (int j = 0; j < 4; j++)
#pragma unroll
            for (int r = 0; r < 4; r++) acc[i][j][r] = 0.f;

    int M0 = (wid >> 2) * 64;
    int Nb = (wid & 3) * 32;
    int g = lane >> 2, q = lane & 3;

#pragma unroll
    for (int ph = 0; ph < 2; ph++) {
        if (ph) __syncthreads();
        const float4* A = ph ? A2 : A1;
        const uint4* Wh4 = (const uint4*)(ph ? W2h : W1h);
        const uint4* Wl4 = (const uint4*)(ph ? W2l : W1l);

        // W planes: dense [n][k] bf16 rows of 256B -> padded smem rows
#pragma unroll
        for (int i = 0; i < 8; i++) {
            int idx = t + i * 256;          // uint4 id over [128][16]
            int row = idx >> 4, c = idx & 15;
            *(uint4*)(sBh + row * GP_BYTES + c * 16) = Wh4[idx];
            *(uint4*)(sBl + row * GP_BYTES + c * 16) = Wl4[idx];
        }
        // A tile: fp32 -> split bf16 hi/lo
#pragma unroll
        for (int i = 0; i < 16; i++) {
            int idx = t + i * 256;          // float4 id over [128][32]
            int row = idx >> 5, kq = idx & 31;
            float4 v = make_float4(0.f, 0.f, 0.f, 0.f);
            int grow = rowBase + row;
            if (grow < M) {
                int rr = grow;
                if (PIDX) { if (strm && ph == 0) rr = __ldg(&pidxN[grow]); }
                v = A[rr * 32 + kq];
            }
            u16 h0, l0, h1, l1, h2, l2, h3, l3;
            split_bf16(v.x, h0, l0); split_bf16(v.y, h1, l1);
            split_bf16(v.z, h2, l2); split_bf16(v.w, h3, l3);
            uint2 ph2, pl2;
            ph2.x = ((u32)h1 << 16) | h0; ph2.y = ((u32)h3 << 16) | h2;
            pl2.x = ((u32)l1 << 16) | l0; pl2.y = ((u32)l3 << 16) | l2;
            *(uint2*)(sAh + row * GP_BYTES + kq * 8) = ph2;
            *(uint2*)(sAl + row * GP_BYTES + kq * 8) = pl2;
        }
        __syncthreads();

#pragma unroll
        for (int kc = 0; kc < 8; kc++) {
            int k0 = kc * 16;
            u32 bh[4][2], bl[4][2];
#pragma unroll
            for (int fn = 0; fn < 4; fn++) {
                int n = Nb + fn * 8 + g;
                const char* pb = (const char*)(u64)(n * GP_BYTES + (k0 + q * 2) * 2);
                bh[fn][0] = *(const u32*)(sBh + (u64)pb);
                bh[fn][1] = *(const u32*)(sBh + (u64)pb + 16);
                bl[fn][0] = *(const u32*)(sBl + (u64)pb);
                bl[fn][1] = *(const u32*)(sBl + (u64)pb + 16);
            }
#pragma unroll
            for (int fm = 0; fm < 4; fm++) {
                int r = M0 + fm * 16 + g;
                u64 ao = (u64)(r * GP_BYTES + (k0 + q * 2) * 2);
                u32 ah[4], al[4];
                ah[0] = *(const u32*)(sAh + ao);
                ah[1] = *(const u32*)(sAh + ao + 8 * GP_BYTES);
                ah[2] = *(const u32*)(sAh + ao + 16);
                ah[3] = *(const u32*)(sAh + ao + 8 * GP_BYTES + 16);
                al[0] = *(const u32*)(sAl + ao);
                al[1] = *(const u32*)(sAl + ao + 8 * GP_BYTES);
                al[2] = *(const u32*)(sAl + ao + 16);
                al[3] = *(const u32*)(sAl + ao + 8 * GP_BYTES + 16);
#pragma unroll
                for (int fn = 0; fn < 4; fn++) {
                    mma_bf16(acc[fm][fn], ah, bh[fn]);
                    mma_bf16(acc[fm][fn], ah, bl[fn]);
                    mma_bf16(acc[fm][fn], al, bh[fn]);
                }
            }
        }
    }

    // epilogue: D fragment layout -> gmem + bias
    float* Cf = (float*)C;
#pragma unroll
    for (int fn = 0; fn < 4; fn++) {
        int col = Nb + fn * 8 + q * 2;
        float2 bv = *(const float2*)(bias + col);
#pragma unroll
        for (int fm = 0; fm < 4; fm++) {
            int row0 = rowBase + M0 + fm * 16 + g;
            int row1 = row0 + 8;
            if (row0 < M) {
                float2 o = make_float2(acc[fm][fn][0] + bv.x, acc[fm][fn][1] + bv.y);
                *(float2*)(Cf + row0 * D + col) = o;
            }
            if (row1 < M) {
                float2 o = make_float2(acc[fm][fn][2] + bv.x, acc[fm][fn][3] + bv.y);
                *(float2*)(Cf + row1 * D + col) = o;
            }
        }
    }
}

// ---------------- f32x2 GEMM (predictor only, R9-proven) ----------------
template <bool PAIRG>
__global__ void __launch_bounds__(512, 1)
gemm_v4(const float4* __restrict__ A, const float4* __restrict__ W,
        const float* __restrict__ bias, float4* __restrict__ C,
        const int* __restrict__ ga, const int* __restrict__ gb,
        const int* __restrict__ ga2, const int* __restrict__ gb2,
        int M, int relu) {
    extern __shared__ float4 smem4[];
    float4* sA = smem4;
    float4* sB = smem4 + 4096;

    int t = threadIdx.x;
    int rowBase = blockIdx.x * 128;
    int c8 = t & 15;
    int r0 = (t >> 4) * 4;
    const ulonglong2* sB2 = (const ulonglong2*)sB;

    u64 acc[4][4];
#pragma unroll
    for (int i = 0; i < 4; i++)
#pragma unroll
        for (int j = 0; j < 4; j++) acc[i][j] = 0ULL;

#pragma unroll
    for (int i = 0; i < 8; i++) sB[t + i * 512] = W[t + i * 512];
#pragma unroll
    for (int i = 0; i < 8; i++) {
        int p = t + i * 512;
        int r = p >> 5, kq = p & 31;
        int row = rowBase + r;
        float4 v = make_float4(0.f, 0.f, 0.f, 0.f);
        if (row < M) {
            if (PAIRG) {
                const int* A_ = (row < EPAIR) ? ga : ga2;
                const int* B_ = (row < EPAIR) ? gb : gb2;
                int rr = (row < EPAIR) ? row : row - EPAIR;
                float4 u = A[A_[rr] * 32 + kq];
                float4 w = A[B_[rr] * 32 + kq];
                v = make_float4(u.x * w.x, u.y * w.y, u.z * w.z, u.w * w.w);
            } else {
                v = A[row * 32 + kq];
            }
        }
        sA[r * 32 + kq] = v;
    }
    __syncthreads();

#pragma unroll 4
    for (int k4 = 0; k4 < 32; k4++) {
        float4 a0 = sA[(r0 + 0) * 32 + k4];
        float4 a1 = sA[(r0 + 1) * 32 + k4];
        float4 a2 = sA[(r0 + 2) * 32 + k4];
        float4 a3 = sA[(r0 + 3) * 32 + k4];
#pragma unroll
        for (int kk = 0; kk < 4; kk++) {
            int k = k4 * 4 + kk;
            ulonglong2 p0 = sB2[k * 32 + c8];
            ulonglong2 p1 = sB2[k * 32 + 16 + c8];
            float f0 = kk == 0 ? a0.x : kk == 1 ? a0.y : kk == 2 ? a0.z : a0.w;
            float f1 = kk == 0 ? a1.x : kk == 1 ? a1.y : kk == 2 ? a1.z : a1.w;
            float f2 = kk == 0 ? a2.x : kk == 1 ? a2.y : kk == 2 ? a2.z : a2.w;
            float f3 = kk == 0 ? a3.x : kk == 1 ? a3.y : kk == 2 ? a3.z : a3.w;
            u64 aa0 = pk2(f0, f0);
            u64 aa1 = pk2(f1, f1);
            u64 aa2 = pk2(f2, f2);
            u64 aa3 = pk2(f3, f3);
            acc[0][0] = fma2(aa0, p0.x, acc[0][0]);
            acc[0][1] = fma2(aa0, p0.y, acc[0][1]);
            acc[0][2] = fma2(aa0, p1.x, acc[0][2]);
            acc[0][3] = fma2(aa0, p1.y, acc[0][3]);
            acc[1][0] = fma2(aa1, p0.x, acc[1][0]);
            acc[1][1] = fma2(aa1, p0.y, acc[1][1]);
            acc[1][2] = fma2(aa1, p1.x, acc[1][2]);
            acc[1][3] = fma2(aa1, p1.y, acc[1][3]);
            acc[2][0] = fma2(aa2, p0.x, acc[2][0]);
            acc[2][1] = fma2(aa2, p0.y, acc[2][1]);
            acc[2][2] = fma2(aa2, p1.x, acc[2][2]);
            acc[2][3] = fma2(aa2, p1.y, acc[2][3]);
            acc[3][0] = fma2(aa3, p0.x, acc[3][0]);
            acc[3][1] = fma2(aa3, p0.y, acc[3][1]);
            acc[3][2] = fma2(aa3, p1.x, acc[3][2]);
            acc[3][3] = fma2(aa3, p1.y, acc[3][3]);
        }
    }

    float4 bv0 = ((const float4*)bias)[c8];
    float4 bv1 = ((const float4*)bias)[16 + c8];

#pragma unroll
    for (int i = 0; i < 4; i++) {
        int row = rowBase + r0 + i;
        if (row >= M) continue;
        float4 o0, o1;
        upk2(acc[i][0], o0.x, o0.y);
        upk2(acc[i][1], o0.z, o0.w);
        upk2(acc[i][2], o1.x, o1.y);
        upk2(acc[i][3], o1.z, o1.w);
        o0.x += bv0.x; o0.y += bv0.y; o0.z += bv0.z; o0.w += bv0.w;
        o1.x += bv1.x; o1.y += bv1.y; o1.z += bv1.z; o1.w += bv1.w;
        if (relu) {
            o0.x = fmaxf(o0.x, 0.f); o0.y = fmaxf(o0.y, 0.f);
            o0.z = fmaxf(o0.z, 0.f); o0.w = fmaxf(o0.w, 0.f);
            o1.x = fmaxf(o1.x, 0.f); o1.y = fmaxf(o1.y, 0.f);
            o1.z = fmaxf(o1.z, 0.f); o1.w = fmaxf(o1.w, 0.f);
        }
        C[row * 32 + c8]      = o0;
        C[row * 32 + 16 + c8] = o1;
    }
}

// per-column stats, both streams via grid.y
__global__ void k_colstats2(const float* __restrict__ Hp, const float* __restrict__ Hn,
                            int M, float* __restrict__ stats) {
    const float* H = blockIdx.y ? Hn : Hp;
    float* sum = stats + blockIdx.y * 2 * D;
    float* sq  = sum + D;
    int c = threadIdx.x;
    int r0 = blockIdx.x * 256;
    int rend = r0 + 256; if (rend > M) rend = M;
    float s = 0.f, s2 = 0.f;
    for (int r = r0; r < rend; r++) {
        float v = H[r * D + c];
        s += v; s2 += v * v;
    }
    atomicAdd(&sum[c], s);
    atomicAdd(&sq[c], s2);
}

__global__ void k_bnrelu2(float* __restrict__ Hp, float* __restrict__ Hn,
                          const float* __restrict__ stats,
                          const float* __restrict__ gamma, const float* __restrict__ beta,
                          int M) {
    int idx = blockIdx.x * blockDim.x + threadIdx.x;
    int tot = M * D;
    if (idx >= 2 * tot) return;
    int strm = idx >= tot;
    int i = idx - strm * tot;
    float* H = strm ? Hn : Hp;
    const float* st = stats + strm * 2 * D;
    int c = i & 127;
    float invM = 1.0f / (float)M;
    float m = st[c] * invM;
    float v = st[D + c] * invM - m * m;
    float y = gamma[c] * (H[i] - m) * rsqrtf(v + BN_EPS) + beta[c];
    H[i] = fmaxf(y, 0.f);
}

__global__ void k_colstats(const float* __restrict__ H, int M,
                           float* __restrict__ sum, float* __restrict__ sq) {
    int c = threadIdx.x;
    int r0 = blockIdx.x * 256;
    int rend = r0 + 256; if (rend > M) rend = M;
    float s = 0.f, s2 = 0.f;
    for (int r = r0; r < rend; r++) {
        float v = H[r * D + c];
        s += v; s2 += v * v;
    }
    atomicAdd(&sum[c], s);
    atomicAdd(&sq[c], s2);
}

__global__ void k_summary_ws(const float* __restrict__ colsum,
                             const float* __restrict__ discW, float* __restrict__ ws) {
    __shared__ float sm[D];
    int t = threadIdx.x;
    float mn = colsum[t] / (float)N3;
    sm[t] = 1.0f / (1.0f + expf(-mn));
    __syncthreads();
    float a = 0.f;
#pragma unroll 8
    for (int j = 0; j < D; j++) a += discW[t * D + j] * sm[j];
    ws[t] = a;
}

__device__ __forceinline__ float warp_dot128(const float4* __restrict__ a,
                                             const float4* __restrict__ b, int lane) {
    float4 x = a[lane], y = b[lane];
    float s = x.x * y.x + x.y * y.y + x.z * y.z + x.w * y.w;
#pragma unroll
    for (int o = 16; o; o >>= 1) s += __shfl_down_sync(0xffffffffu, s, o);
    return s;
}

__global__ void k_loss(const float4* __restrict__ pos, const float4* __restrict__ neg,
                       const float4* __restrict__ ws, float* __restrict__ loss) {
    int tid = blockIdx.x * blockDim.x + threadIdx.x;
    int e = tid >> 5;
    if (e >= 2 * N3) return;
    int lane = tid & 31;
    int strm = (e >= N3);
    int r = e - strm * N3;
    const float4* row = (strm ? neg : pos) + r * 32;
    float s = warp_dot128(row, ws, lane);
    if (lane == 0) {
        float xx = strm ? s : -s;
        float sp = fmaxf(xx, 0.f) + log1pf(expf(-fabsf(xx)));
        atomicAdd(&loss[strm], sp);
    }
}

__global__ void k_pred_out(const float4* __restrict__ z, const float4* __restrict__ w3,
                           const float* __restrict__ b3, float* __restrict__ out) {
    int tid = blockIdx.x * blockDim.x + threadIdx.x;
    int e = tid >> 5;
    if (e >= 2 * EPAIR) return;
    int lane = tid & 31;
    float s = warp_dot128(z + e * 32, w3, lane);
    if (lane == 0) out[e] = s + b3[0];
}

__global__ void k_final_loss(const float* __restrict__ loss, float* __restrict__ out) {
    out[0] = (loss[0] + loss[1]) * (1.0f / (float)N3);
}

// ---------------- host orchestration ----------------
extern "C" void kernel_launch(void* const* d_in, const int* in_sizes, int n_in,
                              void* d_out, int out_size) {
    const float* x      = (const float*)d_in[0];
    const int* srcs[3]  = {(const int*)d_in[1], (const int*)d_in[3], (const int*)d_in[5]};
    const int* dsts[3]  = {(const int*)d_in[2], (const int*)d_in[4], (const int*)d_in[6]};
    const int* perm     = (const int*)d_in[7];
    const int* pos_src  = (const int*)d_in[8];
    const int* pos_dst  = (const int*)d_in[9];
    const int* neg_src  = (const int*)d_in[10];
    const int* neg_dst  = (const int*)d_in[11];
    const float* Ws[3]  = {(const float*)d_in[12], (const float*)d_in[15], (const float*)d_in[18]};
    const float* Wn[3]  = {(const float*)d_in[13], (const float*)d_in[16], (const float*)d_in[19]};
    const float* bb[3]  = {(const float*)d_in[14], (const float*)d_in[17], (const float*)d_in[20]};
    const float* gamma[2] = {(const float*)d_in[21], (const float*)d_in[23]};
    const float* beta [2] = {(const float*)d_in[22], (const float*)d_in[24]};
    const float* discW  = (const float*)d_in[25];
    const float* pW1 = (const float*)d_in[26]; const float* pb1 = (const float*)d_in[27];
    const float* pW2 = (const float*)d_in[28]; const float* pb2 = (const float*)d_in[29];
    const float* pW3 = (const float*)d_in[30]; const float* pb3 = (const float*)d_in[31];
    float* out = (float*)d_out;

    int E[3] = {in_sizes[1], in_sizes[3], in_sizes[5]};
    int ND[3] = {N1, N2, N3};
    int segbase[3] = {0, N1, N1 + N2};

    float *p_bufA, *p_bufB, *p_agg, *p_stats, *p_csum, *p_csq, *p_ws, *p_loss, *p_z, *p_z2;
    int *p_cnt, *p_off, *p_cur, *p_csr, *p_csr2;
    __nv_bfloat16 *p_wth, *p_wtl;
    cudaGetSymbolAddress((void**)&p_bufA,  g_bufA);
    cudaGetSymbolAddress((void**)&p_bufB,  g_bufB);
    cudaGetSymbolAddress((void**)&p_agg,   g_agg);
    cudaGetSymbolAddress((void**)&p_cnt,   g_cnt);
    cudaGetSymbolAddress((void**)&p_off,   g_off);
    cudaGetSymbolAddress((void**)&p_cur,   g_cur);
    cudaGetSymbolAddress((void**)&p_csr,   g_csr);
    cudaGetSymbolAddress((void**)&p_csr2,  g_csr2);
    cudaGetSymbolAddress((void**)&p_stats, g_stats);
    cudaGetSymbolAddress((void**)&p_csum,  g_csum);
    cudaGetSymbolAddress((void**)&p_csq,   g_csq_dummy);
    cudaGetSymbolAddress((void**)&p_ws,    g_ws);
    cudaGetSymbolAddress((void**)&p_loss,  g_loss);
    cudaGetSymbolAddress((void**)&p_z,     g_z);
    cudaGetSymbolAddress((void**)&p_z2,    g_z2);
    cudaGetSymbolAddress((void**)&p_wth,   g_wth);
    cudaGetSymbolAddress((void**)&p_wtl,   g_wtl);

    const size_t PRED_SMEM = 131072;
    cudaFuncSetAttribute(gemm_v4<true >, cudaFuncAttributeMaxDynamicSharedMemorySize, PRED_SMEM);
    cudaFuncSetAttribute(gemm_v4<false>, cudaFuncAttributeMaxDynamicSharedMemorySize, PRED_SMEM);
    cudaFuncSetAttribute(gemm_mma<true >, cudaFuncAttributeMaxDynamicSharedMemorySize, MMA_SMEM);
    cudaFuncSetAttribute(gemm_mma<false>, cudaFuncAttributeMaxDynamicSharedMemorySize, MMA_SMEM);

    int Etot = E[0] + E[1] + E[2];

    // weight prep (split + transpose), all 6 layer matrices
    {
        dim3 pgrid(1, 6);
        k_prep_w<<<pgrid, 256>>>((const float4*)Ws[0], (const float4*)Wn[0],
                                 (const float4*)Ws[1], (const float4*)Wn[1],
                                 (const float4*)Ws[2], (const float4*)Wn[2]);
    }

    // batched CSR build (csr2 = perm[src] for layer-0 segment)
    cudaMemsetAsync(p_cnt, 0, NTOT * sizeof(int), 0);
    cudaMemsetAsync(p_cur, 0, NTOT * sizeof(int), 0);
    k_count_all<<<(Etot + 255) / 256, 256>>>(dsts[0], E[0], dsts[1], E[1], dsts[2], E[2], p_cnt);
    k_scan<<<1, 1024>>>(p_cnt, NTOT, p_off);
    k_fill_all<<<(Etot + 255) / 256, 256>>>(srcs[0], dsts[0], E[0],
                                            srcs[1], dsts[1], E[1],
                                            srcs[2], dsts[2], E[2],
                                            perm, p_off, p_cur, p_csr, p_csr2);

    float* bufA[2] = {p_bufA, p_bufA + (size_t)N1 * D};
    float* bufB[2] = {p_bufB, p_bufB + (size_t)N2 * D};
    float* agg [2] = {p_agg,  p_agg  + (size_t)N1 * D};

    const float* hinP = x;
    const float* hinN = x;   // layer-0 negative: x with perm indirection

    for (int l = 0; l < 3; l++) {
        int nd = ND[l];
        float* outb[2];
        if (l == 1) { outb[0] = bufB[0]; outb[1] = bufB[1]; }
        else        { outb[0] = bufA[0]; outb[1] = bufA[1]; }

        const int* csrN = (l == 0) ? p_csr2 : p_csr;
        k_gather3<<<(nd * 32 + 255) / 256, 256>>>(
            (const float4*)hinP, (const float4*)hinN, p_csr, csrN,
            p_off + segbase[l], (float4*)agg[0], (float4*)agg[1], nd);

        const __nv_bfloat16* W1h = p_wth + (size_t)(2 * l) * D * D;
        const __nv_bfloat16* W1l = p_wtl + (size_t)(2 * l) * D * D;
        const __nv_bfloat16* W2h = p_wth + (size_t)(2 * l + 1) * D * D;
        const __nv_bfloat16* W2l = p_wtl + (size_t)(2 * l + 1) * D * D;

        dim3 grid((nd + 127) / 128, 2);
        if (l == 0) {
            gemm_mma<true><<<grid, 256, MMA_SMEM>>>(
                (const float4*)hinP, (const float4*)hinN,
                (const float4*)agg[0], (const float4*)agg[1],
                W1h, W1l, W2h, W2l, bb[l],
                (float4*)outb[0], (float4*)outb[1], perm, nd);
        } else {
            gemm_mma<false><<<grid, 256, MMA_SMEM>>>(
                (const float4*)hinP, (const float4*)hinN,
                (const float4*)agg[0], (const float4*)agg[1],
                W1h, W1l, W2h, W2l, bb[l],
                (float4*)outb[0], (float4*)outb[1], nullptr, nd);
        }

        if (l < 2) {
            cudaMemsetAsync(p_stats, 0, 2 * 2 * D * sizeof(float), 0);
            dim3 sgrid((nd + 255) / 256, 2);
            k_colstats2<<<sgrid, 128>>>(outb[0], outb[1], nd, p_stats);
            k_bnrelu2<<<(2 * nd * D + 255) / 256, 256>>>(outb[0], outb[1], p_stats,
                                                         gamma[l], beta[l], nd);
        }
        hinP = outb[0];
        hinN = outb[1];
    }

    float* positive = bufA[0];
    float* negative = bufA[1];

    cudaMemsetAsync(p_csum, 0, D * sizeof(float), 0);
    cudaMemsetAsync(p_loss, 0, 2 * sizeof(float), 0);
    k_colstats<<<(N3 + 255) / 256, 128>>>(positive, N3, p_csum, p_csq);
    k_summary_ws<<<1, 128>>>(p_csum, discW, p_ws);
    k_loss<<<(2 * N3 * 32 + 255) / 256, 256>>>((const float4*)positive,
                                               (const float4*)negative,
                                               (const float4*)p_ws, p_loss);

    // link predictor: 20000 rows, pair-product fused into GEMM1 (f32x2 path)
    int Mp = 2 * EPAIR;
    int pgblocks = (Mp + 127) / 128;
    gemm_v4<true><<<pgblocks, 512, PRED_SMEM>>>(
        (const float4*)positive, (const float4*)pW1, pb1, (float4*)p_z2,
        pos_src, pos_dst, neg_src, neg_dst, Mp, 1);
    gemm_v4<false><<<pgblocks, 512, PRED_SMEM>>>(
        (const float4*)p_z2, (const float4*)pW2, pb2, (float4*)p_z,
        nullptr, nullptr, nullptr, nullptr, Mp, 1);
    k_pred_out<<<(Mp * 32 + 255) / 256, 256>>>((const float4*)p_z,
                                               (const float4*)pW3, pb3, out);

    k_final_loss<<<1, 1>>>(p_loss, out + 2 * EPAIR);
}

// round 12
// speedup vs baseline: 2.0488x; 1.0733x over previous
#include <cuda_runtime.h>
#include <cuda_bf16.h>
#include <math.h>

#define N0 100000
#define N1 50000
#define N2 25000
#define N3 12500
#define D  128
#define EPAIR 10000
#define NTOT 87500
#define ETOT 1125000
#define BN_EPS 1e-5f

typedef unsigned int u32;
typedef unsigned short u16;
typedef unsigned long long u64;

// ---------------- scratch ----------------
__device__ float g_bufA[2][N1 * D];
__device__ float g_bufB[2][N2 * D];
__device__ float g_agg [2][N1 * D];
__device__ int   g_cntcur[2 * NTOT];     // [cnt | cur]
__device__ int   g_off [NTOT + 1];
__device__ int   g_csr [ETOT];
__device__ int   g_csr2[750000];         // layer-0 only (perm[src])
__device__ float g_stats[2][2][D];
__device__ float g_csum[D];
__device__ float g_csq_dummy[D];
__device__ float g_ws[D];
__device__ float g_loss[2];
__device__ float g_z [2 * EPAIR * D];
__device__ float g_z2[2 * EPAIR * D];
// pre-split/transposed weights: [matrix][n*128+k], hi and lo bf16 planes
__device__ __nv_bfloat16 g_wth[6][D * D];
__device__ __nv_bfloat16 g_wtl[6][D * D];

// ---------------- f32x2 helpers (predictor GEMM) ----------------
__device__ __forceinline__ u64 pk2(float x, float y) {
    u64 r; asm("mov.b64 %0, {%1, %2};" : "=l"(r) : "f"(x), "f"(y)); return r;
}
__device__ __forceinline__ void upk2(u64 v, float& x, float& y) {
    asm("mov.b64 {%0, %1}, %2;" : "=f"(x), "=f"(y) : "l"(v));
}
__device__ __forceinline__ u64 fma2(u64 a, u64 b, u64 c) {
    u64 d; asm("fma.rn.f32x2 %0, %1, %2, %3;" : "=l"(d) : "l"(a), "l"(b), "l"(c)); return d;
}

// ---------------- bf16 split helpers ----------------
__device__ __forceinline__ void split_bf16(float x, u16& hi, u16& lo) {
    __nv_bfloat16 h = __float2bfloat16(x);
    float hf = __bfloat162float(h);
    __nv_bfloat16 l = __float2bfloat16(x - hf);
    hi = __bfloat16_as_ushort(h);
    lo = __bfloat16_as_ushort(l);
}
__device__ __forceinline__ void mma_bf16(float* d, const u32* a, const u32* b) {
    asm volatile(
        "mma.sync.aligned.m16n8k16.row.col.f32.bf16.bf16.f32 "
        "{%0,%1,%2,%3}, {%4,%5,%6,%7}, {%8,%9}, {%0,%1,%2,%3};"
        : "+f"(d[0]), "+f"(d[1]), "+f"(d[2]), "+f"(d[3])
        : "r"(a[0]), "r"(a[1]), "r"(a[2]), "r"(a[3]), "r"(b[0]), "r"(b[1]));
}

// ---------------- CSR build ----------------
__global__ void k_count_all(const int* __restrict__ d0, int E0,
                            const int* __restrict__ d1, int E1,
                            const int* __restrict__ d2, int E2,
                            int* __restrict__ cnt) {
    int e = blockIdx.x * blockDim.x + threadIdx.x;
    if (e < E0) atomicAdd(&cnt[d0[e]], 1);
    else if (e < E0 + E1) atomicAdd(&cnt[N1 + d1[e - E0]], 1);
    else if (e < E0 + E1 + E2) atomicAdd(&cnt[N1 + N2 + d2[e - E0 - E1]], 1);
}

__global__ void k_scan(const int* __restrict__ cnt, int n, int* __restrict__ off) {
    __shared__ int wsum[32];
    int t = threadIdx.x, lane = t & 31, wid = t >> 5;
    int carry = 0;
    for (int base = 0; base < n; base += 8192) {
        int v[8]; int s = 0;
#pragma unroll
        for (int u = 0; u < 8; u++) {
            int i = base + t * 8 + u;
            v[u] = (i < n) ? cnt[i] : 0;
            s += v[u];
        }
        int ps = s;
#pragma unroll
        for (int o = 1; o < 32; o <<= 1) {
            int x = __shfl_up_sync(0xffffffffu, ps, o);
            if (lane >= o) ps += x;
        }
        if (lane == 31) wsum[wid] = ps;
        __syncthreads();
        if (t < 32) {
            int x = wsum[t];
#pragma unroll
            for (int o = 1; o < 32; o <<= 1) {
                int y = __shfl_up_sync(0xffffffffu, x, o);
                if (t >= o) x += y;
            }
            wsum[t] = x;
        }
        __syncthreads();
        int warpbase = wid ? wsum[wid - 1] : 0;
        int run = carry + warpbase + (ps - s);
#pragma unroll
        for (int u = 0; u < 8; u++) {
            int i = base + t * 8 + u;
            if (i < n) off[i] = run;
            run += v[u];
        }
        carry += wsum[31];
        __syncthreads();
    }
    if (t == 0) off[n] = carry;
}

// csr = src for all; csr2 (layer-0 positions only) = perm[src]
__global__ void k_fill_all(const int* __restrict__ s0, const int* __restrict__ d0, int E0,
                           const int* __restrict__ s1, const int* __restrict__ d1, int E1,
                           const int* __restrict__ s2, const int* __restrict__ d2, int E2,
                           const int* __restrict__ perm,
                           const int* __restrict__ off, int* __restrict__ cur,
                           int* __restrict__ csr, int* __restrict__ csr2) {
    int e = blockIdx.x * blockDim.x + threadIdx.x;
    if (e < E0) {
        int src = s0[e];
        int p = off[d0[e]] + atomicAdd(&cur[d0[e]], 1);
        csr[p] = src;
        csr2[p] = __ldg(&perm[src]);
    } else if (e < E0 + E1) {
        int i = e - E0;
        int node = N1 + d1[i];
        int p = off[node] + atomicAdd(&cur[node], 1);
        csr[p] = s1[i];
    } else if (e < E0 + E1 + E2) {
        int i = e - E0 - E1;
        int node = N1 + N2 + d2[i];
        int p = off[node] + atomicAdd(&cur[node], 1);
        csr[p] = s2[i];
    }
}

// ---------------- gather: neighbor mean for BOTH streams, 4-edge unroll ----------------
__global__ void k_gather3(const float4* __restrict__ hp, const float4* __restrict__ hn,
                          const int* __restrict__ csrP, const int* __restrict__ csrN,
                          const int* __restrict__ off,
                          float4* __restrict__ ap, float4* __restrict__ an, int M) {
    int warp = (blockIdx.x * blockDim.x + threadIdx.x) >> 5;
    if (warp >= M) return;
    int lane = threadIdx.x & 31;
    int s0 = off[warp], s1 = off[warp + 1];
    float4 accp = make_float4(0.f, 0.f, 0.f, 0.f);
    float4 accn = make_float4(0.f, 0.f, 0.f, 0.f);
    int j = s0;
    for (; j + 4 <= s1; j += 4) {
        int a0 = __ldg(&csrP[j]),     a1 = __ldg(&csrP[j + 1]);
        int a2 = __ldg(&csrP[j + 2]), a3 = __ldg(&csrP[j + 3]);
        int b0 = __ldg(&csrN[j]),     b1 = __ldg(&csrN[j + 1]);
        int b2 = __ldg(&csrN[j + 2]), b3 = __ldg(&csrN[j + 3]);
        float4 p0 = hp[a0 * 32 + lane], p1 = hp[a1 * 32 + lane];
        float4 p2 = hp[a2 * 32 + lane], p3 = hp[a3 * 32 + lane];
        float4 n0 = hn[b0 * 32 + lane], n1 = hn[b1 * 32 + lane];
        float4 n2 = hn[b2 * 32 + lane], n3 = hn[b3 * 32 + lane];
        accp.x += (p0.x + p1.x) + (p2.x + p3.x);
        accp.y += (p0.y + p1.y) + (p2.y + p3.y);
        accp.z += (p0.z + p1.z) + (p2.z + p3.z);
        accp.w += (p0.w + p1.w) + (p2.w + p3.w);
        accn.x += (n0.x + n1.x) + (n2.x + n3.x);
        accn.y += (n0.y + n1.y) + (n2.y + n3.y);
        accn.z += (n0.z + n1.z) + (n2.z + n3.z);
        accn.w += (n0.w + n1.w) + (n2.w + n3.w);
    }
    for (; j < s1; j++) {
        int a0 = __ldg(&csrP[j]);
        int b0 = __ldg(&csrN[j]);
        float4 p0 = hp[a0 * 32 + lane];
        float4 n0 = hn[b0 * 32 + lane];
        accp.x += p0.x; accp.y += p0.y; accp.z += p0.z; accp.w += p0.w;
        accn.x += n0.x; accn.y += n0.y; accn.z += n0.z; accn.w += n0.w;
    }
    int deg = s1 - s0;
    float inv = 1.0f / (float)(deg > 0 ? deg : 1);
    accp.x *= inv; accp.y *= inv; accp.z *= inv; accp.w *= inv;
    accn.x *= inv; accn.y *= inv; accn.z *= inv; accn.w *= inv;
    ap[warp * 32 + lane] = accp;
    an[warp * 32 + lane] = accn;
}

// ---------------- weight prep: split fp32 W[k][n] into bf16 Wt[n][k] hi/lo ----------------
__global__ void k_prep_w(const float4* __restrict__ W0, const float4* __restrict__ W1,
                         const float4* __restrict__ W2, const float4* __restrict__ W3,
                         const float4* __restrict__ W4, const float4* __restrict__ W5) {
    int m = blockIdx.y;
    const float4* W = m == 0 ? W0 : m == 1 ? W1 : m == 2 ? W2 : m == 3 ? W3 : m == 4 ? W4 : W5;
    __nv_bfloat16* Th = g_wth[m];
    __nv_bfloat16* Tl = g_wtl[m];
    int t = threadIdx.x;
#pragma unroll
    for (int i = 0; i < 16; i++) {
        int idx = t + i * 256;          // float4 index over [128][32]
        int k = idx >> 5, nq = idx & 31;
        float4 v = W[idx];
        float xs[4] = {v.x, v.y, v.z, v.w};
#pragma unroll
        for (int j = 0; j < 4; j++) {
            int n = nq * 4 + j;
            u16 hi, lo;
            split_bf16(xs[j], hi, lo);
            Th[n * D + k] = __ushort_as_bfloat16(hi);
            Tl[n * D + k] = __ushort_as_bfloat16(lo);
        }
    }
}

// ---------------- mma.sync bf16-split layer GEMM ----------------
// C = A1@W1 + A2@W2 + bias. 256 threads, 64x128 tile, 2 CTAs/SM.
// Warp grid 2(m) x 4(n); warp tile 32x32. Smem pitch 272B (conflict-free).
#define GP_BYTES 272
#define APLANE (64 * GP_BYTES)
#define BPLANE (128 * GP_BYTES)
#define MMA_SMEM (2 * APLANE + 2 * BPLANE)

template <bool PIDX>
__global__ void __launch_bounds__(256, 2)
gemm_mma(const float4* __restrict__ A1p, const float4* __restrict__ A1n,
         const float4* __restrict__ A2p, const float4* __restrict__ A2n,
         const __nv_bfloat16* __restrict__ W1h, const __nv_bfloat16* __restrict__ W1l,
         const __nv_bfloat16* __restrict__ W2h, const __nv_bfloat16* __restrict__ W2l,
         const float* __restrict__ bias,
         float4* __restrict__ Cp, float4* __restrict__ Cn,
         const int* __restrict__ pidxN, int M) {
    extern __shared__ char smem[];
    char* sAh = smem;
    char* sAl = smem + APLANE;
    char* sBh = smem + 2 * APLANE;
    char* sBl = smem + 2 * APLANE + BPLANE;

    int t = threadIdx.x, lane = t & 31, wid = t >> 5;
    int strm = blockIdx.y;
    int rowBase = blockIdx.x * 64;

    const float4* A1 = strm ? A1n : A1p;
    const float4* A2 = strm ? A2n : A2p;
    float4* C = strm ? Cn : Cp;

    float acc[2][4][4];
#pragma unroll
    for (int i = 0; i < 2; i++)
#pragma unroll
        for (int j = 0; j < 4; j++)
#pragma unroll
            for (int r = 0; r < 4; r++) acc[i][j][r] = 0.f;

    int M0 = (wid >> 2) * 32;
    int Nb = (wid & 3) * 32;
    int g = lane >> 2, q = lane & 3;

#pragma unroll
    for (int ph = 0; ph < 2; ph++) {
        if (ph) __syncthreads();
        const float4* A = ph ? A2 : A1;
        const uint4* Wh4 = (const uint4*)(ph ? W2h : W1h);
        const uint4* Wl4 = (const uint4*)(ph ? W2l : W1l);

        // W planes: dense [n][k] bf16 rows of 256B -> padded smem rows
#pragma unroll
        for (int i = 0; i < 8; i++) {
            int idx = t + i * 256;          // uint4 id over [128][16]
            int row = idx >> 4, c = idx & 15;
            *(uint4*)(sBh + row * GP_BYTES + c * 16) = Wh4[idx];
            *(uint4*)(sBl + row * GP_BYTES + c * 16) = Wl4[idx];
        }
        // A tile (64 rows): fp32 -> split bf16 hi/lo
#pragma unroll
        for (int i = 0; i < 8; i++) {
            int idx = t + i * 256;          // float4 id over [64][32]
            int row = idx >> 5, kq = idx & 31;
            float4 v = make_float4(0.f, 0.f, 0.f, 0.f);
            int grow = rowBase + row;
            if (grow < M) {
                int rr = grow;
                if (PIDX) { if (strm && ph == 0) rr = __ldg(&pidxN[grow]); }
                v = A[rr * 32 + kq];
            }
            u16 h0, l0, h1, l1, h2, l2, h3, l3;
            split_bf16(v.x, h0, l0); split_bf16(v.y, h1, l1);
            split_bf16(v.z, h2, l2); split_bf16(v.w, h3, l3);
            uint2 ph2, pl2;
            ph2.x = ((u32)h1 << 16) | h0; ph2.y = ((u32)h3 << 16) | h2;
            pl2.x = ((u32)l1 << 16) | l0; pl2.y = ((u32)l3 << 16) | l2;
            *(uint2*)(sAh + row * GP_BYTES + kq * 8) = ph2;
            *(uint2*)(sAl + row * GP_BYTES + kq * 8) = pl2;
        }
        __syncthreads();

#pragma unroll
        for (int kc = 0; kc < 8; kc++) {
            int k0 = kc * 16;
            u32 bh[4][2], bl[4][2];
#pragma unroll
            for (int fn = 0; fn < 4; fn++) {
                int n = Nb + fn * 8 + g;
                u64 pb = (u64)(n * GP_BYTES + (k0 + q * 2) * 2);
                bh[fn][0] = *(const u32*)(sBh + pb);
                bh[fn][1] = *(const u32*)(sBh + pb + 16);
                bl[fn][0] = *(const u32*)(sBl + pb);
                bl[fn][1] = *(const u32*)(sBl + pb + 16);
            }
#pragma unroll
            for (int fm = 0; fm < 2; fm++) {
                int r = M0 + fm * 16 + g;
                u64 ao = (u64)(r * GP_BYTES + (k0 + q * 2) * 2);
                u32 ah[4], al[4];
                ah[0] = *(const u32*)(sAh + ao);
                ah[1] = *(const u32*)(sAh + ao + 8 * GP_BYTES);
                ah[2] = *(const u32*)(sAh + ao + 16);
                ah[3] = *(const u32*)(sAh + ao + 8 * GP_BYTES + 16);
                al[0] = *(const u32*)(sAl + ao);
                al[1] = *(const u32*)(sAl + ao + 8 * GP_BYTES);
                al[2] = *(const u32*)(sAl + ao + 16);
                al[3] = *(const u32*)(sAl + ao + 8 * GP_BYTES + 16);
#pragma unroll
                for (int fn = 0; fn < 4; fn++) {
                    mma_bf16(acc[fm][fn], ah, bh[fn]);
                    mma_bf16(acc[fm][fn], ah, bl[fn]);
                    mma_bf16(acc[fm][fn], al, bh[fn]);
                }
            }
        }
    }

    // epilogue: D fragment layout -> gmem + bias
    float* Cf = (float*)C;
#pragma unroll
    for (int fn = 0; fn < 4; fn++) {
        int col = Nb + fn * 8 + q * 2;
        float2 bv = *(const float2*)(bias + col);
#pragma unroll
        for (int fm = 0; fm < 2; fm++) {
            int row0 = rowBase + M0 + fm * 16 + g;
            int row1 = row0 + 8;
            if (row0 < M) {
                float2 o = make_float2(acc[fm][fn][0] + bv.x, acc[fm][fn][1] + bv.y);
                *(float2*)(Cf + row0 * D + col) = o;
            }
            if (row1 < M) {
                float2 o = make_float2(acc[fm][fn][2] + bv.x, acc[fm][fn][3] + bv.y);
                *(float2*)(Cf + row1 * D + col) = o;
            }
        }
    }
}

// ---------------- f32x2 GEMM (predictor only, R9-proven) ----------------
template <bool PAIRG>
__global__ void __launch_bounds__(512, 1)
gemm_v4(const float4* __restrict__ A, const float4* __restrict__ W,
        const float* __restrict__ bias, float4* __restrict__ C,
        const int* __restrict__ ga, const int* __restrict__ gb,
        const int* __restrict__ ga2, const int* __restrict__ gb2,
        int M, int relu) {
    extern __shared__ float4 smem4[];
    float4* sA = smem4;
    float4* sB = smem4 + 4096;

    int t = threadIdx.x;
    int rowBase = blockIdx.x * 128;
    int c8 = t & 15;
    int r0 = (t >> 4) * 4;
    const ulonglong2* sB2 = (const ulonglong2*)sB;

    u64 acc[4][4];
#pragma unroll
    for (int i = 0; i < 4; i++)
#pragma unroll
        for (int j = 0; j < 4; j++) acc[i][j] = 0ULL;

#pragma unroll
    for (int i = 0; i < 8; i++) sB[t + i * 512] = W[t + i * 512];
#pragma unroll
    for (int i = 0; i < 8; i++) {
        int p = t + i * 512;
        int r = p >> 5, kq = p & 31;
        int row = rowBase + r;
        float4 v = make_float4(0.f, 0.f, 0.f, 0.f);
        if (row < M) {
            if (PAIRG) {
                const int* A_ = (row < EPAIR) ? ga : ga2;
                const int* B_ = (row < EPAIR) ? gb : gb2;
                int rr = (row < EPAIR) ? row : row - EPAIR;
                float4 u = A[A_[rr] * 32 + kq];
                float4 w = A[B_[rr] * 32 + kq];
                v = make_float4(u.x * w.x, u.y * w.y, u.z * w.z, u.w * w.w);
            } else {
                v = A[row * 32 + kq];
            }
        }
        sA[r * 32 + kq] = v;
    }
    __syncthreads();

#pragma unroll 4
    for (int k4 = 0; k4 < 32; k4++) {
        float4 a0 = sA[(r0 + 0) * 32 + k4];
        float4 a1 = sA[(r0 + 1) * 32 + k4];
        float4 a2 = sA[(r0 + 2) * 32 + k4];
        float4 a3 = sA[(r0 + 3) * 32 + k4];
#pragma unroll
        for (int kk = 0; kk < 4; kk++) {
            int k = k4 * 4 + kk;
            ulonglong2 p0 = sB2[k * 32 + c8];
            ulonglong2 p1 = sB2[k * 32 + 16 + c8];
            float f0 = kk == 0 ? a0.x : kk == 1 ? a0.y : kk == 2 ? a0.z : a0.w;
            float f1 = kk == 0 ? a1.x : kk == 1 ? a1.y : kk == 2 ? a1.z : a1.w;
            float f2 = kk == 0 ? a2.x : kk == 1 ? a2.y : kk == 2 ? a2.z : a2.w;
            float f3 = kk == 0 ? a3.x : kk == 1 ? a3.y : kk == 2 ? a3.z : a3.w;
            u64 aa0 = pk2(f0, f0);
            u64 aa1 = pk2(f1, f1);
            u64 aa2 = pk2(f2, f2);
            u64 aa3 = pk2(f3, f3);
            acc[0][0] = fma2(aa0, p0.x, acc[0][0]);
            acc[0][1] = fma2(aa0, p0.y, acc[0][1]);
            acc[0][2] = fma2(aa0, p1.x, acc[0][2]);
            acc[0][3] = fma2(aa0, p1.y, acc[0][3]);
            acc[1][0] = fma2(aa1, p0.x, acc[1][0]);
            acc[1][1] = fma2(aa1, p0.y, acc[1][1]);
            acc[1][2] = fma2(aa1, p1.x, acc[1][2]);
            acc[1][3] = fma2(aa1, p1.y, acc[1][3]);
            acc[2][0] = fma2(aa2, p0.x, acc[2][0]);
            acc[2][1] = fma2(aa2, p0.y, acc[2][1]);
            acc[2][2] = fma2(aa2, p1.x, acc[2][2]);
            acc[2][3] = fma2(aa2, p1.y, acc[2][3]);
            acc[3][0] = fma2(aa3, p0.x, acc[3][0]);
            acc[3][1] = fma2(aa3, p0.y, acc[3][1]);
            acc[3][2] = fma2(aa3, p1.x, acc[3][2]);
            acc[3][3] = fma2(aa3, p1.y, acc[3][3]);
        }
    }

    float4 bv0 = ((const float4*)bias)[c8];
    float4 bv1 = ((const float4*)bias)[16 + c8];

#pragma unroll
    for (int i = 0; i < 4; i++) {
        int row = rowBase + r0 + i;
        if (row >= M) continue;
        float4 o0, o1;
        upk2(acc[i][0], o0.x, o0.y);
        upk2(acc[i][1], o0.z, o0.w);
        upk2(acc[i][2], o1.x, o1.y);
        upk2(acc[i][3], o1.z, o1.w);
        o0.x += bv0.x; o0.y += bv0.y; o0.z += bv0.z; o0.w += bv0.w;
        o1.x += bv1.x; o1.y += bv1.y; o1.z += bv1.z; o1.w += bv1.w;
        if (relu) {
            o0.x = fmaxf(o0.x, 0.f); o0.y = fmaxf(o0.y, 0.f);
            o0.z = fmaxf(o0.z, 0.f); o0.w = fmaxf(o0.w, 0.f);
            o1.x = fmaxf(o1.x, 0.f); o1.y = fmaxf(o1.y, 0.f);
            o1.z = fmaxf(o1.z, 0.f); o1.w = fmaxf(o1.w, 0.f);
        }
        C[row * 32 + c8]      = o0;
        C[row * 32 + 16 + c8] = o1;
    }
}

// per-column stats, both streams via grid.y
__global__ void k_colstats2(const float* __restrict__ Hp, const float* __restrict__ Hn,
                            int M, float* __restrict__ stats) {
    const float* H = blockIdx.y ? Hn : Hp;
    float* sum = stats + blockIdx.y * 2 * D;
    float* sq  = sum + D;
    int c = threadIdx.x;
    int r0 = blockIdx.x * 256;
    int rend = r0 + 256; if (rend > M) rend = M;
    float s = 0.f, s2 = 0.f;
    for (int r = r0; r < rend; r++) {
        float v = H[r * D + c];
        s += v; s2 += v * v;
    }
    atomicAdd(&sum[c], s);
    atomicAdd(&sq[c], s2);
}

__global__ void k_bnrelu2(float* __restrict__ Hp, float* __restrict__ Hn,
                          const float* __restrict__ stats,
                          const float* __restrict__ gamma, const float* __restrict__ beta,
                          int M) {
    int idx = blockIdx.x * blockDim.x + threadIdx.x;
    int tot = M * D;
    if (idx >= 2 * tot) return;
    int strm = idx >= tot;
    int i = idx - strm * tot;
    float* H = strm ? Hn : Hp;
    const float* st = stats + strm * 2 * D;
    int c = i & 127;
    float invM = 1.0f / (float)M;
    float m = st[c] * invM;
    float v = st[D + c] * invM - m * m;
    float y = gamma[c] * (H[i] - m) * rsqrtf(v + BN_EPS) + beta[c];
    H[i] = fmaxf(y, 0.f);
}

__global__ void k_colstats(const float* __restrict__ H, int M,
                           float* __restrict__ sum, float* __restrict__ sq) {
    int c = threadIdx.x;
    int r0 = blockIdx.x * 256;
    int rend = r0 + 256; if (rend > M) rend = M;
    float s = 0.f, s2 = 0.f;
    for (int r = r0; r < rend; r++) {
        float v = H[r * D + c];
        s += v; s2 += v * v;
    }
    atomicAdd(&sum[c], s);
    atomicAdd(&sq[c], s2);
}

__global__ void k_summary_ws(const float* __restrict__ colsum,
                             const float* __restrict__ discW, float* __restrict__ ws) {
    __shared__ float sm[D];
    int t = threadIdx.x;
    float mn = colsum[t] / (float)N3;
    sm[t] = 1.0f / (1.0f + expf(-mn));
    __syncthreads();
    float a = 0.f;
#pragma unroll 8
    for (int j = 0; j < D; j++) a += discW[t * D + j] * sm[j];
    ws[t] = a;
}

__device__ __forceinline__ float warp_dot128(const float4* __restrict__ a,
                                             const float4* __restrict__ b, int lane) {
    float4 x = a[lane], y = b[lane];
    float s = x.x * y.x + x.y * y.y + x.z * y.z + x.w * y.w;
#pragma unroll
    for (int o = 16; o; o >>= 1) s += __shfl_down_sync(0xffffffffu, s, o);
    return s;
}

__global__ void k_loss(const float4* __restrict__ pos, const float4* __restrict__ neg,
                       const float4* __restrict__ ws, float* __restrict__ loss) {
    int tid = blockIdx.x * blockDim.x + threadIdx.x;
    int e = tid >> 5;
    if (e >= 2 * N3) return;
    int lane = tid & 31;
    int strm = (e >= N3);
    int r = e - strm * N3;
    const float4* row = (strm ? neg : pos) + r * 32;
    float s = warp_dot128(row, ws, lane);
    if (lane == 0) {
        float xx = strm ? s : -s;
        float sp = fmaxf(xx, 0.f) + log1pf(expf(-fabsf(xx)));
        atomicAdd(&loss[strm], sp);
    }
}

__global__ void k_pred_out(const float4* __restrict__ z, const float4* __restrict__ w3,
                           const float* __restrict__ b3, float* __restrict__ out) {
    int tid = blockIdx.x * blockDim.x + threadIdx.x;
    int e = tid >> 5;
    if (e >= 2 * EPAIR) return;
    int lane = tid & 31;
    float s = warp_dot128(z + e * 32, w3, lane);
    if (lane == 0) out[e] = s + b3[0];
}

__global__ void k_final_loss(const float* __restrict__ loss, float* __restrict__ out) {
    out[0] = (loss[0] + loss[1]) * (1.0f / (float)N3);
}

// ---------------- host orchestration ----------------
extern "C" void kernel_launch(void* const* d_in, const int* in_sizes, int n_in,
                              void* d_out, int out_size) {
    const float* x      = (const float*)d_in[0];
    const int* srcs[3]  = {(const int*)d_in[1], (const int*)d_in[3], (const int*)d_in[5]};
    const int* dsts[3]  = {(const int*)d_in[2], (const int*)d_in[4], (const int*)d_in[6]};
    const int* perm     = (const int*)d_in[7];
    const int* pos_src  = (const int*)d_in[8];
    const int* pos_dst  = (const int*)d_in[9];
    const int* neg_src  = (const int*)d_in[10];
    const int* neg_dst  = (const int*)d_in[11];
    const float* Ws[3]  = {(const float*)d_in[12], (const float*)d_in[15], (const float*)d_in[18]};
    const float* Wn[3]  = {(const float*)d_in[13], (const float*)d_in[16], (const float*)d_in[19]};
    const float* bb[3]  = {(const float*)d_in[14], (const float*)d_in[17], (const float*)d_in[20]};
    const float* gamma[2] = {(const float*)d_in[21], (const float*)d_in[23]};
    const float* beta [2] = {(const float*)d_in[22], (const float*)d_in[24]};
    const float* discW  = (const float*)d_in[25];
    const float* pW1 = (const float*)d_in[26]; const float* pb1 = (const float*)d_in[27];
    const float* pW2 = (const float*)d_in[28]; const float* pb2 = (const float*)d_in[29];
    const float* pW3 = (const float*)d_in[30]; const float* pb3 = (const float*)d_in[31];
    float* out = (float*)d_out;

    int E[3] = {in_sizes[1], in_sizes[3], in_sizes[5]};
    int ND[3] = {N1, N2, N3};
    int segbase[3] = {0, N1, N1 + N2};

    float *p_bufA, *p_bufB, *p_agg, *p_stats, *p_csum, *p_csq, *p_ws, *p_loss, *p_z, *p_z2;
    int *p_cntcur, *p_off, *p_csr, *p_csr2;
    __nv_bfloat16 *p_wth, *p_wtl;
    cudaGetSymbolAddress((void**)&p_bufA,   g_bufA);
    cudaGetSymbolAddress((void**)&p_bufB,   g_bufB);
    cudaGetSymbolAddress((void**)&p_agg,    g_agg);
    cudaGetSymbolAddress((void**)&p_cntcur, g_cntcur);
    cudaGetSymbolAddress((void**)&p_off,    g_off);
    cudaGetSymbolAddress((void**)&p_csr,    g_csr);
    cudaGetSymbolAddress((void**)&p_csr2,   g_csr2);
    cudaGetSymbolAddress((void**)&p_stats,  g_stats);
    cudaGetSymbolAddress((void**)&p_csum,   g_csum);
    cudaGetSymbolAddress((void**)&p_csq,    g_csq_dummy);
    cudaGetSymbolAddress((void**)&p_ws,     g_ws);
    cudaGetSymbolAddress((void**)&p_loss,   g_loss);
    cudaGetSymbolAddress((void**)&p_z,      g_z);
    cudaGetSymbolAddress((void**)&p_z2,     g_z2);
    cudaGetSymbolAddress((void**)&p_wth,    g_wth);
    cudaGetSymbolAddress((void**)&p_wtl,    g_wtl);
    int* p_cnt = p_cntcur;
    int* p_cur = p_cntcur + NTOT;

    const size_t PRED_SMEM = 131072;
    cudaFuncSetAttribute(gemm_v4<true >, cudaFuncAttributeMaxDynamicSharedMemorySize, PRED_SMEM);
    cudaFuncSetAttribute(gemm_v4<false>, cudaFuncAttributeMaxDynamicSharedMemorySize, PRED_SMEM);
    cudaFuncSetAttribute(gemm_mma<true >, cudaFuncAttributeMaxDynamicSharedMemorySize, MMA_SMEM);
    cudaFuncSetAttribute(gemm_mma<false>, cudaFuncAttributeMaxDynamicSharedMemorySize, MMA_SMEM);

    int Etot = E[0] + E[1] + E[2];

    // weight prep (split + transpose), all 6 layer matrices
    {
        dim3 pgrid(1, 6);
        k_prep_w<<<pgrid, 256>>>((const float4*)Ws[0], (const float4*)Wn[0],
                                 (const float4*)Ws[1], (const float4*)Wn[1],
                                 (const float4*)Ws[2], (const float4*)Wn[2]);
    }

    // batched CSR build (csr2 = perm[src] for layer-0 segment only)
    cudaMemsetAsync(p_cntcur, 0, 2 * NTOT * sizeof(int), 0);
    k_count_all<<<(Etot + 255) / 256, 256>>>(dsts[0], E[0], dsts[1], E[1], dsts[2], E[2], p_cnt);
    k_scan<<<1, 1024>>>(p_cnt, NTOT, p_off);
    k_fill_all<<<(Etot + 255) / 256, 256>>>(srcs[0], dsts[0], E[0],
                                            srcs[1], dsts[1], E[1],
                                            srcs[2], dsts[2], E[2],
                                            perm, p_off, p_cur, p_csr, p_csr2);

    float* bufA[2] = {p_bufA, p_bufA + (size_t)N1 * D};
    float* bufB[2] = {p_bufB, p_bufB + (size_t)N2 * D};
    float* agg [2] = {p_agg,  p_agg  + (size_t)N1 * D};

    const float* hinP = x;
    const float* hinN = x;   // layer-0 negative: x with perm indirection

    for (int l = 0; l < 3; l++) {
        int nd = ND[l];
        float* outb[2];
        if (l == 1) { outb[0] = bufB[0]; outb[1] = bufB[1]; }
        else        { outb[0] = bufA[0]; outb[1] = bufA[1]; }

        const int* csrN = (l == 0) ? p_csr2 : p_csr;
        k_gather3<<<(nd * 32 + 255) / 256, 256>>>(
            (const float4*)hinP, (const float4*)hinN, p_csr, csrN,
            p_off + segbase[l], (float4*)agg[0], (float4*)agg[1], nd);

        const __nv_bfloat16* W1h = p_wth + (size_t)(2 * l) * D * D;
        const __nv_bfloat16* W1l = p_wtl + (size_t)(2 * l) * D * D;
        const __nv_bfloat16* W2h = p_wth + (size_t)(2 * l + 1) * D * D;
        const __nv_bfloat16* W2l = p_wtl + (size_t)(2 * l + 1) * D * D;

        dim3 grid((nd + 63) / 64, 2);
        if (l == 0) {
            gemm_mma<true><<<grid, 256, MMA_SMEM>>>(
                (const float4*)hinP, (const float4*)hinN,
                (const float4*)agg[0], (const float4*)agg[1],
                W1h, W1l, W2h, W2l, bb[l],
                (float4*)outb[0], (float4*)outb[1], perm, nd);
        } else {
            gemm_mma<false><<<grid, 256, MMA_SMEM>>>(
                (const float4*)hinP, (const float4*)hinN,
                (const float4*)agg[0], (const float4*)agg[1],
                W1h, W1l, W2h, W2l, bb[l],
                (float4*)outb[0], (float4*)outb[1], nullptr, nd);
        }

        if (l < 2) {
            cudaMemsetAsync(p_stats, 0, 2 * 2 * D * sizeof(float), 0);
            dim3 sgrid((nd + 255) / 256, 2);
            k_colstats2<<<sgrid, 128>>>(outb[0], outb[1], nd, p_stats);
            k_bnrelu2<<<(2 * nd * D + 255) / 256, 256>>>(outb[0], outb[1], p_stats,
                                                         gamma[l], beta[l], nd);
        }
        hinP = outb[0];
        hinN = outb[1];
    }

    float* positive = bufA[0];
    float* negative = bufA[1];

    cudaMemsetAsync(p_csum, 0, D * sizeof(float), 0);
    cudaMemsetAsync(p_loss, 0, 2 * sizeof(float), 0);
    k_colstats<<<(N3 + 255) / 256, 128>>>(positive, N3, p_csum, p_csq);
    k_summary_ws<<<1, 128>>>(p_csum, discW, p_ws);
    k_loss<<<(2 * N3 * 32 + 255) / 256, 256>>>((const float4*)positive,
                                               (const float4*)negative,
                                               (const float4*)p_ws, p_loss);

    // link predictor: 20000 rows, pair-product fused into GEMM1 (f32x2 path)
    int Mp = 2 * EPAIR;
    int pgblocks = (Mp + 127) / 128;
    gemm_v4<true><<<pgblocks, 512, PRED_SMEM>>>(
        (const float4*)positive, (const float4*)pW1, pb1, (float4*)p_z2,
        pos_src, pos_dst, neg_src, neg_dst, Mp, 1);
    gemm_v4<false><<<pgblocks, 512, PRED_SMEM>>>(
        (const float4*)p_z2, (const float4*)pW2, pb2, (float4*)p_z,
        nullptr, nullptr, nullptr, nullptr, Mp, 1);
    k_pred_out<<<(Mp * 32 + 255) / 256, 256>>>((const float4*)p_z,
                                               (const float4*)pW3, pb3, out);

    k_final_loss<<<1, 1>>>(p_loss, out + 2 * EPAIR);
}

// round 15
// speedup vs baseline: 2.1859x; 1.0669x over previous
#include <cuda_runtime.h>
#include <cuda_bf16.h>
#include <math.h>

#define N0 100000
#define N1 50000
#define N2 25000
#define N3 12500
#define D  128
#define EPAIR 10000
#define NTOT 87500
#define ETOT 1125000
#define BN_EPS 1e-5f

typedef unsigned int u32;
typedef unsigned short u16;
typedef unsigned long long u64;

// ---------------- scratch ----------------
__device__ float g_bufA[2][N1 * D];
__device__ float g_bufB[2][N2 * D];
__device__ float g_agg [2][N1 * D];
__device__ int   g_cnt [NTOT];
__device__ int   g_off [NTOT + 1];
__device__ int   g_slot[ETOT];
__device__ int   g_csr [ETOT];
__device__ int   g_csr2[750000];         // layer-0 only (perm[src])
__device__ float g_stats[2][2][D];
__device__ float g_bnA[2][D];
__device__ float g_bnB[2][D];
__device__ float g_csum[D];
__device__ float g_csq_dummy[D];
__device__ float g_ws[D];
__device__ float g_loss[2];
__device__ float g_z [2 * EPAIR * D];
__device__ float g_z2[2 * EPAIR * D];
__device__ __nv_bfloat16 g_wth[6][D * D];
__device__ __nv_bfloat16 g_wtl[6][D * D];

// ---------------- f32x2 helpers (predictor GEMM) ----------------
__device__ __forceinline__ u64 pk2(float x, float y) {
    u64 r; asm("mov.b64 %0, {%1, %2};" : "=l"(r) : "f"(x), "f"(y)); return r;
}
__device__ __forceinline__ void upk2(u64 v, float& x, float& y) {
    asm("mov.b64 {%0, %1}, %2;" : "=f"(x), "=f"(y) : "l"(v));
}
__device__ __forceinline__ u64 fma2(u64 a, u64 b, u64 c) {
    u64 d; asm("fma.rn.f32x2 %0, %1, %2, %3;" : "=l"(d) : "l"(a), "l"(b), "l"(c)); return d;
}

// ---------------- bf16 split / mma helpers ----------------
__device__ __forceinline__ void split_bf16(float x, u16& hi, u16& lo) {
    __nv_bfloat16 h = __float2bfloat16(x);
    float hf = __bfloat162float(h);
    __nv_bfloat16 l = __float2bfloat16(x - hf);
    hi = __bfloat16_as_ushort(h);
    lo = __bfloat16_as_ushort(l);
}
__device__ __forceinline__ void mma_bf16(float* d, const u32* a, const u32* b) {
    asm volatile(
        "mma.sync.aligned.m16n8k16.row.col.f32.bf16.bf16.f32 "
        "{%0,%1,%2,%3}, {%4,%5,%6,%7}, {%8,%9}, {%0,%1,%2,%3};"
        : "+f"(d[0]), "+f"(d[1]), "+f"(d[2]), "+f"(d[3])
        : "r"(a[0]), "r"(a[1]), "r"(a[2]), "r"(a[3]), "r"(b[0]), "r"(b[1]));
}

__device__ __forceinline__ float4 bn_relu4(float4 v, float4 a, float4 b) {
    v.x = fmaxf(fmaf(v.x, a.x, b.x), 0.f);
    v.y = fmaxf(fmaf(v.y, a.y, b.y), 0.f);
    v.z = fmaxf(fmaf(v.z, a.z, b.z), 0.f);
    v.w = fmaxf(fmaf(v.w, a.w, b.w), 0.f);
    return v;
}

// ---------------- CSR build ----------------
// count + record slot (fill becomes atomic-free)
__global__ void k_count_all(const int* __restrict__ d0, int E0,
                            const int* __restrict__ d1, int E1,
                            const int* __restrict__ d2, int E2,
                            int* __restrict__ cnt, int* __restrict__ slot) {
    int e = blockIdx.x * blockDim.x + threadIdx.x;
    int node;
    if (e < E0) node = d0[e];
    else if (e < E0 + E1) node = N1 + d1[e - E0];
    else if (e < E0 + E1 + E2) node = N1 + N2 + d2[e - E0 - E1];
    else return;
    slot[e] = atomicAdd(&cnt[node], 1);
}

__global__ void k_scan(const int* __restrict__ cnt, int n, int* __restrict__ off) {
    __shared__ int wsum[32];
    int t = threadIdx.x, lane = t & 31, wid = t >> 5;
    int carry = 0;
    for (int base = 0; base < n; base += 8192) {
        int v[8]; int s = 0;
#pragma unroll
        for (int u = 0; u < 8; u++) {
            int i = base + t * 8 + u;
            v[u] = (i < n) ? cnt[i] : 0;
            s += v[u];
        }
        int ps = s;
#pragma unroll
        for (int o = 1; o < 32; o <<= 1) {
            int x = __shfl_up_sync(0xffffffffu, ps, o);
            if (lane >= o) ps += x;
        }
        if (lane == 31) wsum[wid] = ps;
        __syncthreads();
        if (t < 32) {
            int x = wsum[t];
#pragma unroll
            for (int o = 1; o < 32; o <<= 1) {
                int y = __shfl_up_sync(0xffffffffu, x, o);
                if (t >= o) x += y;
            }
            wsum[t] = x;
        }
        __syncthreads();
        int warpbase = wid ? wsum[wid - 1] : 0;
        int run = carry + warpbase + (ps - s);
#pragma unroll
        for (int u = 0; u < 8; u++) {
            int i = base + t * 8 + u;
            if (i < n) off[i] = run;
            run += v[u];
        }
        carry += wsum[31];
        __syncthreads();
    }
    if (t == 0) off[n] = carry;
}

// atomic-free fill: p = off[node] + slot[e]
__global__ void k_fill_all(const int* __restrict__ s0, const int* __restrict__ d0, int E0,
                           const int* __restrict__ s1, const int* __restrict__ d1, int E1,
                           const int* __restrict__ s2, const int* __restrict__ d2, int E2,
                           const int* __restrict__ perm,
                           const int* __restrict__ off, const int* __restrict__ slot,
                           int* __restrict__ csr, int* __restrict__ csr2) {
    int e = blockIdx.x * blockDim.x + threadIdx.x;
    if (e < E0) {
        int src = s0[e];
        int p = off[d0[e]] + slot[e];
        csr[p] = src;
        csr2[p] = __ldg(&perm[src]);
    } else if (e < E0 + E1) {
        int i = e - E0;
        int p = off[N1 + d1[i]] + slot[e];
        csr[p] = s1[i];
    } else if (e < E0 + E1 + E2) {
        int i = e - E0 - E1;
        int p = off[N1 + N2 + d2[i]] + slot[e];
        csr[p] = s2[i];
    }
}

// ---------------- gather: neighbor mean, both streams, optional lazy BN+relu ----------------
template <bool BN>
__global__ void k_gather4(const float4* __restrict__ hp, const float4* __restrict__ hn,
                          const int* __restrict__ csrP, const int* __restrict__ csrN,
                          const int* __restrict__ off,
                          const float4* __restrict__ bnAp, const float4* __restrict__ bnBp,
                          const float4* __restrict__ bnAn, const float4* __restrict__ bnBn,
                          float4* __restrict__ ap, float4* __restrict__ an, int M) {
    int warp = (blockIdx.x * blockDim.x + threadIdx.x) >> 5;
    if (warp >= M) return;
    int lane = threadIdx.x & 31;
    int s0 = off[warp], s1 = off[warp + 1];

    float4 cAp, cBp, cAn, cBn;
    if (BN) {
        cAp = __ldg(&bnAp[lane]); cBp = __ldg(&bnBp[lane]);
        cAn = __ldg(&bnAn[lane]); cBn = __ldg(&bnBn[lane]);
    }

    float4 accp = make_float4(0.f, 0.f, 0.f, 0.f);
    float4 accn = make_float4(0.f, 0.f, 0.f, 0.f);
    int j = s0;
    for (; j + 4 <= s1; j += 4) {
        int a0 = __ldg(&csrP[j]),     a1 = __ldg(&csrP[j + 1]);
        int a2 = __ldg(&csrP[j + 2]), a3 = __ldg(&csrP[j + 3]);
        int b0 = __ldg(&csrN[j]),     b1 = __ldg(&csrN[j + 1]);
        int b2 = __ldg(&csrN[j + 2]), b3 = __ldg(&csrN[j + 3]);
        float4 p0 = hp[a0 * 32 + lane], p1 = hp[a1 * 32 + lane];
        float4 p2 = hp[a2 * 32 + lane], p3 = hp[a3 * 32 + lane];
        float4 n0 = hn[b0 * 32 + lane], n1 = hn[b1 * 32 + lane];
        float4 n2 = hn[b2 * 32 + lane], n3 = hn[b3 * 32 + lane];
        if (BN) {
            p0 = bn_relu4(p0, cAp, cBp); p1 = bn_relu4(p1, cAp, cBp);
            p2 = bn_relu4(p2, cAp, cBp); p3 = bn_relu4(p3, cAp, cBp);
            n0 = bn_relu4(n0, cAn, cBn); n1 = bn_relu4(n1, cAn, cBn);
            n2 = bn_relu4(n2, cAn, cBn); n3 = bn_relu4(n3, cAn, cBn);
        }
        accp.x += (p0.x + p1.x) + (p2.x + p3.x);
        accp.y += (p0.y + p1.y) + (p2.y + p3.y);
        accp.z += (p0.z + p1.z) + (p2.z + p3.z);
        accp.w += (p0.w + p1.w) + (p2.w + p3.w);
        accn.x += (n0.x + n1.x) + (n2.x + n3.x);
        accn.y += (n0.y + n1.y) + (n2.y + n3.y);
        accn.z += (n0.z + n1.z) + (n2.z + n3.z);
        accn.w += (n0.w + n1.w) + (n2.w + n3.w);
    }
    for (; j < s1; j++) {
        int a0 = __ldg(&csrP[j]);
        int b0 = __ldg(&csrN[j]);
        float4 p0 = hp[a0 * 32 + lane];
        float4 n0 = hn[b0 * 32 + lane];
        if (BN) {
            p0 = bn_relu4(p0, cAp, cBp);
            n0 = bn_relu4(n0, cAn, cBn);
        }
        accp.x += p0.x; accp.y += p0.y; accp.z += p0.z; accp.w += p0.w;
        accn.x += n0.x; accn.y += n0.y; accn.z += n0.z; accn.w += n0.w;
    }
    int deg = s1 - s0;
    float inv = 1.0f / (float)(deg > 0 ? deg : 1);
    accp.x *= inv; accp.y *= inv; accp.z *= inv; accp.w *= inv;
    accn.x *= inv; accn.y *= inv; accn.z *= inv; accn.w *= inv;
    ap[warp * 32 + lane] = accp;
    an[warp * 32 + lane] = accn;
}

// ---------------- weight prep: split fp32 W[k][n] into bf16 Wt[n][k] hi/lo ----------------
__global__ void k_prep_w(const float4* __restrict__ W0, const float4* __restrict__ W1,
                         const float4* __restrict__ W2, const float4* __restrict__ W3,
                         const float4* __restrict__ W4, const float4* __restrict__ W5) {
    int m = blockIdx.y;
    const float4* W = m == 0 ? W0 : m == 1 ? W1 : m == 2 ? W2 : m == 3 ? W3 : m == 4 ? W4 : W5;
    __nv_bfloat16* Th = g_wth[m];
    __nv_bfloat16* Tl = g_wtl[m];
    int t = threadIdx.x;
#pragma unroll
    for (int i = 0; i < 16; i++) {
        int idx = t + i * 256;
        int k = idx >> 5, nq = idx & 31;
        float4 v = W[idx];
        float xs[4] = {v.x, v.y, v.z, v.w};
#pragma unroll
        for (int j = 0; j < 4; j++) {
            int n = nq * 4 + j;
            u16 hi, lo;
            split_bf16(xs[j], hi, lo);
            Th[n * D + k] = __ushort_as_bfloat16(hi);
            Tl[n * D + k] = __ushort_as_bfloat16(lo);
        }
    }
}

// ---------------- mma.sync bf16-split layer GEMM ----------------
// C = A1@W1 + A2@W2 + bias. 256 threads, 64x128 tile, 2 CTAs/SM.
// BN: phase-0 A rows get relu(a*h+b) applied at load (lazy BN from prev layer).
#define GP_BYTES 272
#define APLANE (64 * GP_BYTES)
#define BPLANE (128 * GP_BYTES)
#define MMA_SMEM (2 * APLANE + 2 * BPLANE)

template <bool PIDX, bool BN>
__global__ void __launch_bounds__(256, 2)
gemm_mma(const float4* __restrict__ A1p, const float4* __restrict__ A1n,
         const float4* __restrict__ A2p, const float4* __restrict__ A2n,
         const __nv_bfloat16* __restrict__ W1h, const __nv_bfloat16* __restrict__ W1l,
         const __nv_bfloat16* __restrict__ W2h, const __nv_bfloat16* __restrict__ W2l,
         const float* __restrict__ bias,
         float4* __restrict__ Cp, float4* __restrict__ Cn,
         const float4* __restrict__ bnAp, const float4* __restrict__ bnBp,
         const float4* __restrict__ bnAn, const float4* __restrict__ bnBn,
         const int* __restrict__ pidxN, int M) {
    extern __shared__ char smem[];
    char* sAh = smem;
    char* sAl = smem + APLANE;
    char* sBh = smem + 2 * APLANE;
    char* sBl = smem + 2 * APLANE + BPLANE;

    int t = threadIdx.x, lane = t & 31, wid = t >> 5;
    int strm = blockIdx.y;
    int rowBase = blockIdx.x * 64;

    const float4* A1 = strm ? A1n : A1p;
    const float4* A2 = strm ? A2n : A2p;
    float4* C = strm ? Cn : Cp;
    const float4* bnA = strm ? bnAn : bnAp;
    const float4* bnB = strm ? bnBn : bnBp;

    float acc[2][4][4];
#pragma unroll
    for (int i = 0; i < 2; i++)
#pragma unroll
        for (int j = 0; j < 4; j++)
#pragma unroll
            for (int r = 0; r < 4; r++) acc[i][j][r] = 0.f;

    int M0 = (wid >> 2) * 32;
    int Nb = (wid & 3) * 32;
    int g = lane >> 2, q = lane & 3;

#pragma unroll
    for (int ph = 0; ph < 2; ph++) {
        if (ph) __syncthreads();
        const float4* A = ph ? A2 : A1;
        const uint4* Wh4 = (const uint4*)(ph ? W2h : W1h);
        const uint4* Wl4 = (const uint4*)(ph ? W2l : W1l);

#pragma unroll
        for (int i = 0; i < 8; i++) {
            int idx = t + i * 256;
            int row = idx >> 4, c = idx & 15;
            *(uint4*)(sBh + row * GP_BYTES + c * 16) = Wh4[idx];
            *(uint4*)(sBl + row * GP_BYTES + c * 16) = Wl4[idx];
        }
#pragma unroll
        for (int i = 0; i < 8; i++) {
            int idx = t + i * 256;
            int row = idx >> 5, kq = idx & 31;
            float4 v = make_float4(0.f, 0.f, 0.f, 0.f);
            int grow = rowBase + row;
            if (grow < M) {
                int rr = grow;
                if (PIDX) { if (strm && ph == 0) rr = __ldg(&pidxN[grow]); }
                v = A[rr * 32 + kq];
                if (BN && ph == 0)
                    v = bn_relu4(v, __ldg(&bnA[kq]), __ldg(&bnB[kq]));
            }
            u16 h0, l0, h1, l1, h2, l2, h3, l3;
            split_bf16(v.x, h0, l0); split_bf16(v.y, h1, l1);
            split_bf16(v.z, h2, l2); split_bf16(v.w, h3, l3);
            uint2 ph2, pl2;
            ph2.x = ((u32)h1 << 16) | h0; ph2.y = ((u32)h3 << 16) | h2;
            pl2.x = ((u32)l1 << 16) | l0; pl2.y = ((u32)l3 << 16) | l2;
            *(uint2*)(sAh + row * GP_BYTES + kq * 8) = ph2;
            *(uint2*)(sAl + row * GP_BYTES + kq * 8) = pl2;
        }
        __syncthreads();

#pragma unroll
        for (int kc = 0; kc < 8; kc++) {
            int k0 = kc * 16;
            u32 bh[4][2], bl[4][2];
#pragma unroll
            for (int fn = 0; fn < 4; fn++) {
                int n = Nb + fn * 8 + g;
                u64 pb = (u64)(n * GP_BYTES + (k0 + q * 2) * 2);
                bh[fn][0] = *(const u32*)(sBh + pb);
                bh[fn][1] = *(const u32*)(sBh + pb + 16);
                bl[fn][0] = *(const u32*)(sBl + pb);
                bl[fn][1] = *(const u32*)(sBl + pb + 16);
            }
#pragma unroll
            for (int fm = 0; fm < 2; fm++) {
                int r = M0 + fm * 16 + g;
                u64 ao = (u64)(r * GP_BYTES + (k0 + q * 2) * 2);
                u32 ah[4], al[4];
                ah[0] = *(const u32*)(sAh + ao);
                ah[1] = *(const u32*)(sAh + ao + 8 * GP_BYTES);
                ah[2] = *(const u32*)(sAh + ao + 16);
                ah[3] = *(const u32*)(sAh + ao + 8 * GP_BYTES + 16);
                al[0] = *(const u32*)(sAl + ao);
                al[1] = *(const u32*)(sAl + ao + 8 * GP_BYTES);
                al[2] = *(const u32*)(sAl + ao + 16);
                al[3] = *(const u32*)(sAl + ao + 8 * GP_BYTES + 16);
#pragma unroll
                for (int fn = 0; fn < 4; fn++) {
                    mma_bf16(acc[fm][fn], ah, bh[fn]);
                    mma_bf16(acc[fm][fn], ah, bl[fn]);
                    mma_bf16(acc[fm][fn], al, bh[fn]);
                }
            }
        }
    }

    float* Cf = (float*)C;
#pragma unroll
    for (int fn = 0; fn < 4; fn++) {
        int col = Nb + fn * 8 + q * 2;
        float2 bv = *(const float2*)(bias + col);
#pragma unroll
        for (int fm = 0; fm < 2; fm++) {
            int row0 = rowBase + M0 + fm * 16 + g;
            int row1 = row0 + 8;
            if (row0 < M) {
                float2 o = make_float2(acc[fm][fn][0] + bv.x, acc[fm][fn][1] + bv.y);
                *(float2*)(Cf + row0 * D + col) = o;
            }
            if (row1 < M) {
                float2 o = make_float2(acc[fm][fn][2] + bv.x, acc[fm][fn][3] + bv.y);
                *(float2*)(Cf + row1 * D + col) = o;
            }
        }
    }
}

// ---------------- f32x2 GEMM (predictor only, R9-proven) ----------------
template <bool PAIRG>
__global__ void __launch_bounds__(512, 1)
gemm_v4(const float4* __restrict__ A, const float4* __restrict__ W,
        const float* __restrict__ bias, float4* __restrict__ C,
        const int* __restrict__ ga, const int* __restrict__ gb,
        const int* __restrict__ ga2, const int* __restrict__ gb2,
        int M, int relu) {
    extern __shared__ float4 smem4[];
    float4* sA = smem4;
    float4* sB = smem4 + 4096;

    int t = threadIdx.x;
    int rowBase = blockIdx.x * 128;
    int c8 = t & 15;
    int r0 = (t >> 4) * 4;
    const ulonglong2* sB2 = (const ulonglong2*)sB;

    u64 acc[4][4];
#pragma unroll
    for (int i = 0; i < 4; i++)
#pragma unroll
        for (int j = 0; j < 4; j++) acc[i][j] = 0ULL;

#pragma unroll
    for (int i = 0; i < 8; i++) sB[t + i * 512] = W[t + i * 512];
#pragma unroll
    for (int i = 0; i < 8; i++) {
        int p = t + i * 512;
        int r = p >> 5, kq = p & 31;
        int row = rowBase + r;
        float4 v = make_float4(0.f, 0.f, 0.f, 0.f);
        if (row < M) {
            if (PAIRG) {
                const int* A_ = (row < EPAIR) ? ga : ga2;
                const int* B_ = (row < EPAIR) ? gb : gb2;
                int rr = (row < EPAIR) ? row : row - EPAIR;
                float4 u = A[A_[rr] * 32 + kq];
                float4 w = A[B_[rr] * 32 + kq];
                v = make_float4(u.x * w.x, u.y * w.y, u.z * w.z, u.w * w.w);
            } else {
                v = A[row * 32 + kq];
            }
        }
        sA[r * 32 + kq] = v;
    }
    __syncthreads();

#pragma unroll 4
    for (int k4 = 0; k4 < 32; k4++) {
        float4 a0 = sA[(r0 + 0) * 32 + k4];
        float4 a1 = sA[(r0 + 1) * 32 + k4];
        float4 a2 = sA[(r0 + 2) * 32 + k4];
        float4 a3 = sA[(r0 + 3) * 32 + k4];
#pragma unroll
        for (int kk = 0; kk < 4; kk++) {
            int k = k4 * 4 + kk;
            ulonglong2 p0 = sB2[k * 32 + c8];
            ulonglong2 p1 = sB2[k * 32 + 16 + c8];
            float f0 = kk == 0 ? a0.x : kk == 1 ? a0.y : kk == 2 ? a0.z : a0.w;
            float f1 = kk == 0 ? a1.x : kk == 1 ? a1.y : kk == 2 ? a1.z : a1.w;
            float f2 = kk == 0 ? a2.x : kk == 1 ? a2.y : kk == 2 ? a2.z : a2.w;
            float f3 = kk == 0 ? a3.x : kk == 1 ? a3.y : kk == 2 ? a3.z : a3.w;
            u64 aa0 = pk2(f0, f0);
            u64 aa1 = pk2(f1, f1);
            u64 aa2 = pk2(f2, f2);
            u64 aa3 = pk2(f3, f3);
            acc[0][0] = fma2(aa0, p0.x, acc[0][0]);
            acc[0][1] = fma2(aa0, p0.y, acc[0][1]);
            acc[0][2] = fma2(aa0, p1.x, acc[0][2]);
            acc[0][3] = fma2(aa0, p1.y, acc[0][3]);
            acc[1][0] = fma2(aa1, p0.x, acc[1][0]);
            acc[1][1] = fma2(aa1, p0.y, acc[1][1]);
            acc[1][2] = fma2(aa1, p1.x, acc[1][2]);
            acc[1][3] = fma2(aa1, p1.y, acc[1][3]);
            acc[2][0] = fma2(aa2, p0.x, acc[2][0]);
            acc[2][1] = fma2(aa2, p0.y, acc[2][1]);
            acc[2][2] = fma2(aa2, p1.x, acc[2][2]);
            acc[2][3] = fma2(aa2, p1.y, acc[2][3]);
            acc[3][0] = fma2(aa3, p0.x, acc[3][0]);
            acc[3][1] = fma2(aa3, p0.y, acc[3][1]);
            acc[3][2] = fma2(aa3, p1.x, acc[3][2]);
            acc[3][3] = fma2(aa3, p1.y, acc[3][3]);
        }
    }

    float4 bv0 = ((const float4*)bias)[c8];
    float4 bv1 = ((const float4*)bias)[16 + c8];

#pragma unroll
    for (int i = 0; i < 4; i++) {
        int row = rowBase + r0 + i;
        if (row >= M) continue;
        float4 o0, o1;
        upk2(acc[i][0], o0.x, o0.y);
        upk2(acc[i][1], o0.z, o0.w);
        upk2(acc[i][2], o1.x, o1.y);
        upk2(acc[i][3], o1.z, o1.w);
        o0.x += bv0.x; o0.y += bv0.y; o0.z += bv0.z; o0.w += bv0.w;
        o1.x += bv1.x; o1.y += bv1.y; o1.z += bv1.z; o1.w += bv1.w;
        if (relu) {
            o0.x = fmaxf(o0.x, 0.f); o0.y = fmaxf(o0.y, 0.f);
            o0.z = fmaxf(o0.z, 0.f); o0.w = fmaxf(o0.w, 0.f);
            o1.x = fmaxf(o1.x, 0.f); o1.y = fmaxf(o1.y, 0.f);
            o1.z = fmaxf(o1.z, 0.f); o1.w = fmaxf(o1.w, 0.f);
        }
        C[row * 32 + c8]      = o0;
        C[row * 32 + 16 + c8] = o1;
    }
}

// per-column stats, both streams via grid.y
__global__ void k_colstats2(const float* __restrict__ Hp, const float* __restrict__ Hn,
                            int M, float* __restrict__ stats) {
    const float* H = blockIdx.y ? Hn : Hp;
    float* sum = stats + blockIdx.y * 2 * D;
    float* sq  = sum + D;
    int c = threadIdx.x;
    int r0 = blockIdx.x * 256;
    int rend = r0 + 256; if (rend > M) rend = M;
    float s = 0.f, s2 = 0.f;
    for (int r = r0; r < rend; r++) {
        float v = H[r * D + c];
        s += v; s2 += v * v;
    }
    atomicAdd(&sum[c], s);
    atomicAdd(&sq[c], s2);
}

// fold stats + gamma/beta -> per-column scale/shift (both streams)
__global__ void k_bncoef(const float* __restrict__ stats,
                         const float* __restrict__ gamma, const float* __restrict__ beta,
                         float* __restrict__ bnA, float* __restrict__ bnB, int M) {
    int t = threadIdx.x;             // 256 = 2 streams x 128 cols
    int strm = t >> 7, c = t & 127;
    const float* st = stats + strm * 2 * D;
    float invM = 1.0f / (float)M;
    float m = st[c] * invM;
    float v = st[D + c] * invM - m * m;
    float a = gamma[c] * rsqrtf(v + BN_EPS);
    bnA[strm * D + c] = a;
    bnB[strm * D + c] = beta[c] - m * a;
}

__global__ void k_colstats(const float* __restrict__ H, int M,
                           float* __restrict__ sum, float* __restrict__ sq) {
    int c = threadIdx.x;
    int r0 = blockIdx.x * 256;
    int rend = r0 + 256; if (rend > M) rend = M;
    float s = 0.f, s2 = 0.f;
    for (int r = r0; r < rend; r++) {
        float v = H[r * D + c];
        s += v; s2 += v * v;
    }
    atomicAdd(&sum[c], s);
    atomicAdd(&sq[c], s2);
}

__global__ void k_summary_ws(const float* __restrict__ colsum,
                             const float* __restrict__ discW, float* __restrict__ ws) {
    __shared__ float sm[D];
    int t = threadIdx.x;
    float mn = colsum[t] / (float)N3;
    sm[t] = 1.0f / (1.0f + expf(-mn));
    __syncthreads();
    float a = 0.f;
#pragma unroll 8
    for (int j = 0; j < D; j++) a += discW[t * D + j] * sm[j];
    ws[t] = a;
}

__device__ __forceinline__ float warp_dot128(const float4* __restrict__ a,
                                             const float4* __restrict__ b, int lane) {
    float4 x = a[lane], y = b[lane];
    float s = x.x * y.x + x.y * y.y + x.z * y.z + x.w * y.w;
#pragma unroll
    for (int o = 16; o; o >>= 1) s += __shfl_down_sync(0xffffffffu, s, o);
    return s;
}

__global__ void k_loss(const float4* __restrict__ pos, const float4* __restrict__ neg,
                       const float4* __restrict__ ws, float* __restrict__ loss) {
    int tid = blockIdx.x * blockDim.x + threadIdx.x;
    int e = tid >> 5;
    if (e >= 2 * N3) return;
    int lane = tid & 31;
    int strm = (e >= N3);
    int r = e - strm * N3;
    const float4* row = (strm ? neg : pos) + r * 32;
    float s = warp_dot128(row, ws, lane);
    if (lane == 0) {
        float xx = strm ? s : -s;
        float sp = fmaxf(xx, 0.f) + log1pf(expf(-fabsf(xx)));
        atomicAdd(&loss[strm], sp);
    }
}

__global__ void k_pred_out(const float4* __restrict__ z, const float4* __restrict__ w3,
                           const float* __restrict__ b3, float* __restrict__ out) {
    int tid = blockIdx.x * blockDim.x + threadIdx.x;
    int e = tid >> 5;
    if (e >= 2 * EPAIR) return;
    int lane = tid & 31;
    float s = warp_dot128(z + e * 32, w3, lane);
    if (lane == 0) out[e] = s + b3[0];
}

__global__ void k_final_loss(const float* __restrict__ loss, float* __restrict__ out) {
    out[0] = (loss[0] + loss[1]) * (1.0f / (float)N3);
}

// ---------------- host orchestration ----------------
extern "C" void kernel_launch(void* const* d_in, const int* in_sizes, int n_in,
                              void* d_out, int out_size) {
    const float* x      = (const float*)d_in[0];
    const int* srcs[3]  = {(const int*)d_in[1], (const int*)d_in[3], (const int*)d_in[5]};
    const int* dsts[3]  = {(const int*)d_in[2], (const int*)d_in[4], (const int*)d_in[6]};
    const int* perm     = (const int*)d_in[7];
    const int* pos_src  = (const int*)d_in[8];
    const int* pos_dst  = (const int*)d_in[9];
    const int* neg_src  = (const int*)d_in[10];
    const int* neg_dst  = (const int*)d_in[11];
    const float* Ws[3]  = {(const float*)d_in[12], (const float*)d_in[15], (const float*)d_in[18]};
    const float* Wn[3]  = {(const float*)d_in[13], (const float*)d_in[16], (const float*)d_in[19]};
    const float* bb[3]  = {(const float*)d_in[14], (const float*)d_in[17], (const float*)d_in[20]};
    const float* gamma[2] = {(const float*)d_in[21], (const float*)d_in[23]};
    const float* beta [2] = {(const float*)d_in[22], (const float*)d_in[24]};
    const float* discW  = (const float*)d_in[25];
    const float* pW1 = (const float*)d_in[26]; const float* pb1 = (const float*)d_in[27];
    const float* pW2 = (const float*)d_in[28]; const float* pb2 = (const float*)d_in[29];
    const float* pW3 = (const float*)d_in[30]; const float* pb3 = (const float*)d_in[31];
    float* out = (float*)d_out;

    int E[3] = {in_sizes[1], in_sizes[3], in_sizes[5]};
    int ND[3] = {N1, N2, N3};
    int segbase[3] = {0, N1, N1 + N2};

    float *p_bufA, *p_bufB, *p_agg, *p_stats, *p_bnA, *p_bnB, *p_csum, *p_csq,
          *p_ws, *p_loss, *p_z, *p_z2;
    int *p_cnt, *p_off, *p_slot, *p_csr, *p_csr2;
    __nv_bfloat16 *p_wth, *p_wtl;
    cudaGetSymbolAddress((void**)&p_bufA,  g_bufA);
    cudaGetSymbolAddress((void**)&p_bufB,  g_bufB);
    cudaGetSymbolAddress((void**)&p_agg,   g_agg);
    cudaGetSymbolAddress((void**)&p_cnt,   g_cnt);
    cudaGetSymbolAddress((void**)&p_off,   g_off);
    cudaGetSymbolAddress((void**)&p_slot,  g_slot);
    cudaGetSymbolAddress((void**)&p_csr,   g_csr);
    cudaGetSymbolAddress((void**)&p_csr2,  g_csr2);
    cudaGetSymbolAddress((void**)&p_stats, g_stats);
    cudaGetSymbolAddress((void**)&p_bnA,   g_bnA);
    cudaGetSymbolAddress((void**)&p_bnB,   g_bnB);
    cudaGetSymbolAddress((void**)&p_csum,  g_csum);
    cudaGetSymbolAddress((void**)&p_csq,   g_csq_dummy);
    cudaGetSymbolAddress((void**)&p_ws,    g_ws);
    cudaGetSymbolAddress((void**)&p_loss,  g_loss);
    cudaGetSymbolAddress((void**)&p_z,     g_z);
    cudaGetSymbolAddress((void**)&p_z2,    g_z2);
    cudaGetSymbolAddress((void**)&p_wth,   g_wth);
    cudaGetSymbolAddress((void**)&p_wtl,   g_wtl);

    const size_t PRED_SMEM = 131072;
    cudaFuncSetAttribute(gemm_v4<true >, cudaFuncAttributeMaxDynamicSharedMemorySize, PRED_SMEM);
    cudaFuncSetAttribute(gemm_v4<false>, cudaFuncAttributeMaxDynamicSharedMemorySize, PRED_SMEM);
    cudaFuncSetAttribute((const void*)gemm_mma<true,  false>, cudaFuncAttributeMaxDynamicSharedMemorySize, MMA_SMEM);
    cudaFuncSetAttribute((const void*)gemm_mma<false, true >, cudaFuncAttributeMaxDynamicSharedMemorySize, MMA_SMEM);

    int Etot = E[0] + E[1] + E[2];

    // weight prep
    {
        dim3 pgrid(1, 6);
        k_prep_w<<<pgrid, 256>>>((const float4*)Ws[0], (const float4*)Wn[0],
                                 (const float4*)Ws[1], (const float4*)Wn[1],
                                 (const float4*)Ws[2], (const float4*)Wn[2]);
    }

    // batched CSR build (count records slots; fill atomic-free)
    cudaMemsetAsync(p_cnt, 0, NTOT * sizeof(int), 0);
    k_count_all<<<(Etot + 255) / 256, 256>>>(dsts[0], E[0], dsts[1], E[1], dsts[2], E[2],
                                             p_cnt, p_slot);
    k_scan<<<1, 1024>>>(p_cnt, NTOT, p_off);
    k_fill_all<<<(Etot + 255) / 256, 256>>>(srcs[0], dsts[0], E[0],
                                            srcs[1], dsts[1], E[1],
                                            srcs[2], dsts[2], E[2],
                                            perm, p_off, p_slot, p_csr, p_csr2);

    float* bufA[2] = {p_bufA, p_bufA + (size_t)N1 * D};
    float* bufB[2] = {p_bufB, p_bufB + (size_t)N2 * D};
    float* agg [2] = {p_agg,  p_agg  + (size_t)N1 * D};
    float* bnAp = p_bnA;          float* bnAn = p_bnA + D;
    float* bnBp = p_bnB;          float* bnBn = p_bnB + D;

    const float* hinP = x;
    const float* hinN = x;   // layer-0 negative: x with perm indirection

    for (int l = 0; l < 3; l++) {
        int nd = ND[l];
        float* outb[2];
        if (l == 1) { outb[0] = bufB[0]; outb[1] = bufB[1]; }
        else        { outb[0] = bufA[0]; outb[1] = bufA[1]; }

        const int* csrN = (l == 0) ? p_csr2 : p_csr;
        if (l == 0) {
            k_gather4<false><<<(nd * 32 + 255) / 256, 256>>>(
                (const float4*)hinP, (const float4*)hinN, p_csr, csrN,
                p_off + segbase[l], nullptr, nullptr, nullptr, nullptr,
                (float4*)agg[0], (float4*)agg[1], nd);
        } else {
            k_gather4<true><<<(nd * 32 + 255) / 256, 256>>>(
                (const float4*)hinP, (const float4*)hinN, p_csr, csrN,
                p_off + segbase[l],
                (const float4*)bnAp, (const float4*)bnBp,
                (const float4*)bnAn, (const float4*)bnBn,
                (float4*)agg[0], (float4*)agg[1], nd);
        }

        const __nv_bfloat16* W1h = p_wth + (size_t)(2 * l) * D * D;
        const __nv_bfloat16* W1l = p_wtl + (size_t)(2 * l) * D * D;
        const __nv_bfloat16* W2h = p_wth + (size_t)(2 * l + 1) * D * D;
        const __nv_bfloat16* W2l = p_wtl + (size_t)(2 * l + 1) * D * D;

        dim3 grid((nd + 63) / 64, 2);
        if (l == 0) {
            gemm_mma<true, false><<<grid, 256, MMA_SMEM>>>(
                (const float4*)hinP, (const float4*)hinN,
                (const float4*)agg[0], (const float4*)agg[1],
                W1h, W1l, W2h, W2l, bb[l],
                (float4*)outb[0], (float4*)outb[1],
                nullptr, nullptr, nullptr, nullptr, perm, nd);
        } else {
            gemm_mma<false, true><<<grid, 256, MMA_SMEM>>>(
                (const float4*)hinP, (const float4*)hinN,
                (const float4*)agg[0], (const float4*)agg[1],
                W1h, W1l, W2h, W2l, bb[l],
                (float4*)outb[0], (float4*)outb[1],
                (const float4*)bnAp, (const float4*)bnBp,
                (const float4*)bnAn, (const float4*)bnBn, nullptr, nd);
        }

        if (l < 2) {
            cudaMemsetAsync(p_stats, 0, 2 * 2 * D * sizeof(float), 0);
            dim3 sgrid((nd + 255) / 256, 2);
            k_colstats2<<<sgrid, 128>>>(outb[0], outb[1], nd, p_stats);
            k_bncoef<<<1, 256>>>(p_stats, gamma[l], beta[l], p_bnA, p_bnB, nd);
        }
        hinP = outb[0];
        hinN = outb[1];
    }

    float* positive = bufA[0];
    float* negative = bufA[1];

    cudaMemsetAsync(p_csum, 0, D * sizeof(float), 0);
    cudaMemsetAsync(p_loss, 0, 2 * sizeof(float), 0);
    k_colstats<<<(N3 + 255) / 256, 128>>>(positive, N3, p_csum, p_csq);
    k_summary_ws<<<1, 128>>>(p_csum, discW, p_ws);
    k_loss<<<(2 * N3 * 32 + 255) / 256, 256>>>((const float4*)positive,
                                               (const float4*)negative,
                                               (const float4*)p_ws, p_loss);

    // link predictor: 20000 rows, pair-product fused into GEMM1 (f32x2 path)
    int Mp = 2 * EPAIR;
    int pgblocks = (Mp + 127) / 128;
    gemm_v4<true><<<pgblocks, 512, PRED_SMEM>>>(
        (const float4*)positive, (const float4*)pW1, pb1, (float4*)p_z2,
        pos_src, pos_dst, neg_src, neg_dst, Mp, 1);
    gemm_v4<false><<<pgblocks, 512, PRED_SMEM>>>(
        (const float4*)p_z2, (const float4*)pW2, pb2, (float4*)p_z,
        nullptr, nullptr, nullptr, nullptr, Mp, 1);
    k_pred_out<<<(Mp * 32 + 255) / 256, 256>>>((const float4*)p_z,
                                               (const float4*)pW3, pb3, out);

    k_final_loss<<<1, 1>>>(p_loss, out + 2 * EPAIR);
}

// round 16
// speedup vs baseline: 2.2058x; 1.0091x over previous
#include <cuda_runtime.h>
#include <cuda_bf16.h>
#include <math.h>

#define N0 100000
#define N1 50000
#define N2 25000
#define N3 12500
#define D  128
#define EPAIR 10000
#define NTOT 87500
#define ETOT 1125000
#define BN_EPS 1e-5f

typedef unsigned int u32;
typedef unsigned short u16;
typedef unsigned long long u64;

// ---------------- scratch ----------------
__device__ float g_bufA[2][N1 * D];
__device__ float g_bufB[2][N2 * D];
__device__ float g_agg [2][N1 * D];
__device__ int   g_cnt [NTOT];
__device__ int   g_off [NTOT + 1];
__device__ int   g_slot[ETOT];
__device__ int   g_csr [ETOT];
__device__ int   g_csr2[750000];         // layer-0 only (perm[src])
__device__ float g_stats[2][2][D];
__device__ float g_bnA[2][D];
__device__ float g_bnB[2][D];
__device__ float g_csum[D];
__device__ float g_csq_dummy[D];
__device__ float g_ws[D];
__device__ float g_loss[2];
__device__ float g_z [2 * EPAIR * D];
__device__ float g_z2[2 * EPAIR * D];
__device__ __nv_bfloat16 g_wth[6][D * D];
__device__ __nv_bfloat16 g_wtl[6][D * D];

// ---------------- f32x2 helpers (predictor GEMM) ----------------
__device__ __forceinline__ u64 pk2(float x, float y) {
    u64 r; asm("mov.b64 %0, {%1, %2};" : "=l"(r) : "f"(x), "f"(y)); return r;
}
__device__ __forceinline__ void upk2(u64 v, float& x, float& y) {
    asm("mov.b64 {%0, %1}, %2;" : "=f"(x), "=f"(y) : "l"(v));
}
__device__ __forceinline__ u64 fma2(u64 a, u64 b, u64 c) {
    u64 d; asm("fma.rn.f32x2 %0, %1, %2, %3;" : "=l"(d) : "l"(a), "l"(b), "l"(c)); return d;
}

// ---------------- bf16 split / mma helpers ----------------
__device__ __forceinline__ void split_bf16(float x, u16& hi, u16& lo) {
    __nv_bfloat16 h = __float2bfloat16(x);
    float hf = __bfloat162float(h);
    __nv_bfloat16 l = __float2bfloat16(x - hf);
    hi = __bfloat16_as_ushort(h);
    lo = __bfloat16_as_ushort(l);
}
__device__ __forceinline__ void mma_bf16(float* d, const u32* a, const u32* b) {
    asm volatile(
        "mma.sync.aligned.m16n8k16.row.col.f32.bf16.bf16.f32 "
        "{%0,%1,%2,%3}, {%4,%5,%6,%7}, {%8,%9}, {%0,%1,%2,%3};"
        : "+f"(d[0]), "+f"(d[1]), "+f"(d[2]), "+f"(d[3])
        : "r"(a[0]), "r"(a[1]), "r"(a[2]), "r"(a[3]), "r"(b[0]), "r"(b[1]));
}

__device__ __forceinline__ float4 bn_relu4(float4 v, float4 a, float4 b) {
    v.x = fmaxf(fmaf(v.x, a.x, b.x), 0.f);
    v.y = fmaxf(fmaf(v.y, a.y, b.y), 0.f);
    v.z = fmaxf(fmaf(v.z, a.z, b.z), 0.f);
    v.w = fmaxf(fmaf(v.w, a.w, b.w), 0.f);
    return v;
}

// ---------------- CSR build ----------------
__global__ void k_count_all(const int* __restrict__ d0, int E0,
                            const int* __restrict__ d1, int E1,
                            const int* __restrict__ d2, int E2,
                            int* __restrict__ cnt, int* __restrict__ slot) {
    int e = blockIdx.x * blockDim.x + threadIdx.x;
    int node;
    if (e < E0) node = d0[e];
    else if (e < E0 + E1) node = N1 + d1[e - E0];
    else if (e < E0 + E1 + E2) node = N1 + N2 + d2[e - E0 - E1];
    else return;
    slot[e] = atomicAdd(&cnt[node], 1);
}

__global__ void k_scan(const int* __restrict__ cnt, int n, int* __restrict__ off) {
    __shared__ int wsum[32];
    int t = threadIdx.x, lane = t & 31, wid = t >> 5;
    int carry = 0;
    for (int base = 0; base < n; base += 8192) {
        int v[8]; int s = 0;
#pragma unroll
        for (int u = 0; u < 8; u++) {
            int i = base + t * 8 + u;
            v[u] = (i < n) ? cnt[i] : 0;
            s += v[u];
        }
        int ps = s;
#pragma unroll
        for (int o = 1; o < 32; o <<= 1) {
            int x = __shfl_up_sync(0xffffffffu, ps, o);
            if (lane >= o) ps += x;
        }
        if (lane == 31) wsum[wid] = ps;
        __syncthreads();
        if (t < 32) {
            int x = wsum[t];
#pragma unroll
            for (int o = 1; o < 32; o <<= 1) {
                int y = __shfl_up_sync(0xffffffffu, x, o);
                if (t >= o) x += y;
            }
            wsum[t] = x;
        }
        __syncthreads();
        int warpbase = wid ? wsum[wid - 1] : 0;
        int run = carry + warpbase + (ps - s);
#pragma unroll
        for (int u = 0; u < 8; u++) {
            int i = base + t * 8 + u;
            if (i < n) off[i] = run;
            run += v[u];
        }
        carry += wsum[31];
        __syncthreads();
    }
    if (t == 0) off[n] = carry;
}

__global__ void k_fill_all(const int* __restrict__ s0, const int* __restrict__ d0, int E0,
                           const int* __restrict__ s1, const int* __restrict__ d1, int E1,
                           const int* __restrict__ s2, const int* __restrict__ d2, int E2,
                           const int* __restrict__ perm,
                           const int* __restrict__ off, const int* __restrict__ slot,
                           int* __restrict__ csr, int* __restrict__ csr2) {
    int e = blockIdx.x * blockDim.x + threadIdx.x;
    if (e < E0) {
        int src = s0[e];
        int p = off[d0[e]] + slot[e];
        csr[p] = src;
        csr2[p] = __ldg(&perm[src]);
    } else if (e < E0 + E1) {
        int i = e - E0;
        int p = off[N1 + d1[i]] + slot[e];
        csr[p] = s1[i];
    } else if (e < E0 + E1 + E2) {
        int i = e - E0 - E1;
        int p = off[N1 + N2 + d2[i]] + slot[e];
        csr[p] = s2[i];
    }
}

// ---------------- gather: one warp per (row, stream); 4-edge unroll ----------------
template <bool BN>
__global__ void k_gather5(const float4* __restrict__ hp, const float4* __restrict__ hn,
                          const int* __restrict__ csrP, const int* __restrict__ csrN,
                          const int* __restrict__ off,
                          const float4* __restrict__ bnAp, const float4* __restrict__ bnBp,
                          const float4* __restrict__ bnAn, const float4* __restrict__ bnBn,
                          float4* __restrict__ ap, float4* __restrict__ an, int M) {
    int w = (blockIdx.x * blockDim.x + threadIdx.x) >> 5;
    if (w >= 2 * M) return;
    int row = w >> 1, strm = w & 1;
    int lane = threadIdx.x & 31;

    const float4* h = strm ? hn : hp;
    const int* csr = strm ? csrN : csrP;
    float4* outp = strm ? an : ap;

    float4 cA, cB;
    if (BN) {
        cA = __ldg((strm ? bnAn : bnAp) + lane);
        cB = __ldg((strm ? bnBn : bnBp) + lane);
    }

    int s0 = off[row], s1 = off[row + 1];
    float4 acc = make_float4(0.f, 0.f, 0.f, 0.f);
    int j = s0;
    for (; j + 4 <= s1; j += 4) {
        int a0 = __ldg(&csr[j]),     a1 = __ldg(&csr[j + 1]);
        int a2 = __ldg(&csr[j + 2]), a3 = __ldg(&csr[j + 3]);
        float4 v0 = h[a0 * 32 + lane], v1 = h[a1 * 32 + lane];
        float4 v2 = h[a2 * 32 + lane], v3 = h[a3 * 32 + lane];
        if (BN) {
            v0 = bn_relu4(v0, cA, cB); v1 = bn_relu4(v1, cA, cB);
            v2 = bn_relu4(v2, cA, cB); v3 = bn_relu4(v3, cA, cB);
        }
        acc.x += (v0.x + v1.x) + (v2.x + v3.x);
        acc.y += (v0.y + v1.y) + (v2.y + v3.y);
        acc.z += (v0.z + v1.z) + (v2.z + v3.z);
        acc.w += (v0.w + v1.w) + (v2.w + v3.w);
    }
    for (; j < s1; j++) {
        int a0 = __ldg(&csr[j]);
        float4 v0 = h[a0 * 32 + lane];
        if (BN) v0 = bn_relu4(v0, cA, cB);
        acc.x += v0.x; acc.y += v0.y; acc.z += v0.z; acc.w += v0.w;
    }
    int deg = s1 - s0;
    float inv = 1.0f / (float)(deg > 0 ? deg : 1);
    acc.x *= inv; acc.y *= inv; acc.z *= inv; acc.w *= inv;
    outp[row * 32 + lane] = acc;
}

// ---------------- weight prep ----------------
__global__ void k_prep_w(const float4* __restrict__ W0, const float4* __restrict__ W1,
                         const float4* __restrict__ W2, const float4* __restrict__ W3,
                         const float4* __restrict__ W4, const float4* __restrict__ W5) {
    int m = blockIdx.y;
    const float4* W = m == 0 ? W0 : m == 1 ? W1 : m == 2 ? W2 : m == 3 ? W3 : m == 4 ? W4 : W5;
    __nv_bfloat16* Th = g_wth[m];
    __nv_bfloat16* Tl = g_wtl[m];
    int t = threadIdx.x;
#pragma unroll
    for (int i = 0; i < 16; i++) {
        int idx = t + i * 256;
        int k = idx >> 5, nq = idx & 31;
        float4 v = W[idx];
        float xs[4] = {v.x, v.y, v.z, v.w};
#pragma unroll
        for (int j = 0; j < 4; j++) {
            int n = nq * 4 + j;
            u16 hi, lo;
            split_bf16(xs[j], hi, lo);
            Th[n * D + k] = __ushort_as_bfloat16(hi);
            Tl[n * D + k] = __ushort_as_bfloat16(lo);
        }
    }
}

// ---------------- mma.sync bf16-split layer GEMM (R12/R15-proven) ----------------
#define GP_BYTES 272
#define APLANE (64 * GP_BYTES)
#define BPLANE (128 * GP_BYTES)
#define MMA_SMEM (2 * APLANE + 2 * BPLANE)

template <bool PIDX, bool BN>
__global__ void __launch_bounds__(256, 2)
gemm_mma(const float4* __restrict__ A1p, const float4* __restrict__ A1n,
         const float4* __restrict__ A2p, const float4* __restrict__ A2n,
         const __nv_bfloat16* __restrict__ W1h, const __nv_bfloat16* __restrict__ W1l,
         const __nv_bfloat16* __restrict__ W2h, const __nv_bfloat16* __restrict__ W2l,
         const float* __restrict__ bias,
         float4* __restrict__ Cp, float4* __restrict__ Cn,
         const float4* __restrict__ bnAp, const float4* __restrict__ bnBp,
         const float4* __restrict__ bnAn, const float4* __restrict__ bnBn,
         const int* __restrict__ pidxN, int M) {
    extern __shared__ char smem[];
    char* sAh = smem;
    char* sAl = smem + APLANE;
    char* sBh = smem + 2 * APLANE;
    char* sBl = smem + 2 * APLANE + BPLANE;

    int t = threadIdx.x, lane = t & 31, wid = t >> 5;
    int strm = blockIdx.y;
    int rowBase = blockIdx.x * 64;

    const float4* A1 = strm ? A1n : A1p;
    const float4* A2 = strm ? A2n : A2p;
    float4* C = strm ? Cn : Cp;
    const float4* bnA = strm ? bnAn : bnAp;
    const float4* bnB = strm ? bnBn : bnBp;

    float acc[2][4][4];
#pragma unroll
    for (int i = 0; i < 2; i++)
#pragma unroll
        for (int j = 0; j < 4; j++)
#pragma unroll
            for (int r = 0; r < 4; r++) acc[i][j][r] = 0.f;

    int M0 = (wid >> 2) * 32;
    int Nb = (wid & 3) * 32;
    int g = lane >> 2, q = lane & 3;

#pragma unroll
    for (int ph = 0; ph < 2; ph++) {
        if (ph) __syncthreads();
        const float4* A = ph ? A2 : A1;
        const uint4* Wh4 = (const uint4*)(ph ? W2h : W1h);
        const uint4* Wl4 = (const uint4*)(ph ? W2l : W1l);

#pragma unroll
        for (int i = 0; i < 8; i++) {
            int idx = t + i * 256;
            int row = idx >> 4, c = idx & 15;
            *(uint4*)(sBh + row * GP_BYTES + c * 16) = Wh4[idx];
            *(uint4*)(sBl + row * GP_BYTES + c * 16) = Wl4[idx];
        }
#pragma unroll
        for (int i = 0; i < 8; i++) {
            int idx = t + i * 256;
            int row = idx >> 5, kq = idx & 31;
            float4 v = make_float4(0.f, 0.f, 0.f, 0.f);
            int grow = rowBase + row;
            if (grow < M) {
                int rr = grow;
                if (PIDX) { if (strm && ph == 0) rr = __ldg(&pidxN[grow]); }
                v = A[rr * 32 + kq];
                if (BN && ph == 0)
                    v = bn_relu4(v, __ldg(&bnA[kq]), __ldg(&bnB[kq]));
            }
            u16 h0, l0, h1, l1, h2, l2, h3, l3;
            split_bf16(v.x, h0, l0); split_bf16(v.y, h1, l1);
            split_bf16(v.z, h2, l2); split_bf16(v.w, h3, l3);
            uint2 ph2, pl2;
            ph2.x = ((u32)h1 << 16) | h0; ph2.y = ((u32)h3 << 16) | h2;
            pl2.x = ((u32)l1 << 16) | l0; pl2.y = ((u32)l3 << 16) | l2;
            *(uint2*)(sAh + row * GP_BYTES + kq * 8) = ph2;
            *(uint2*)(sAl + row * GP_BYTES + kq * 8) = pl2;
        }
        __syncthreads();

#pragma unroll
        for (int kc = 0; kc < 8; kc++) {
            int k0 = kc * 16;
            u32 bh[4][2], bl[4][2];
#pragma unroll
            for (int fn = 0; fn < 4; fn++) {
                int n = Nb + fn * 8 + g;
                u64 pb = (u64)(n * GP_BYTES + (k0 + q * 2) * 2);
                bh[fn][0] = *(const u32*)(sBh + pb);
                bh[fn][1] = *(const u32*)(sBh + pb + 16);
                bl[fn][0] = *(const u32*)(sBl + pb);
                bl[fn][1] = *(const u32*)(sBl + pb + 16);
            }
#pragma unroll
            for (int fm = 0; fm < 2; fm++) {
                int r = M0 + fm * 16 + g;
                u64 ao = (u64)(r * GP_BYTES + (k0 + q * 2) * 2);
                u32 ah[4], al[4];
                ah[0] = *(const u32*)(sAh + ao);
                ah[1] = *(const u32*)(sAh + ao + 8 * GP_BYTES);
                ah[2] = *(const u32*)(sAh + ao + 16);
                ah[3] = *(const u32*)(sAh + ao + 8 * GP_BYTES + 16);
                al[0] = *(const u32*)(sAl + ao);
                al[1] = *(const u32*)(sAl + ao + 8 * GP_BYTES);
                al[2] = *(const u32*)(sAl + ao + 16);
                al[3] = *(const u32*)(sAl + ao + 8 * GP_BYTES + 16);
#pragma unroll
                for (int fn = 0; fn < 4; fn++) {
                    mma_bf16(acc[fm][fn], ah, bh[fn]);
                    mma_bf16(acc[fm][fn], ah, bl[fn]);
                    mma_bf16(acc[fm][fn], al, bh[fn]);
                }
            }
        }
    }

    float* Cf = (float*)C;
#pragma unroll
    for (int fn = 0; fn < 4; fn++) {
        int col = Nb + fn * 8 + q * 2;
        float2 bv = *(const float2*)(bias + col);
#pragma unroll
        for (int fm = 0; fm < 2; fm++) {
            int row0 = rowBase + M0 + fm * 16 + g;
            int row1 = row0 + 8;
            if (row0 < M) {
                float2 o = make_float2(acc[fm][fn][0] + bv.x, acc[fm][fn][1] + bv.y);
                *(float2*)(Cf + row0 * D + col) = o;
            }
            if (row1 < M) {
                float2 o = make_float2(acc[fm][fn][2] + bv.x, acc[fm][fn][3] + bv.y);
                *(float2*)(Cf + row1 * D + col) = o;
            }
        }
    }
}

// ---------------- f32x2 GEMM (predictor only, R9-proven) ----------------
template <bool PAIRG>
__global__ void __launch_bounds__(512, 1)
gemm_v4(const float4* __restrict__ A, const float4* __restrict__ W,
        const float* __restrict__ bias, float4* __restrict__ C,
        const int* __restrict__ ga, const int* __restrict__ gb,
        const int* __restrict__ ga2, const int* __restrict__ gb2,
        int M, int relu) {
    extern __shared__ float4 smem4[];
    float4* sA = smem4;
    float4* sB = smem4 + 4096;

    int t = threadIdx.x;
    int rowBase = blockIdx.x * 128;
    int c8 = t & 15;
    int r0 = (t >> 4) * 4;
    const ulonglong2* sB2 = (const ulonglong2*)sB;

    u64 acc[4][4];
#pragma unroll
    for (int i = 0; i < 4; i++)
#pragma unroll
        for (int j = 0; j < 4; j++) acc[i][j] = 0ULL;

#pragma unroll
    for (int i = 0; i < 8; i++) sB[t + i * 512] = W[t + i * 512];
#pragma unroll
    for (int i = 0; i < 8; i++) {
        int p = t + i * 512;
        int r = p >> 5, kq = p & 31;
        int row = rowBase + r;
        float4 v = make_float4(0.f, 0.f, 0.f, 0.f);
        if (row < M) {
            if (PAIRG) {
                const int* A_ = (row < EPAIR) ? ga : ga2;
                const int* B_ = (row < EPAIR) ? gb : gb2;
                int rr = (row < EPAIR) ? row : row - EPAIR;
                float4 u = A[A_[rr] * 32 + kq];
                float4 w = A[B_[rr] * 32 + kq];
                v = make_float4(u.x * w.x, u.y * w.y, u.z * w.z, u.w * w.w);
            } else {
                v = A[row * 32 + kq];
            }
        }
        sA[r * 32 + kq] = v;
    }
    __syncthreads();

#pragma unroll 4
    for (int k4 = 0; k4 < 32; k4++) {
        float4 a0 = sA[(r0 + 0) * 32 + k4];
        float4 a1 = sA[(r0 + 1) * 32 + k4];
        float4 a2 = sA[(r0 + 2) * 32 + k4];
        float4 a3 = sA[(r0 + 3) * 32 + k4];
#pragma unroll
        for (int kk = 0; kk < 4; kk++) {
            int k = k4 * 4 + kk;
            ulonglong2 p0 = sB2[k * 32 + c8];
            ulonglong2 p1 = sB2[k * 32 + 16 + c8];
            float f0 = kk == 0 ? a0.x : kk == 1 ? a0.y : kk == 2 ? a0.z : a0.w;
            float f1 = kk == 0 ? a1.x : kk == 1 ? a1.y : kk == 2 ? a1.z : a1.w;
            float f2 = kk == 0 ? a2.x : kk == 1 ? a2.y : kk == 2 ? a2.z : a2.w;
            float f3 = kk == 0 ? a3.x : kk == 1 ? a3.y : kk == 2 ? a3.z : a3.w;
            u64 aa0 = pk2(f0, f0);
            u64 aa1 = pk2(f1, f1);
            u64 aa2 = pk2(f2, f2);
            u64 aa3 = pk2(f3, f3);
            acc[0][0] = fma2(aa0, p0.x, acc[0][0]);
            acc[0][1] = fma2(aa0, p0.y, acc[0][1]);
            acc[0][2] = fma2(aa0, p1.x, acc[0][2]);
            acc[0][3] = fma2(aa0, p1.y, acc[0][3]);
            acc[1][0] = fma2(aa1, p0.x, acc[1][0]);
            acc[1][1] = fma2(aa1, p0.y, acc[1][1]);
            acc[1][2] = fma2(aa1, p1.x, acc[1][2]);
            acc[1][3] = fma2(aa1, p1.y, acc[1][3]);
            acc[2][0] = fma2(aa2, p0.x, acc[2][0]);
            acc[2][1] = fma2(aa2, p0.y, acc[2][1]);
            acc[2][2] = fma2(aa2, p1.x, acc[2][2]);
            acc[2][3] = fma2(aa2, p1.y, acc[2][3]);
            acc[3][0] = fma2(aa3, p0.x, acc[3][0]);
            acc[3][1] = fma2(aa3, p0.y, acc[3][1]);
            acc[3][2] = fma2(aa3, p1.x, acc[3][2]);
            acc[3][3] = fma2(aa3, p1.y, acc[3][3]);
        }
    }

    float4 bv0 = ((const float4*)bias)[c8];
    float4 bv1 = ((const float4*)bias)[16 + c8];

#pragma unroll
    for (int i = 0; i < 4; i++) {
        int row = rowBase + r0 + i;
        if (row >= M) continue;
        float4 o0, o1;
        upk2(acc[i][0], o0.x, o0.y);
        upk2(acc[i][1], o0.z, o0.w);
        upk2(acc[i][2], o1.x, o1.y);
        upk2(acc[i][3], o1.z, o1.w);
        o0.x += bv0.x; o0.y += bv0.y; o0.z += bv0.z; o0.w += bv0.w;
        o1.x += bv1.x; o1.y += bv1.y; o1.z += bv1.z; o1.w += bv1.w;
        if (relu) {
            o0.x = fmaxf(o0.x, 0.f); o0.y = fmaxf(o0.y, 0.f);
            o0.z = fmaxf(o0.z, 0.f); o0.w = fmaxf(o0.w, 0.f);
            o1.x = fmaxf(o1.x, 0.f); o1.y = fmaxf(o1.y, 0.f);
            o1.z = fmaxf(o1.z, 0.f); o1.w = fmaxf(o1.w, 0.f);
        }
        C[row * 32 + c8]      = o0;
        C[row * 32 + 16 + c8] = o1;
    }
}

// per-column stats, both streams via grid.y
__global__ void k_colstats2(const float* __restrict__ Hp, const float* __restrict__ Hn,
                            int M, float* __restrict__ stats) {
    const float* H = blockIdx.y ? Hn : Hp;
    float* sum = stats + blockIdx.y * 2 * D;
    float* sq  = sum + D;
    int c = threadIdx.x;
    int r0 = blockIdx.x * 256;
    int rend = r0 + 256; if (rend > M) rend = M;
    float s = 0.f, s2 = 0.f;
    for (int r = r0; r < rend; r++) {
        float v = H[r * D + c];
        s += v; s2 += v * v;
    }
    atomicAdd(&sum[c], s);
    atomicAdd(&sq[c], s2);
}

__global__ void k_bncoef(const float* __restrict__ stats,
                         const float* __restrict__ gamma, const float* __restrict__ beta,
                         float* __restrict__ bnA, float* __restrict__ bnB, int M) {
    int t = threadIdx.x;
    int strm = t >> 7, c = t & 127;
    const float* st = stats + strm * 2 * D;
    float invM = 1.0f / (float)M;
    float m = st[c] * invM;
    float v = st[D + c] * invM - m * m;
    float a = gamma[c] * rsqrtf(v + BN_EPS);
    bnA[strm * D + c] = a;
    bnB[strm * D + c] = beta[c] - m * a;
}

__global__ void k_colstats(const float* __restrict__ H, int M,
                           float* __restrict__ sum, float* __restrict__ sq) {
    int c = threadIdx.x;
    int r0 = blockIdx.x * 256;
    int rend = r0 + 256; if (rend > M) rend = M;
    float s = 0.f, s2 = 0.f;
    for (int r = r0; r < rend; r++) {
        float v = H[r * D + c];
        s += v; s2 += v * v;
    }
    atomicAdd(&sum[c], s);
    atomicAdd(&sq[c], s2);
}

__global__ void k_summary_ws(const float* __restrict__ colsum,
                             const float* __restrict__ discW, float* __restrict__ ws) {
    __shared__ float sm[D];
    int t = threadIdx.x;
    float mn = colsum[t] / (float)N3;
    sm[t] = 1.0f / (1.0f + expf(-mn));
    __syncthreads();
    float a = 0.f;
#pragma unroll 8
    for (int j = 0; j < D; j++) a += discW[t * D + j] * sm[j];
    ws[t] = a;
}

__device__ __forceinline__ float warp_dot128(const float4* __restrict__ a,
                                             const float4* __restrict__ b, int lane) {
    float4 x = a[lane], y = b[lane];
    float s = x.x * y.x + x.y * y.y + x.z * y.z + x.w * y.w;
#pragma unroll
    for (int o = 16; o; o >>= 1) s += __shfl_down_sync(0xffffffffu, s, o);
    return s;
}

__global__ void k_loss(const float4* __restrict__ pos, const float4* __restrict__ neg,
                       const float4* __restrict__ ws, float* __restrict__ loss) {
    int tid = blockIdx.x * blockDim.x + threadIdx.x;
    int e = tid >> 5;
    if (e >= 2 * N3) return;
    int lane = tid & 31;
    int strm = (e >= N3);
    int r = e - strm * N3;
    const float4* row = (strm ? neg : pos) + r * 32;
    float s = warp_dot128(row, ws, lane);
    if (lane == 0) {
        float xx = strm ? s : -s;
        float sp = fmaxf(xx, 0.f) + log1pf(expf(-fabsf(xx)));
        atomicAdd(&loss[strm], sp);
    }
}

// pred output + final loss scalar (loss[] complete by stream order)
__global__ void k_pred_out(const float4* __restrict__ z, const float4* __restrict__ w3,
                           const float* __restrict__ b3, const float* __restrict__ loss,
                           float* __restrict__ out) {
    int tid = blockIdx.x * blockDim.x + threadIdx.x;
    if (tid == 0)
        out[2 * EPAIR] = (loss[0] + loss[1]) * (1.0f / (float)N3);
    int e = tid >> 5;
    if (e >= 2 * EPAIR) return;
    int lane = tid & 31;
    float s = warp_dot128(z + e * 32, w3, lane);
    if (lane == 0) out[e] = s + b3[0];
}

// ---------------- host orchestration ----------------
extern "C" void kernel_launch(void* const* d_in, const int* in_sizes, int n_in,
                              void* d_out, int out_size) {
    const float* x      = (const float*)d_in[0];
    const int* srcs[3]  = {(const int*)d_in[1], (const int*)d_in[3], (const int*)d_in[5]};
    const int* dsts[3]  = {(const int*)d_in[2], (const int*)d_in[4], (const int*)d_in[6]};
    const int* perm     = (const int*)d_in[7];
    const int* pos_src  = (const int*)d_in[8];
    const int* pos_dst  = (const int*)d_in[9];
    const int* neg_src  = (const int*)d_in[10];
    const int* neg_dst  = (const int*)d_in[11];
    const float* Ws[3]  = {(const float*)d_in[12], (const float*)d_in[15], (const float*)d_in[18]};
    const float* Wn[3]  = {(const float*)d_in[13], (const float*)d_in[16], (const float*)d_in[19]};
    const float* bb[3]  = {(const float*)d_in[14], (const float*)d_in[17], (const float*)d_in[20]};
    const float* gamma[2] = {(const float*)d_in[21], (const float*)d_in[23]};
    const float* beta [2] = {(const float*)d_in[22], (const float*)d_in[24]};
    const float* discW  = (const float*)d_in[25];
    const float* pW1 = (const float*)d_in[26]; const float* pb1 = (const float*)d_in[27];
    const float* pW2 = (const float*)d_in[28]; const float* pb2 = (const float*)d_in[29];
    const float* pW3 = (const float*)d_in[30]; const float* pb3 = (const float*)d_in[31];
    float* out = (float*)d_out;

    int E[3] = {in_sizes[1], in_sizes[3], in_sizes[5]};
    int ND[3] = {N1, N2, N3};
    int segbase[3] = {0, N1, N1 + N2};

    float *p_bufA, *p_bufB, *p_agg, *p_stats, *p_bnA, *p_bnB, *p_csum, *p_csq,
          *p_ws, *p_loss, *p_z, *p_z2;
    int *p_cnt, *p_off, *p_slot, *p_csr, *p_csr2;
    __nv_bfloat16 *p_wth, *p_wtl;
    cudaGetSymbolAddress((void**)&p_bufA,  g_bufA);
    cudaGetSymbolAddress((void**)&p_bufB,  g_bufB);
    cudaGetSymbolAddress((void**)&p_agg,   g_agg);
    cudaGetSymbolAddress((void**)&p_cnt,   g_cnt);
    cudaGetSymbolAddress((void**)&p_off,   g_off);
    cudaGetSymbolAddress((void**)&p_slot,  g_slot);
    cudaGetSymbolAddress((void**)&p_csr,   g_csr);
    cudaGetSymbolAddress((void**)&p_csr2,  g_csr2);
    cudaGetSymbolAddress((void**)&p_stats, g_stats);
    cudaGetSymbolAddress((void**)&p_bnA,   g_bnA);
    cudaGetSymbolAddress((void**)&p_bnB,   g_bnB);
    cudaGetSymbolAddress((void**)&p_csum,  g_csum);
    cudaGetSymbolAddress((void**)&p_csq,   g_csq_dummy);
    cudaGetSymbolAddress((void**)&p_ws,    g_ws);
    cudaGetSymbolAddress((void**)&p_loss,  g_loss);
    cudaGetSymbolAddress((void**)&p_z,     g_z);
    cudaGetSymbolAddress((void**)&p_z2,    g_z2);
    cudaGetSymbolAddress((void**)&p_wth,   g_wth);
    cudaGetSymbolAddress((void**)&p_wtl,   g_wtl);

    const size_t PRED_SMEM = 131072;
    cudaFuncSetAttribute(gemm_v4<true >, cudaFuncAttributeMaxDynamicSharedMemorySize, PRED_SMEM);
    cudaFuncSetAttribute(gemm_v4<false>, cudaFuncAttributeMaxDynamicSharedMemorySize, PRED_SMEM);
    cudaFuncSetAttribute((const void*)gemm_mma<true,  false>, cudaFuncAttributeMaxDynamicSharedMemorySize, MMA_SMEM);
    cudaFuncSetAttribute((const void*)gemm_mma<false, true >, cudaFuncAttributeMaxDynamicSharedMemorySize, MMA_SMEM);

    int Etot = E[0] + E[1] + E[2];

    // weight prep
    {
        dim3 pgrid(1, 6);
        k_prep_w<<<pgrid, 256>>>((const float4*)Ws[0], (const float4*)Wn[0],
                                 (const float4*)Ws[1], (const float4*)Wn[1],
                                 (const float4*)Ws[2], (const float4*)Wn[2]);
    }

    // batched CSR build
    cudaMemsetAsync(p_cnt, 0, NTOT * sizeof(int), 0);
    k_count_all<<<(Etot + 255) / 256, 256>>>(dsts[0], E[0], dsts[1], E[1], dsts[2], E[2],
                                             p_cnt, p_slot);
    k_scan<<<1, 1024>>>(p_cnt, NTOT, p_off);
    k_fill_all<<<(Etot + 255) / 256, 256>>>(srcs[0], dsts[0], E[0],
                                            srcs[1], dsts[1], E[1],
                                            srcs[2], dsts[2], E[2],
                                            perm, p_off, p_slot, p_csr, p_csr2);

    float* bufA[2] = {p_bufA, p_bufA + (size_t)N1 * D};
    float* bufB[2] = {p_bufB, p_bufB + (size_t)N2 * D};
    float* agg [2] = {p_agg,  p_agg  + (size_t)N1 * D};
    float* bnAp = p_bnA;          float* bnAn = p_bnA + D;
    float* bnBp = p_bnB;          float* bnBn = p_bnB + D;

    const float* hinP = x;
    const float* hinN = x;   // layer-0 negative: x with perm indirection

    for (int l = 0; l < 3; l++) {
        int nd = ND[l];
        float* outb[2];
        if (l == 1) { outb[0] = bufB[0]; outb[1] = bufB[1]; }
        else        { outb[0] = bufA[0]; outb[1] = bufA[1]; }

        const int* csrN = (l == 0) ? p_csr2 : p_csr;
        int gthreads = 2 * nd * 32;
        if (l == 0) {
            k_gather5<false><<<(gthreads + 255) / 256, 256>>>(
                (const float4*)hinP, (const float4*)hinN, p_csr, csrN,
                p_off + segbase[l], nullptr, nullptr, nullptr, nullptr,
                (float4*)agg[0], (float4*)agg[1], nd);
        } else {
            k_gather5<true><<<(gthreads + 255) / 256, 256>>>(
                (const float4*)hinP, (const float4*)hinN, p_csr, csrN,
                p_off + segbase[l],
                (const float4*)bnAp, (const float4*)bnBp,
                (const float4*)bnAn, (const float4*)bnBn,
                (float4*)agg[0], (float4*)agg[1], nd);
        }

        const __nv_bfloat16* W1h = p_wth + (size_t)(2 * l) * D * D;
        const __nv_bfloat16* W1l = p_wtl + (size_t)(2 * l) * D * D;
        const __nv_bfloat16* W2h = p_wth + (size_t)(2 * l + 1) * D * D;
        const __nv_bfloat16* W2l = p_wtl + (size_t)(2 * l + 1) * D * D;

        dim3 grid((nd + 63) / 64, 2);
        if (l == 0) {
            gemm_mma<true, false><<<grid, 256, MMA_SMEM>>>(
                (const float4*)hinP, (const float4*)hinN,
                (const float4*)agg[0], (const float4*)agg[1],
                W1h, W1l, W2h, W2l, bb[l],
                (float4*)outb[0], (float4*)outb[1],
                nullptr, nullptr, nullptr, nullptr, perm, nd);
        } else {
            gemm_mma<false, true><<<grid, 256, MMA_SMEM>>>(
                (const float4*)hinP, (const float4*)hinN,
                (const float4*)agg[0], (const float4*)agg[1],
                W1h, W1l, W2h, W2l, bb[l],
                (float4*)outb[0], (float4*)outb[1],
                (const float4*)bnAp, (const float4*)bnBp,
                (const float4*)bnAn, (const float4*)bnBn, nullptr, nd);
        }

        if (l < 2) {
            cudaMemsetAsync(p_stats, 0, 2 * 2 * D * sizeof(float), 0);
            dim3 sgrid((nd + 255) / 256, 2);
            k_colstats2<<<sgrid, 128>>>(outb[0], outb[1], nd, p_stats);
            k_bncoef<<<1, 256>>>(p_stats, gamma[l], beta[l], p_bnA, p_bnB, nd);
        }
        hinP = outb[0];
        hinN = outb[1];
    }

    float* positive = bufA[0];
    float* negative = bufA[1];

    cudaMemsetAsync(p_csum, 0, D * sizeof(float), 0);
    cudaMemsetAsync(p_loss, 0, 2 * sizeof(float), 0);
    k_colstats<<<(N3 + 255) / 256, 128>>>(positive, N3, p_csum, p_csq);
    k_summary_ws<<<1, 128>>>(p_csum, discW, p_ws);
    k_loss<<<(2 * N3 * 32 + 255) / 256, 256>>>((const float4*)positive,
                                               (const float4*)negative,
                                               (const float4*)p_ws, p_loss);

    // link predictor: 20000 rows, pair-product fused into GEMM1 (f32x2 path)
    int Mp = 2 * EPAIR;
    int pgblocks = (Mp + 127) / 128;
    gemm_v4<true><<<pgblocks, 512, PRED_SMEM>>>(
        (const float4*)positive, (const float4*)pW1, pb1, (float4*)p_z2,
        pos_src, pos_dst, neg_src, neg_dst, Mp, 1);
    gemm_v4<false><<<pgblocks, 512, PRED_SMEM>>>(
        (const float4*)p_z2, (const float4*)pW2, pb2, (float4*)p_z,
        nullptr, nullptr, nullptr, nullptr, Mp, 1);
    k_pred_out<<<(Mp * 32 + 255) / 256, 256>>>((const float4*)p_z,
                                               (const float4*)pW3, pb3, p_loss, out);
}